// round 6
// baseline (speedup 1.0000x reference)
#include <cuda_runtime.h>
#include <cuda_fp16.h>
#include <cuda_bf16.h>
#include <math.h>
#include <stdint.h>

#define NN  50000
#define TT  8
#define EE  800000
#define FIN 9
#define HH  64
#define GG  256   // 4*H
#define TILE_M 128
#define NBLK ((NN + TILE_M - 1) / TILE_M)   // 391

// ---------------- scratch (__device__ globals) -----------------------------
__device__ int      g_deg [TT * NN];
__device__ int      g_fill[TT * NN];
__device__ int      g_ptr [TT * (NN + 1)];
__device__ int      g_csr [TT * EE];        // pre-offset src: t*NN + s
__device__ float    g_dinv[TT * NN];
__device__ uint32_t g_hsh [TT * NN * 32];   // layer-1 hs, half2 packed (51 MB)
__device__ float    g_hs  [TT * NN * HH];   // layer-2 hs (fp32, 102 MB)
__device__ uint32_t g_shi [TT * NN * 32];   // seq bf16-hi plane (51 MB)
__device__ uint32_t g_slo [TT * NN * 32];   // seq bf16-lo plane (51 MB)

// ---------------- math helpers ---------------------------------------------
__device__ __forceinline__ float sigf(float x) {
    return __fdividef(1.f, 1.f + __expf(-x));
}
__device__ __forceinline__ float tanhf_fast(float x) {
    float a = fabsf(x);
    float e = __expf(-2.f * a);
    float t = __fdividef(1.f - e, 1.f + e);
    return copysignf(t, x);
}

// ---------------- bf16 split helpers ---------------------------------------
__device__ __forceinline__ uint32_t packbf(float e0, float e1) {
    uint32_t r;
    asm("cvt.rn.bf16x2.f32 %0, %1, %2;" : "=r"(r) : "f"(e1), "f"(e0));
    return r;
}
__device__ __forceinline__ float2 unpackbf(uint32_t u) {
    __nv_bfloat162 b = *reinterpret_cast<__nv_bfloat162*>(&u);
    return make_float2(__bfloat162float(b.x), __bfloat162float(b.y));
}
__device__ __forceinline__ void split2(float e0, float e1, uint32_t& hi, uint32_t& lo) {
    hi = packbf(e0, e1);
    float2 hf = unpackbf(hi);
    lo = packbf(e0 - hf.x, e1 - hf.y);
}
__device__ __forceinline__ void mma_bf16(float* d, const uint32_t* a,
                                         uint32_t b0, uint32_t b1) {
    asm volatile(
        "mma.sync.aligned.m16n8k16.row.col.f32.bf16.bf16.f32 "
        "{%0,%1,%2,%3}, {%4,%5,%6,%7}, {%8,%9}, {%0,%1,%2,%3};"
        : "+f"(d[0]), "+f"(d[1]), "+f"(d[2]), "+f"(d[3])
        : "r"(a[0]), "r"(a[1]), "r"(a[2]), "r"(a[3]), "r"(b0), "r"(b1));
}

// ---------------- init: zero deg/fill --------------------------------------
__global__ void k_init() {
    int i0 = blockIdx.x * blockDim.x + threadIdx.x;
    for (int i = i0; i < TT * NN; i += gridDim.x * blockDim.x) {
        g_deg[i] = 0; g_fill[i] = 0;
    }
}

// ---------------- CSR build ------------------------------------------------
__global__ void k_hist_all(const int* __restrict__ ei) {
    int idx = blockIdx.x * blockDim.x + threadIdx.x;
    if (idx >= TT * EE) return;
    int t = idx / EE, e = idx - t * EE;
    int d = ei[(size_t)t * 2 * EE + EE + e];
    atomicAdd(&g_deg[t * NN + d], 1);
}

__global__ __launch_bounds__(1024) void k_scan_all() {
    int t = blockIdx.x;
    const int* deg = g_deg + t * NN;
    int*   ptr  = g_ptr  + t * (NN + 1);
    float* dinv = g_dinv + t * NN;
    __shared__ int s_ws[32];
    int tid = threadIdx.x, lane = tid & 31, wid = tid >> 5;
    const int iters = (NN + 1023) / 1024;
    int running = 0;
    int i = tid;
    int v = (i < NN) ? deg[i] : 0;
    for (int it = 0; it < iters; it++) {
        int inext = (it + 1) * 1024 + tid;
        int vnext = (it + 1 < iters && inext < NN) ? deg[inext] : 0;
        int x = v;
#pragma unroll
        for (int off = 1; off < 32; off <<= 1) {
            int y = __shfl_up_sync(0xffffffffu, x, off);
            if (lane >= off) x += y;
        }
        if (lane == 31) s_ws[wid] = x;
        __syncthreads();
        if (wid == 0) {
            int w = s_ws[lane];
#pragma unroll
            for (int off = 1; off < 32; off <<= 1) {
                int y = __shfl_up_sync(0xffffffffu, w, off);
                if (lane >= off) w += y;
            }
            s_ws[lane] = w;
        }
        __syncthreads();
        int base  = (wid > 0) ? s_ws[wid - 1] : 0;
        int total = s_ws[31];
        if (i < NN) {
            ptr[i]  = running + base + (x - v);
            dinv[i] = rsqrtf((float)(v + 1));
        }
        __syncthreads();
        running += total;
        i = inext; v = vnext;
    }
    if (tid == 0) ptr[NN] = running;
}

__global__ void k_fill_all(const int* __restrict__ ei) {
    int idx = blockIdx.x * blockDim.x + threadIdx.x;
    if (idx >= TT * EE) return;
    int t = idx / EE, e = idx - t * EE;
    int s = ei[(size_t)t * 2 * EE + e];
    int d = ei[(size_t)t * 2 * EE + EE + e];
    int pos = g_ptr[t * (NN + 1) + d] + atomicAdd(&g_fill[t * NN + d], 1);
    g_csr[(size_t)t * EE + pos] = t * NN + s;
}

// ---------------- layer-1 GEMM (K=9), half2 output -------------------------
__global__ void k_gemm1h(const float* __restrict__ x, const float* __restrict__ W1) {
    __shared__ float sW[FIN * HH];
    int tid = threadIdx.x;
    for (int i = tid; i < FIN * HH; i += blockDim.x) sW[i] = W1[i];
    __syncthreads();
    int n = blockIdx.x * blockDim.x + tid;
    if (n >= TT * NN) return;
    float xv[FIN];
#pragma unroll
    for (int k = 0; k < FIN; k++) xv[k] = x[(size_t)n * FIN + k];
    float dv = g_dinv[n];
#pragma unroll
    for (int c = 0; c < HH; c += 4) {
        float4 o = make_float4(0.f, 0.f, 0.f, 0.f);
#pragma unroll
        for (int k = 0; k < FIN; k++) {
            float xk = xv[k];
            o.x = fmaf(xk, sW[k * HH + c + 0], o.x);
            o.y = fmaf(xk, sW[k * HH + c + 1], o.y);
            o.z = fmaf(xk, sW[k * HH + c + 2], o.z);
            o.w = fmaf(xk, sW[k * HH + c + 3], o.w);
        }
        __half2 p0 = __floats2half2_rn(o.x * dv, o.y * dv);
        __half2 p1 = __floats2half2_rn(o.z * dv, o.w * dv);
        uint2 u;
        u.x = *reinterpret_cast<uint32_t*>(&p0);
        u.y = *reinterpret_cast<uint32_t*>(&p1);
        *reinterpret_cast<uint2*>(g_hsh + (size_t)n * 32 + c / 2) = u;
    }
}

// ====== fused: layer-1 aggregation (fp16 gather) + layer-2 GEMM ============
// block = 1024 threads = 32 warps; warp w aggregates node blockIdx*32+w,
// then 16 warps do the 32x64 @ 64x64 GEMM (bf16 split) with dinv epilogue.
#define AG_BHI 0       // 64 x 36 u32
#define AG_BLO 2304
#define AG_AHI 4608    // 32 x 36 u32
#define AG_ALO 5760
#define AG_TOT 6912    // u32 -> 27648 bytes

__global__ __launch_bounds__(1024) void k_aggmm(
    const float* __restrict__ W2, const float* __restrict__ b1,
    float* __restrict__ ouths)
{
    extern __shared__ uint32_t sa[];
    int tid = threadIdx.x, lane = tid & 31, w = tid >> 5;

    // load W2 split: [64 cols][32 kpairs + 4 pad]
    for (int i = tid; i < 64 * 32; i += 1024) {
        int j = i >> 5, kp = i & 31;
        float e0 = W2[(2 * kp) * 64 + j];
        float e1 = W2[(2 * kp + 1) * 64 + j];
        uint32_t hi, lo; split2(e0, e1, hi, lo);
        sa[AG_BHI + j * 36 + kp] = hi;
        sa[AG_BLO + j * 36 + kp] = lo;
    }

    // ---- phase A: gather (fp16) + relu ------------------------------------
    int gw = blockIdx.x * 32 + w;               // < TT*NN exactly
    int t = gw / NN, n = gw - t * NN;
    const int* pbase = g_ptr + t * (NN + 1) + n;
    const int* csr   = g_csr + (size_t)t * EE;
    const uint32_t* hsh = g_hsh;
    float2 acc = __half22float2(*reinterpret_cast<const __half2*>(
                     hsh + (size_t)gw * 32 + lane));
    int e = pbase[0], end = pbase[1];
    for (; e + 3 < end; e += 4) {
        int s0 = csr[e], s1 = csr[e + 1], s2 = csr[e + 2], s3 = csr[e + 3];
        float2 v0 = __half22float2(*reinterpret_cast<const __half2*>(hsh + (size_t)s0 * 32 + lane));
        float2 v1 = __half22float2(*reinterpret_cast<const __half2*>(hsh + (size_t)s1 * 32 + lane));
        float2 v2 = __half22float2(*reinterpret_cast<const __half2*>(hsh + (size_t)s2 * 32 + lane));
        float2 v3 = __half22float2(*reinterpret_cast<const __half2*>(hsh + (size_t)s3 * 32 + lane));
        acc.x += (v0.x + v1.x) + (v2.x + v3.x);
        acc.y += (v0.y + v1.y) + (v2.y + v3.y);
    }
    for (; e < end; e++) {
        int s0 = csr[e];
        float2 v0 = __half22float2(*reinterpret_cast<const __half2*>(hsh + (size_t)s0 * 32 + lane));
        acc.x += v0.x; acc.y += v0.y;
    }
    float dv = g_dinv[gw];
    float2 bb = reinterpret_cast<const float2*>(b1)[lane];
    float ax = fmaxf(fmaf(acc.x, dv, bb.x), 0.f);
    float ay = fmaxf(fmaf(acc.y, dv, bb.y), 0.f);
    {
        uint32_t hi, lo; split2(ax, ay, hi, lo);
        sa[AG_AHI + w * 36 + lane] = hi;
        sa[AG_ALO + w * 36 + lane] = lo;
    }
    __syncthreads();

    // ---- phase B: 32x64 @ 64x64 GEMM, warps 0..15 -------------------------
    if (w < 16) {
        int wm = w >> 3, wn = w & 7;
        int grp = lane >> 2, tig = lane & 3;
        float acc4[4] = {};
#pragma unroll
        for (int cs = 0; cs < 4; cs++) {
            int kb = cs * 8;
            int pb = (wn * 8 + grp) * 36 + kb;
            uint32_t b0h = sa[AG_BHI + pb + tig], b1h = sa[AG_BHI + pb + tig + 4];
            uint32_t b0l = sa[AG_BLO + pb + tig], b1l = sa[AG_BLO + pb + tig + 4];
            int rb = wm * 16;
            uint32_t Ah[4], Al[4];
            Ah[0] = sa[AG_AHI + (rb + grp) * 36 + kb + tig];
            Ah[1] = sa[AG_AHI + (rb + grp + 8) * 36 + kb + tig];
            Ah[2] = sa[AG_AHI + (rb + grp) * 36 + kb + tig + 4];
            Ah[3] = sa[AG_AHI + (rb + grp + 8) * 36 + kb + tig + 4];
            Al[0] = sa[AG_ALO + (rb + grp) * 36 + kb + tig];
            Al[1] = sa[AG_ALO + (rb + grp + 8) * 36 + kb + tig];
            Al[2] = sa[AG_ALO + (rb + grp) * 36 + kb + tig + 4];
            Al[3] = sa[AG_ALO + (rb + grp + 8) * 36 + kb + tig + 4];
            mma_bf16(acc4, Ah, b0h, b1h);
            mma_bf16(acc4, Ah, b0l, b1l);
            mma_bf16(acc4, Al, b0h, b1h);
        }
#pragma unroll
        for (int rh = 0; rh < 2; rh++) {
            int row = blockIdx.x * 32 + wm * 16 + grp + rh * 8;
            float dv2 = g_dinv[row];
            float2 o = make_float2(acc4[rh * 2] * dv2, acc4[rh * 2 + 1] * dv2);
            *reinterpret_cast<float2*>(ouths + (size_t)row * 64 + wn * 8 + tig * 2) = o;
        }
    }
}

// ---------------- layer-2 aggregation (fp32) -> bf16 hi/lo planes ----------
__global__ void k_agg2bf(const float* __restrict__ hs, const float* __restrict__ b) {
    int gw = (blockIdx.x * blockDim.x + threadIdx.x) >> 5;
    int lane = threadIdx.x & 31;
    if (gw >= TT * NN) return;
    int t = gw / NN, n = gw - t * NN;
    const int* pbase = g_ptr + t * (NN + 1) + n;
    const int* csr   = g_csr + (size_t)t * EE;
    const float2* h2 = reinterpret_cast<const float2*>(hs);
    float2 acc = h2[(size_t)gw * 32 + lane];
    int e = pbase[0], end = pbase[1];
    for (; e + 3 < end; e += 4) {
        int s0 = csr[e], s1 = csr[e + 1], s2 = csr[e + 2], s3 = csr[e + 3];
        float2 v0 = h2[(size_t)s0 * 32 + lane];
        float2 v1 = h2[(size_t)s1 * 32 + lane];
        float2 v2 = h2[(size_t)s2 * 32 + lane];
        float2 v3 = h2[(size_t)s3 * 32 + lane];
        acc.x += (v0.x + v1.x) + (v2.x + v3.x);
        acc.y += (v0.y + v1.y) + (v2.y + v3.y);
    }
    for (; e < end; e++) {
        int s0 = csr[e];
        float2 v0 = h2[(size_t)s0 * 32 + lane];
        acc.x += v0.x; acc.y += v0.y;
    }
    float dv = g_dinv[gw];
    float2 bb = reinterpret_cast<const float2*>(b)[lane];
    float ox = fmaxf(fmaf(acc.x, dv, bb.x), 0.f);
    float oy = fmaxf(fmaf(acc.y, dv, bb.y), 0.f);
    uint32_t hi, lo; split2(ox, oy, hi, lo);
    g_shi[(size_t)gw * 32 + lane] = hi;
    g_slo[(size_t)gw * 32 + lane] = lo;
}

// ============== fused LSTM over all T + head, bf16-split mma ===============
#define L_XHI  0          // 128 x 36
#define L_XLO  4608
#define L_HHI  9216
#define L_HLO  13824
#define L_BHI  18432      // 256 x 68
#define L_BLO  35840
#define L_BIAS 53248      // 256 floats
#define L_LOG  53504      // 128 floats
#define L_TOT  53632      // u32 -> 214528 bytes

__global__ __launch_bounds__(512, 1) void k_lstm_bf16(
    const float* __restrict__ w_ih, const float* __restrict__ w_hh,
    const float* __restrict__ b_ih, const float* __restrict__ b_hh,
    const float* __restrict__ head_w, const float* __restrict__ head_b,
    float* __restrict__ out)
{
    extern __shared__ uint32_t sm_u[];
    float* sBias = reinterpret_cast<float*>(sm_u + L_BIAS);
    float* sLog  = reinterpret_cast<float*>(sm_u + L_LOG);

    int tid = threadIdx.x, lane = tid & 31, w = tid >> 5;
    int grp = lane >> 2, tig = lane & 3;
    int wm = w >> 3, wn = w & 7;
    int row0 = blockIdx.x * TILE_M;
    int j0 = (wn << 3) + tig, j1 = j0 + 4;

    // ---- B: permuted gate columns, split bf16 ------------------------------
    for (int i = tid; i < 256 * 64; i += 512) {
        int p = i >> 6, kp = i & 63;
        int wnp = p >> 5, rem = p & 31, q = rem >> 3, e = rem & 7;
        int gate = ((q & 1) << 1) | (e & 1);
        int L = (gate << 6) + (wnp << 3) + ((q >> 1) << 2) + (e >> 1);
        int k = kp * 2;
        float2 v = (k < 64)
            ? *reinterpret_cast<const float2*>(w_ih + (size_t)L * 64 + k)
            : *reinterpret_cast<const float2*>(w_hh + (size_t)L * 64 + (k - 64));
        uint32_t hi, lo; split2(v.x, v.y, hi, lo);
        sm_u[L_BHI + p * 68 + kp] = hi;
        sm_u[L_BLO + p * 68 + kp] = lo;
    }
    for (int i = tid; i < 9216; i += 512) sm_u[L_HHI + i] = 0u;
    if (tid < 256) sBias[tid] = b_ih[tid] + b_hh[tid];
    if (tid < 128) sLog[tid] = 0.f;
    // load x(0) from planes
#pragma unroll
    for (int i = 0; i < 8; i++) {
        int idx = tid + i * 512;
        int r = idx >> 5, c = idx & 31;
        int row = row0 + r;
        uint32_t hi = 0u, lo = 0u;
        if (row < NN) {
            hi = g_shi[(size_t)row * 32 + c];
            lo = g_slo[(size_t)row * 32 + c];
        }
        sm_u[L_XHI + r * 36 + c] = hi;
        sm_u[L_XLO + r * 36 + c] = lo;
    }
    float hw0 = head_w[j0], hw1 = head_w[j1];
    float creg[4][2][2];
#pragma unroll
    for (int a = 0; a < 4; a++)
#pragma unroll
        for (int b = 0; b < 2; b++) { creg[a][b][0] = 0.f; creg[a][b][1] = 0.f; }
    __syncthreads();

    for (int t = 0; t < TT; t++) {
        float acc[4][4][4] = {};
#pragma unroll 1
        for (int cs = 0; cs < 8; cs++) {
            const uint32_t* Ahi;
            const uint32_t* Alo;
            int kb;
            if (cs < 4) { Ahi = sm_u + L_XHI; Alo = sm_u + L_XLO; kb = cs * 8; }
            else        { Ahi = sm_u + L_HHI; Alo = sm_u + L_HLO; kb = (cs - 4) * 8; }
            int kb2 = cs * 8;
            uint32_t Bh[4][2], Bl[4][2];
#pragma unroll
            for (int q = 0; q < 4; q++) {
                int pb = ((wn << 5) + (q << 3) + grp) * 68 + kb2;
                Bh[q][0] = sm_u[L_BHI + pb + tig];
                Bh[q][1] = sm_u[L_BHI + pb + tig + 4];
                Bl[q][0] = sm_u[L_BLO + pb + tig];
                Bl[q][1] = sm_u[L_BLO + pb + tig + 4];
            }
#pragma unroll
            for (int mi = 0; mi < 4; mi++) {
                int rb = wm * 64 + mi * 16;
                uint32_t Ah[4], Al[4];
                Ah[0] = Ahi[(rb + grp) * 36 + kb + tig];
                Ah[1] = Ahi[(rb + grp + 8) * 36 + kb + tig];
                Ah[2] = Ahi[(rb + grp) * 36 + kb + tig + 4];
                Ah[3] = Ahi[(rb + grp + 8) * 36 + kb + tig + 4];
                Al[0] = Alo[(rb + grp) * 36 + kb + tig];
                Al[1] = Alo[(rb + grp + 8) * 36 + kb + tig];
                Al[2] = Alo[(rb + grp) * 36 + kb + tig + 4];
                Al[3] = Alo[(rb + grp + 8) * 36 + kb + tig + 4];
#pragma unroll
                for (int q = 0; q < 4; q++) {
                    mma_bf16(acc[mi][q], Ah, Bh[q][0], Bh[q][1]);
                    mma_bf16(acc[mi][q], Ah, Bl[q][0], Bl[q][1]);
                    mma_bf16(acc[mi][q], Al, Bh[q][0], Bh[q][1]);
                }
            }
        }
        __syncthreads();

        // ---- issue x(t+1) loads FIRST so latency hides under gate math ----
        uint32_t rxh[8], rxl[8];
        if (t < TT - 1) {
            const uint32_t* ph = g_shi + (size_t)(t + 1) * NN * 32;
            const uint32_t* pl = g_slo + (size_t)(t + 1) * NN * 32;
#pragma unroll
            for (int i = 0; i < 8; i++) {
                int idx = tid + i * 512;
                int r = idx >> 5, c = idx & 31;
                int row = row0 + r;
                rxh[i] = (row < NN) ? ph[(size_t)row * 32 + c] : 0u;
                rxl[i] = (row < NN) ? pl[(size_t)row * 32 + c] : 0u;
            }
        }

        // ---- epilogue: gates -> c,h ---------------------------------------
        float bi0 = sBias[j0], bf0_ = sBias[64 + j0], bg0 = sBias[128 + j0], bo0 = sBias[192 + j0];
        float bi1 = sBias[j1], bf1_ = sBias[64 + j1], bg1 = sBias[128 + j1], bo1 = sBias[192 + j1];
#pragma unroll
        for (int mi = 0; mi < 4; mi++) {
#pragma unroll
            for (int rh = 0; rh < 2; rh++) {
                int r = wm * 64 + mi * 16 + grp + rh * 8;
                int ci = rh * 2;
                float gi0 = acc[mi][0][ci] + bi0, gf0 = acc[mi][0][ci + 1] + bf0_;
                float gg0 = acc[mi][1][ci] + bg0, go0 = acc[mi][1][ci + 1] + bo0;
                float gi1 = acc[mi][2][ci] + bi1, gf1 = acc[mi][2][ci + 1] + bf1_;
                float gg1 = acc[mi][3][ci] + bg1, go1 = acc[mi][3][ci + 1] + bo1;
                float c0 = creg[mi][rh][0], c1 = creg[mi][rh][1];
                c0 = sigf(gf0) * c0 + sigf(gi0) * tanhf_fast(gg0);
                c1 = sigf(gf1) * c1 + sigf(gi1) * tanhf_fast(gg1);
                creg[mi][rh][0] = c0; creg[mi][rh][1] = c1;
                float h0 = sigf(go0) * tanhf_fast(c0);
                float h1 = sigf(go1) * tanhf_fast(c1);
                if (t < TT - 1) {
                    int base0 = r * 36 + (j0 >> 1);
                    int sl = j0 & 1;
                    __nv_bfloat16 b0 = __float2bfloat16(h0);
                    reinterpret_cast<__nv_bfloat16*>(&sm_u[L_HHI + base0])[sl] = b0;
                    reinterpret_cast<__nv_bfloat16*>(&sm_u[L_HLO + base0])[sl] =
                        __float2bfloat16(h0 - __bfloat162float(b0));
                    __nv_bfloat16 b1 = __float2bfloat16(h1);
                    reinterpret_cast<__nv_bfloat16*>(&sm_u[L_HHI + base0 + 2])[sl] = b1;
                    reinterpret_cast<__nv_bfloat16*>(&sm_u[L_HLO + base0 + 2])[sl] =
                        __float2bfloat16(h1 - __bfloat162float(b1));
                } else {
                    float v = h0 * hw0 + h1 * hw1;
                    v += __shfl_xor_sync(0xffffffffu, v, 1);
                    v += __shfl_xor_sync(0xffffffffu, v, 2);
                    if (tig == 0) atomicAdd(&sLog[r], v);
                }
            }
        }

        // ---- store x(t+1) into sX -----------------------------------------
        if (t < TT - 1) {
#pragma unroll
            for (int i = 0; i < 8; i++) {
                int idx = tid + i * 512;
                int r = idx >> 5, c = idx & 31;
                sm_u[L_XHI + r * 36 + c] = rxh[i];
                sm_u[L_XLO + r * 36 + c] = rxl[i];
            }
        }
        __syncthreads();
    }

    if (tid < 128) {
        int row = row0 + tid;
        if (row < NN) out[row] = sLog[tid] + head_b[0];
    }
}

// ---------------- host launch ----------------------------------------------
extern "C" void kernel_launch(void* const* d_in, const int* in_sizes, int n_in,
                              void* d_out, int out_size) {
    const float* xs  = (const float*)d_in[0];
    const int*   ei  = (const int*)  d_in[1];
    const float* W1  = (const float*)d_in[2];
    const float* b1  = (const float*)d_in[3];
    const float* W2  = (const float*)d_in[4];
    const float* b2  = (const float*)d_in[5];
    const float* wih = (const float*)d_in[6];
    const float* whh = (const float*)d_in[7];
    const float* bih = (const float*)d_in[8];
    const float* bhh = (const float*)d_in[9];
    const float* hw  = (const float*)d_in[10];
    const float* hb  = (const float*)d_in[11];
    float* out = (float*)d_out;

    float* p_hs;
    cudaGetSymbolAddress((void**)&p_hs, g_hs);

    cudaFuncSetAttribute(k_lstm_bf16,
                         cudaFuncAttributeMaxDynamicSharedMemorySize, L_TOT * 4);
    cudaFuncSetAttribute(k_aggmm,
                         cudaFuncAttributeMaxDynamicSharedMemorySize, AG_TOT * 4);

    k_init<<<(TT * NN + 255) / 256, 256>>>();
    k_hist_all<<<(TT * EE + 255) / 256, 256>>>(ei);
    k_scan_all<<<TT, 1024>>>();
    k_fill_all<<<(TT * EE + 255) / 256, 256>>>(ei);

    k_gemm1h<<<(TT * NN + 127) / 128, 128>>>(xs, W1);
    k_aggmm<<<(TT * NN) / 32, 1024, AG_TOT * 4>>>(W2, b1, p_hs);
    k_agg2bf<<<((size_t)TT * NN * 32 + 511) / 512, 512>>>(p_hs, b2);

    k_lstm_bf16<<<NBLK, 512, L_TOT * 4>>>(wih, whh, bih, bhh, hw, hb, out);
}

// round 7
// speedup vs baseline: 1.1824x; 1.1824x over previous
#include <cuda_runtime.h>
#include <cuda_fp16.h>
#include <cuda_bf16.h>
#include <math.h>
#include <stdint.h>

#define NN  50000
#define TT  8
#define EE  800000
#define FIN 9
#define HH  64
#define TILE_M 128
#define NBLK ((NN + TILE_M - 1) / TILE_M)

__device__ int      g_deg [TT * NN];
__device__ int      g_fill[TT * NN];
__device__ int      g_ptr [TT * (NN + 1)];
__device__ int      g_csr [TT * EE];
__device__ float    g_dinv[TT * NN];
__device__ uint32_t g_hsh [TT * NN * 32];   // layer-1 hs (dinv-scaled), half2
__device__ uint32_t g_acth[TT * NN * 32];   // layer-1 activation, half2
__device__ uint32_t g_hs2h[TT * NN * 32];   // layer-2 hs, half2
__device__ uint32_t g_shi [TT * NN * 32];   // seq bf16-hi
__device__ uint32_t g_slo [TT * NN * 32];   // seq bf16-lo

__device__ __forceinline__ float sigf(float x) {
    return __fdividef(1.f, 1.f + __expf(-x));
}
__device__ __forceinline__ float tanhf_fast(float x) {
    float a = fabsf(x);
    float e = __expf(-2.f * a);
    float t = __fdividef(1.f - e, 1.f + e);
    return copysignf(t, x);
}
__device__ __forceinline__ uint32_t packbf(float e0, float e1) {
    uint32_t r;
    asm("cvt.rn.bf16x2.f32 %0, %1, %2;" : "=r"(r) : "f"(e1), "f"(e0));
    return r;
}
__device__ __forceinline__ float2 unpackbf(uint32_t u) {
    __nv_bfloat162 b = *reinterpret_cast<__nv_bfloat162*>(&u);
    return make_float2(__bfloat162float(b.x), __bfloat162float(b.y));
}
__device__ __forceinline__ void split2(float e0, float e1, uint32_t& hi, uint32_t& lo) {
    hi = packbf(e0, e1);
    float2 hf = unpackbf(hi);
    lo = packbf(e0 - hf.x, e1 - hf.y);
}
__device__ __forceinline__ uint32_t packh(float e0, float e1) {
    __half2 p = __floats2half2_rn(e0, e1);
    return *reinterpret_cast<uint32_t*>(&p);
}
__device__ __forceinline__ void splith(float e0, float e1, uint32_t& hi, uint32_t& lo) {
    __half2 p = __floats2half2_rn(e0, e1);
    float2 hf = __half22float2(p);
    hi = *reinterpret_cast<uint32_t*>(&p);
    lo = packh(e0 - hf.x, e1 - hf.y);
}
__device__ __forceinline__ void mma_bf16(float* d, const uint32_t* a,
                                         uint32_t b0, uint32_t b1) {
    asm volatile(
        "mma.sync.aligned.m16n8k16.row.col.f32.bf16.bf16.f32 "
        "{%0,%1,%2,%3}, {%4,%5,%6,%7}, {%8,%9}, {%0,%1,%2,%3};"
        : "+f"(d[0]), "+f"(d[1]), "+f"(d[2]), "+f"(d[3])
        : "r"(a[0]), "r"(a[1]), "r"(a[2]), "r"(a[3]), "r"(b0), "r"(b1));
}
__device__ __forceinline__ void mma_f16(float* d, const uint32_t* a,
                                        uint32_t b0, uint32_t b1) {
    asm volatile(
        "mma.sync.aligned.m16n8k16.row.col.f32.f16.f16.f32 "
        "{%0,%1,%2,%3}, {%4,%5,%6,%7}, {%8,%9}, {%0,%1,%2,%3};"
        : "+f"(d[0]), "+f"(d[1]), "+f"(d[2]), "+f"(d[3])
        : "r"(a[0]), "r"(a[1]), "r"(a[2]), "r"(a[3]), "r"(b0), "r"(b1));
}

__global__ void k_init() {
    int i0 = blockIdx.x * blockDim.x + threadIdx.x;
    for (int i = i0; i < TT * NN; i += gridDim.x * blockDim.x) {
        g_deg[i] = 0; g_fill[i] = 0;
    }
}

__global__ void k_hist_all(const int* __restrict__ ei) {
    int idx = blockIdx.x * blockDim.x + threadIdx.x;
    if (idx >= TT * EE) return;
    int t = idx / EE, e = idx - t * EE;
    int d = ei[(size_t)t * 2 * EE + EE + e];
    atomicAdd(&g_deg[t * NN + d], 1);
}

__global__ __launch_bounds__(1024) void k_scan_all() {
    int t = blockIdx.x;
    const int* deg = g_deg + t * NN;
    int*   ptr  = g_ptr  + t * (NN + 1);
    float* dinv = g_dinv + t * NN;
    __shared__ int s_ws[32];
    int tid = threadIdx.x, lane = tid & 31, wid = tid >> 5;
    const int iters = (NN + 1023) / 1024;
    int running = 0;
    int i = tid;
    int v = (i < NN) ? deg[i] : 0;
    for (int it = 0; it < iters; it++) {
        int inext = (it + 1) * 1024 + tid;
        int vnext = (it + 1 < iters && inext < NN) ? deg[inext] : 0;
        int x = v;
#pragma unroll
        for (int off = 1; off < 32; off <<= 1) {
            int y = __shfl_up_sync(0xffffffffu, x, off);
            if (lane >= off) x += y;
        }
        if (lane == 31) s_ws[wid] = x;
        __syncthreads();
        if (wid == 0) {
            int w = s_ws[lane];
#pragma unroll
            for (int off = 1; off < 32; off <<= 1) {
                int y = __shfl_up_sync(0xffffffffu, w, off);
                if (lane >= off) w += y;
            }
            s_ws[lane] = w;
        }
        __syncthreads();
        int base  = (wid > 0) ? s_ws[wid - 1] : 0;
        int total = s_ws[31];
        if (i < NN) {
            ptr[i]  = running + base + (x - v);
            dinv[i] = rsqrtf((float)(v + 1));
        }
        __syncthreads();
        running += total;
        i = inext; v = vnext;
    }
    if (tid == 0) ptr[NN] = running;
}

__global__ void k_fill_all(const int* __restrict__ ei) {
    int idx = blockIdx.x * blockDim.x + threadIdx.x;
    if (idx >= TT * EE) return;
    int t = idx / EE, e = idx - t * EE;
    int s = ei[(size_t)t * 2 * EE + e];
    int d = ei[(size_t)t * 2 * EE + EE + e];
    int pos = g_ptr[t * (NN + 1) + d] + atomicAdd(&g_fill[t * NN + d], 1);
    g_csr[(size_t)t * EE + pos] = t * NN + s;
}

// layer-1 GEMM (K=9): hs1 = (x @ W1) * dinv -> half2 in g_hsh
__global__ void k_gemm1h(const float* __restrict__ x, const float* __restrict__ W1) {
    __shared__ float sW[FIN * HH];
    int tid = threadIdx.x;
    for (int i = tid; i < FIN * HH; i += blockDim.x) sW[i] = W1[i];
    __syncthreads();
    int n = blockIdx.x * blockDim.x + tid;
    if (n >= TT * NN) return;
    float xv[FIN];
#pragma unroll
    for (int k = 0; k < FIN; k++) xv[k] = x[(size_t)n * FIN + k];
    float dv = g_dinv[n];
#pragma unroll
    for (int c = 0; c < HH; c += 4) {
        float4 o = make_float4(0.f, 0.f, 0.f, 0.f);
#pragma unroll
        for (int k = 0; k < FIN; k++) {
            float xk = xv[k];
            o.x = fmaf(xk, sW[k * HH + c + 0], o.x);
            o.y = fmaf(xk, sW[k * HH + c + 1], o.y);
            o.z = fmaf(xk, sW[k * HH + c + 2], o.z);
            o.w = fmaf(xk, sW[k * HH + c + 3], o.w);
        }
        uint2 u;
        u.x = packh(o.x * dv, o.y * dv);
        u.y = packh(o.z * dv, o.w * dv);
        *reinterpret_cast<uint2*>(g_hsh + (size_t)n * 32 + c / 2) = u;
    }
}

// layer-1 aggregation: gather g_hsh (fp16), relu -> g_acth (half2)
__global__ void k_agg1h(const float* __restrict__ b1) {
    int gw = (blockIdx.x * blockDim.x + threadIdx.x) >> 5;
    int lane = threadIdx.x & 31;
    if (gw >= TT * NN) return;
    int t = gw / NN, n = gw - t * NN;
    const int* pbase = g_ptr + t * (NN + 1) + n;
    const int* csr   = g_csr + (size_t)t * EE;
    const uint32_t* hsh = g_hsh;
    float2 acc = __half22float2(*reinterpret_cast<const __half2*>(
                     hsh + (size_t)gw * 32 + lane));
    int e = pbase[0], end = pbase[1];
    for (; e + 3 < end; e += 4) {
        int s0 = csr[e], s1 = csr[e + 1], s2 = csr[e + 2], s3 = csr[e + 3];
        float2 v0 = __half22float2(*reinterpret_cast<const __half2*>(hsh + (size_t)s0 * 32 + lane));
        float2 v1 = __half22float2(*reinterpret_cast<const __half2*>(hsh + (size_t)s1 * 32 + lane));
        float2 v2 = __half22float2(*reinterpret_cast<const __half2*>(hsh + (size_t)s2 * 32 + lane));
        float2 v3 = __half22float2(*reinterpret_cast<const __half2*>(hsh + (size_t)s3 * 32 + lane));
        acc.x += (v0.x + v1.x) + (v2.x + v3.x);
        acc.y += (v0.y + v1.y) + (v2.y + v3.y);
    }
    for (; e < end; e++) {
        int s0 = csr[e];
        float2 v0 = __half22float2(*reinterpret_cast<const __half2*>(hsh + (size_t)s0 * 32 + lane));
        acc.x += v0.x; acc.y += v0.y;
    }
    float dv = g_dinv[gw];
    float2 bb = reinterpret_cast<const float2*>(b1)[lane];
    float ax = fmaxf(fmaf(acc.x, dv, bb.x), 0.f);
    float ay = fmaxf(fmaf(acc.y, dv, bb.y), 0.f);
    g_acth[(size_t)gw * 32 + lane] = packh(ax, ay);
}

// layer-2 GEMM: A = g_acth (exact fp16) @ W2 (fp16 hi/lo) * dinv -> g_hs2h
#define G2_A   0
#define G2_BHI 4608
#define G2_BLO 6912
#define G2_TOT 9216

__global__ __launch_bounds__(512) void k_gemm64h(const float* __restrict__ W2) {
    extern __shared__ uint32_t sg[];
    int tid = threadIdx.x, lane = tid & 31, w = tid >> 5;
    int grp = lane >> 2, tig = lane & 3;
    int wm = w >> 3, wn = w & 7;
    int row0 = blockIdx.x * 128;

    for (int i = tid; i < 64 * 32; i += 512) {
        int j = i >> 5, kp = i & 31;
        float e0 = W2[(2 * kp) * 64 + j];
        float e1 = W2[(2 * kp + 1) * 64 + j];
        uint32_t hi, lo; splith(e0, e1, hi, lo);
        sg[G2_BHI + j * 36 + kp] = hi;
        sg[G2_BLO + j * 36 + kp] = lo;
    }
#pragma unroll
    for (int i = 0; i < 8; i++) {
        int idx = tid + i * 512;
        int r = idx >> 5, kp = idx & 31;
        sg[G2_A + r * 36 + kp] = g_acth[(size_t)(row0 + r) * 32 + kp];
    }
    __syncthreads();

    float acc4[4][4] = {};
#pragma unroll
    for (int cs = 0; cs < 4; cs++) {
        int kb = cs * 8;
        int pb = (wn * 8 + grp) * 36 + kb;
        uint32_t b0h = sg[G2_BHI + pb + tig], b1h = sg[G2_BHI + pb + tig + 4];
        uint32_t b0l = sg[G2_BLO + pb + tig], b1l = sg[G2_BLO + pb + tig + 4];
#pragma unroll
        for (int mi = 0; mi < 4; mi++) {
            int rb = wm * 64 + mi * 16;
            uint32_t Ah[4];
            Ah[0] = sg[G2_A + (rb + grp) * 36 + kb + tig];
            Ah[1] = sg[G2_A + (rb + grp + 8) * 36 + kb + tig];
            Ah[2] = sg[G2_A + (rb + grp) * 36 + kb + tig + 4];
            Ah[3] = sg[G2_A + (rb + grp + 8) * 36 + kb + tig + 4];
            mma_f16(acc4[mi], Ah, b0h, b1h);
            mma_f16(acc4[mi], Ah, b0l, b1l);
        }
    }
#pragma unroll
    for (int mi = 0; mi < 4; mi++) {
#pragma unroll
        for (int rh = 0; rh < 2; rh++) {
            int row = row0 + wm * 64 + mi * 16 + grp + rh * 8;
            float dv = g_dinv[row];
            g_hs2h[(size_t)row * 32 + wn * 4 + tig] =
                packh(acc4[mi][rh * 2] * dv, acc4[mi][rh * 2 + 1] * dv);
        }
    }
}

// layer-2 aggregation: gather g_hs2h (fp16) -> bf16 hi/lo planes
__global__ void k_agg2bf(const float* __restrict__ b) {
    int gw = (blockIdx.x * blockDim.x + threadIdx.x) >> 5;
    int lane = threadIdx.x & 31;
    if (gw >= TT * NN) return;
    int t = gw / NN, n = gw - t * NN;
    const int* pbase = g_ptr + t * (NN + 1) + n;
    const int* csr   = g_csr + (size_t)t * EE;
    const uint32_t* h2 = g_hs2h;
    float2 acc = __half22float2(*reinterpret_cast<const __half2*>(
                     h2 + (size_t)gw * 32 + lane));
    int e = pbase[0], end = pbase[1];
    for (; e + 3 < end; e += 4) {
        int s0 = csr[e], s1 = csr[e + 1], s2 = csr[e + 2], s3 = csr[e + 3];
        float2 v0 = __half22float2(*reinterpret_cast<const __half2*>(h2 + (size_t)s0 * 32 + lane));
        float2 v1 = __half22float2(*reinterpret_cast<const __half2*>(h2 + (size_t)s1 * 32 + lane));
        float2 v2 = __half22float2(*reinterpret_cast<const __half2*>(h2 + (size_t)s2 * 32 + lane));
        float2 v3 = __half22float2(*reinterpret_cast<const __half2*>(h2 + (size_t)s3 * 32 + lane));
        acc.x += (v0.x + v1.x) + (v2.x + v3.x);
        acc.y += (v0.y + v1.y) + (v2.y + v3.y);
    }
    for (; e < end; e++) {
        int s0 = csr[e];
        float2 v0 = __half22float2(*reinterpret_cast<const __half2*>(h2 + (size_t)s0 * 32 + lane));
        acc.x += v0.x; acc.y += v0.y;
    }
    float dv = g_dinv[gw];
    float2 bb = reinterpret_cast<const float2*>(b)[lane];
    float ox = fmaxf(fmaf(acc.x, dv, bb.x), 0.f);
    float oy = fmaxf(fmaf(acc.y, dv, bb.y), 0.f);
    uint32_t hi, lo; split2(ox, oy, hi, lo);
    g_shi[(size_t)gw * 32 + lane] = hi;
    g_slo[(size_t)gw * 32 + lane] = lo;
}

// fused LSTM over all T + head, bf16-split mma
#define L_XHI  0
#define L_XLO  4608
#define L_HHI  9216
#define L_HLO  13824
#define L_BHI  18432
#define L_BLO  35840
#define L_BIAS 53248
#define L_LOG  53504
#define L_TOT  53632

__global__ __launch_bounds__(512, 1) void k_lstm_bf16(
    const float* __restrict__ w_ih, const float* __restrict__ w_hh,
    const float* __restrict__ b_ih, const float* __restrict__ b_hh,
    const float* __restrict__ head_w, const float* __restrict__ head_b,
    float* __restrict__ out)
{
    extern __shared__ uint32_t sm_u[];
    float* sBias = reinterpret_cast<float*>(sm_u + L_BIAS);
    float* sLog  = reinterpret_cast<float*>(sm_u + L_LOG);

    int tid = threadIdx.x, lane = tid & 31, w = tid >> 5;
    int grp = lane >> 2, tig = lane & 3;
    int wm = w >> 3, wn = w & 7;
    int row0 = blockIdx.x * TILE_M;
    int j0 = (wn << 3) + tig, j1 = j0 + 4;

    for (int i = tid; i < 256 * 64; i += 512) {
        int p = i >> 6, kp = i & 63;
        int wnp = p >> 5, rem = p & 31, q = rem >> 3, e = rem & 7;
        int gate = ((q & 1) << 1) | (e & 1);
        int L = (gate << 6) + (wnp << 3) + ((q >> 1) << 2) + (e >> 1);
        int k = kp * 2;
        float2 v = (k < 64)
            ? *reinterpret_cast<const float2*>(w_ih + (size_t)L * 64 + k)
            : *reinterpret_cast<const float2*>(w_hh + (size_t)L * 64 + (k - 64));
        uint32_t hi, lo; split2(v.x, v.y, hi, lo);
        sm_u[L_BHI + p * 68 + kp] = hi;
        sm_u[L_BLO + p * 68 + kp] = lo;
    }
    for (int i = tid; i < 9216; i += 512) sm_u[L_HHI + i] = 0u;
    if (tid < 256) sBias[tid] = b_ih[tid] + b_hh[tid];
    if (tid < 128) sLog[tid] = 0.f;
#pragma unroll
    for (int i = 0; i < 8; i++) {
        int idx = tid + i * 512;
        int r = idx >> 5, c = idx & 31;
        int row = row0 + r;
        uint32_t hi = 0u, lo = 0u;
        if (row < NN) {
            hi = g_shi[(size_t)row * 32 + c];
            lo = g_slo[(size_t)row * 32 + c];
        }
        sm_u[L_XHI + r * 36 + c] = hi;
        sm_u[L_XLO + r * 36 + c] = lo;
    }
    float hw0 = head_w[j0], hw1 = head_w[j1];
    float creg[4][2][2];
#pragma unroll
    for (int a = 0; a < 4; a++)
#pragma unroll
        for (int b = 0; b < 2; b++) { creg[a][b][0] = 0.f; creg[a][b][1] = 0.f; }
    __syncthreads();

    for (int t = 0; t < TT; t++) {
        float acc[4][4][4] = {};
#pragma unroll 1
        for (int cs = 0; cs < 8; cs++) {
            const uint32_t* Ahi;
            const uint32_t* Alo;
            int kb;
            if (cs < 4) { Ahi = sm_u + L_XHI; Alo = sm_u + L_XLO; kb = cs * 8; }
            else        { Ahi = sm_u + L_HHI; Alo = sm_u + L_HLO; kb = (cs - 4) * 8; }
            int kb2 = cs * 8;
            uint32_t Bh[4][2], Bl[4][2];
#pragma unroll
            for (int q = 0; q < 4; q++) {
                int pb = ((wn << 5) + (q << 3) + grp) * 68 + kb2;
                Bh[q][0] = sm_u[L_BHI + pb + tig];
                Bh[q][1] = sm_u[L_BHI + pb + tig + 4];
                Bl[q][0] = sm_u[L_BLO + pb + tig];
                Bl[q][1] = sm_u[L_BLO + pb + tig + 4];
            }
#pragma unroll
            for (int mi = 0; mi < 4; mi++) {
                int rb = wm * 64 + mi * 16;
                uint32_t Ah[4], Al[4];
                Ah[0] = Ahi[(rb + grp) * 36 + kb + tig];
                Ah[1] = Ahi[(rb + grp + 8) * 36 + kb + tig];
                Ah[2] = Ahi[(rb + grp) * 36 + kb + tig + 4];
                Ah[3] = Ahi[(rb + grp + 8) * 36 + kb + tig + 4];
                Al[0] = Alo[(rb + grp) * 36 + kb + tig];
                Al[1] = Alo[(rb + grp + 8) * 36 + kb + tig];
                Al[2] = Alo[(rb + grp) * 36 + kb + tig + 4];
                Al[3] = Alo[(rb + grp + 8) * 36 + kb + tig + 4];
#pragma unroll
                for (int q = 0; q < 4; q++) {
                    mma_bf16(acc[mi][q], Ah, Bh[q][0], Bh[q][1]);
                    mma_bf16(acc[mi][q], Ah, Bl[q][0], Bl[q][1]);
                    mma_bf16(acc[mi][q], Al, Bh[q][0], Bh[q][1]);
                }
            }
        }
        __syncthreads();

        uint32_t rxh[8], rxl[8];
        if (t < TT - 1) {
            const uint32_t* ph = g_shi + (size_t)(t + 1) * NN * 32;
            const uint32_t* pl = g_slo + (size_t)(t + 1) * NN * 32;
#pragma unroll
            for (int i = 0; i < 8; i++) {
                int idx = tid + i * 512;
                int r = idx >> 5, c = idx & 31;
                int row = row0 + r;
                rxh[i] = (row < NN) ? ph[(size_t)row * 32 + c] : 0u;
                rxl[i] = (row < NN) ? pl[(size_t)row * 32 + c] : 0u;
            }
        }

        float bi0 = sBias[j0], bf0_ = sBias[64 + j0], bg0 = sBias[128 + j0], bo0 = sBias[192 + j0];
        float bi1 = sBias[j1], bf1_ = sBias[64 + j1], bg1 = sBias[128 + j1], bo1 = sBias[192 + j1];
#pragma unroll
        for (int mi = 0; mi < 4; mi++) {
#pragma unroll
            for (int rh = 0; rh < 2; rh++) {
                int r = wm * 64 + mi * 16 + grp + rh * 8;
                int ci = rh * 2;
                float gi0 = acc[mi][0][ci] + bi0, gf0 = acc[mi][0][ci + 1] + bf0_;
                float gg0 = acc[mi][1][ci] + bg0, go0 = acc[mi][1][ci + 1] + bo0;
                float gi1 = acc[mi][2][ci] + bi1, gf1 = acc[mi][2][ci + 1] + bf1_;
                float gg1 = acc[mi][3][ci] + bg1, go1 = acc[mi][3][ci + 1] + bo1;
                float c0 = creg[mi][rh][0], c1 = creg[mi][rh][1];
                c0 = sigf(gf0) * c0 + sigf(gi0) * tanhf_fast(gg0);
                c1 = sigf(gf1) * c1 + sigf(gi1) * tanhf_fast(gg1);
                creg[mi][rh][0] = c0; creg[mi][rh][1] = c1;
                float h0 = sigf(go0) * tanhf_fast(c0);
                float h1 = sigf(go1) * tanhf_fast(c1);
                if (t < TT - 1) {
                    int base0 = r * 36 + (j0 >> 1);
                    int sl = j0 & 1;
                    __nv_bfloat16 b0 = __float2bfloat16(h0);
                    reinterpret_cast<__nv_bfloat16*>(&sm_u[L_HHI + base0])[sl] = b0;
                    reinterpret_cast<__nv_bfloat16*>(&sm_u[L_HLO + base0])[sl] =
                        __float2bfloat16(h0 - __bfloat162float(b0));
                    __nv_bfloat16 b1 = __float2bfloat16(h1);
                    reinterpret_cast<__nv_bfloat16*>(&sm_u[L_HHI + base0 + 2])[sl] = b1;
                    reinterpret_cast<__nv_bfloat16*>(&sm_u[L_HLO + base0 + 2])[sl] =
                        __float2bfloat16(h1 - __bfloat162float(b1));
                } else {
                    float v = h0 * hw0 + h1 * hw1;
                    v += __shfl_xor_sync(0xffffffffu, v, 1);
                    v += __shfl_xor_sync(0xffffffffu, v, 2);
                    if (tig == 0) atomicAdd(&sLog[r], v);
                }
            }
        }

        if (t < TT - 1) {
#pragma unroll
            for (int i = 0; i < 8; i++) {
                int idx = tid + i * 512;
                int r = idx >> 5, c = idx & 31;
                sm_u[L_XHI + r * 36 + c] = rxh[i];
                sm_u[L_XLO + r * 36 + c] = rxl[i];
            }
        }
        __syncthreads();
    }

    if (tid < 128) {
        int row = row0 + tid;
        if (row < NN) out[row] = sLog[tid] + head_b[0];
    }
}

extern "C" void kernel_launch(void* const* d_in, const int* in_sizes, int n_in,
                              void* d_out, int out_size) {
    const float* xs  = (const float*)d_in[0];
    const int*   ei  = (const int*)  d_in[1];
    const float* W1  = (const float*)d_in[2];
    const float* b1  = (const float*)d_in[3];
    const float* W2  = (const float*)d_in[4];
    const float* b2  = (const float*)d_in[5];
    const float* wih = (const float*)d_in[6];
    const float* whh = (const float*)d_in[7];
    const float* bih = (const float*)d_in[8];
    const float* bhh = (const float*)d_in[9];
    const float* hw  = (const float*)d_in[10];
    const float* hb  = (const float*)d_in[11];
    float* out = (float*)d_out;

    cudaFuncSetAttribute(k_lstm_bf16,
                         cudaFuncAttributeMaxDynamicSharedMemorySize, L_TOT * 4);
    cudaFuncSetAttribute(k_gemm64h,
                         cudaFuncAttributeMaxDynamicSharedMemorySize, G2_TOT * 4);

    k_init<<<(TT * NN + 255) / 256, 256>>>();
    k_hist_all<<<(TT * EE + 255) / 256, 256>>>(ei);
    k_scan_all<<<TT, 1024>>>();
    k_fill_all<<<(TT * EE + 255) / 256, 256>>>(ei);

    k_gemm1h<<<(TT * NN + 127) / 128, 128>>>(xs, W1);
    k_agg1h<<<((size_t)TT * NN * 32 + 511) / 512, 512>>>(b1);
    k_gemm64h<<<(TT * NN) / 128, 512, G2_TOT * 4>>>(W2);
    k_agg2bf<<<((size_t)TT * NN * 32 + 511) / 512, 512>>>(b2);

    k_lstm_bf16<<<NBLK, 512, L_TOT * 4>>>(wih, whh, bih, bhh, hw, hb, out);
}

// round 8
// speedup vs baseline: 1.2648x; 1.0697x over previous
#include <cuda_runtime.h>
#include <cuda_fp16.h>
#include <cuda_bf16.h>
#include <math.h>
#include <stdint.h>

#define NN  50000
#define TT  8
#define EE  800000
#define FIN 9
#define HH  64
#define CAP 96
#define TILE_M 128
#define NBLK ((NN + TILE_M - 1) / TILE_M)

__device__ int      g_deg [TT * NN];
__device__ int      g_bkt [(size_t)TT * NN * CAP];  // bucketed sources (pre-offset)
__device__ float    g_dinv[TT * NN];
__device__ uint32_t g_hsh [TT * NN * 32];   // layer-1 hs (dinv-scaled), half2
__device__ uint32_t g_acth[TT * NN * 32];   // layer-1 activation, half2
__device__ uint32_t g_hs2h[TT * NN * 32];   // layer-2 hs, half2
__device__ uint32_t g_shi [TT * NN * 32];   // seq bf16-hi
__device__ uint32_t g_slo [TT * NN * 32];   // seq bf16-lo

__device__ __forceinline__ float sigf(float x) {
    return __fdividef(1.f, 1.f + __expf(-x));
}
__device__ __forceinline__ float tanhf_fast(float x) {
    float a = fabsf(x);
    float e = __expf(-2.f * a);
    float t = __fdividef(1.f - e, 1.f + e);
    return copysignf(t, x);
}
__device__ __forceinline__ uint32_t packbf(float e0, float e1) {
    uint32_t r;
    asm("cvt.rn.bf16x2.f32 %0, %1, %2;" : "=r"(r) : "f"(e1), "f"(e0));
    return r;
}
__device__ __forceinline__ float2 unpackbf(uint32_t u) {
    __nv_bfloat162 b = *reinterpret_cast<__nv_bfloat162*>(&u);
    return make_float2(__bfloat162float(b.x), __bfloat162float(b.y));
}
__device__ __forceinline__ void split2(float e0, float e1, uint32_t& hi, uint32_t& lo) {
    hi = packbf(e0, e1);
    float2 hf = unpackbf(hi);
    lo = packbf(e0 - hf.x, e1 - hf.y);
}
__device__ __forceinline__ uint32_t packh(float e0, float e1) {
    __half2 p = __floats2half2_rn(e0, e1);
    return *reinterpret_cast<uint32_t*>(&p);
}
__device__ __forceinline__ void splith(float e0, float e1, uint32_t& hi, uint32_t& lo) {
    __half2 p = __floats2half2_rn(e0, e1);
    float2 hf = __half22float2(p);
    hi = *reinterpret_cast<uint32_t*>(&p);
    lo = packh(e0 - hf.x, e1 - hf.y);
}
__device__ __forceinline__ void mma_bf16(float* d, const uint32_t* a,
                                         uint32_t b0, uint32_t b1) {
    asm volatile(
        "mma.sync.aligned.m16n8k16.row.col.f32.bf16.bf16.f32 "
        "{%0,%1,%2,%3}, {%4,%5,%6,%7}, {%8,%9}, {%0,%1,%2,%3};"
        : "+f"(d[0]), "+f"(d[1]), "+f"(d[2]), "+f"(d[3])
        : "r"(a[0]), "r"(a[1]), "r"(a[2]), "r"(a[3]), "r"(b0), "r"(b1));
}
__device__ __forceinline__ void mma_f16(float* d, const uint32_t* a,
                                        uint32_t b0, uint32_t b1) {
    asm volatile(
        "mma.sync.aligned.m16n8k16.row.col.f32.f16.f16.f32 "
        "{%0,%1,%2,%3}, {%4,%5,%6,%7}, {%8,%9}, {%0,%1,%2,%3};"
        : "+f"(d[0]), "+f"(d[1]), "+f"(d[2]), "+f"(d[3])
        : "r"(a[0]), "r"(a[1]), "r"(a[2]), "r"(a[3]), "r"(b0), "r"(b1));
}

__global__ void k_init() {
    int i0 = blockIdx.x * blockDim.x + threadIdx.x;
    for (int i = i0; i < TT * NN; i += gridDim.x * blockDim.x) g_deg[i] = 0;
}

// single-pass bucket scatter: atomic return value IS the slot index
__global__ void k_fill_bucket(const int* __restrict__ ei) {
    int idx = blockIdx.x * blockDim.x + threadIdx.x;
    if (idx >= TT * EE) return;
    int t = idx / EE, e = idx - t * EE;
    int s = ei[(size_t)t * 2 * EE + e];
    int d = ei[(size_t)t * 2 * EE + EE + e];
    int td = t * NN + d;
    int pos = atomicAdd(&g_deg[td], 1);
    g_bkt[(size_t)td * CAP + pos] = t * NN + s;
}

// layer-1 GEMM (K=9): dinv = rsqrt(deg+1); hs1 = (x @ W1) * dinv -> half2
__global__ void k_gemm1h(const float* __restrict__ x, const float* __restrict__ W1) {
    __shared__ float sW[FIN * HH];
    int tid = threadIdx.x;
    for (int i = tid; i < FIN * HH; i += blockDim.x) sW[i] = W1[i];
    __syncthreads();
    int n = blockIdx.x * blockDim.x + tid;
    if (n >= TT * NN) return;
    float dv = rsqrtf((float)(g_deg[n] + 1));
    g_dinv[n] = dv;
    float xv[FIN];
#pragma unroll
    for (int k = 0; k < FIN; k++) xv[k] = x[(size_t)n * FIN + k];
#pragma unroll
    for (int c = 0; c < HH; c += 4) {
        float4 o = make_float4(0.f, 0.f, 0.f, 0.f);
#pragma unroll
        for (int k = 0; k < FIN; k++) {
            float xk = xv[k];
            o.x = fmaf(xk, sW[k * HH + c + 0], o.x);
            o.y = fmaf(xk, sW[k * HH + c + 1], o.y);
            o.z = fmaf(xk, sW[k * HH + c + 2], o.z);
            o.w = fmaf(xk, sW[k * HH + c + 3], o.w);
        }
        uint2 u;
        u.x = packh(o.x * dv, o.y * dv);
        u.y = packh(o.z * dv, o.w * dv);
        *reinterpret_cast<uint2*>(g_hsh + (size_t)n * 32 + c / 2) = u;
    }
}

// layer-1 aggregation: gather g_hsh (fp16) from buckets, relu -> g_acth
__global__ void k_agg1h(const float* __restrict__ b1) {
    int gw = (blockIdx.x * blockDim.x + threadIdx.x) >> 5;
    int lane = threadIdx.x & 31;
    if (gw >= TT * NN) return;
    int deg = g_deg[gw];
    const int* bkt = g_bkt + (size_t)gw * CAP;
    const uint32_t* hsh = g_hsh;
    float2 acc = __half22float2(*reinterpret_cast<const __half2*>(
                     hsh + (size_t)gw * 32 + lane));
    int e = 0;
    for (; e + 3 < deg; e += 4) {
        int s0 = bkt[e], s1 = bkt[e + 1], s2 = bkt[e + 2], s3 = bkt[e + 3];
        float2 v0 = __half22float2(*reinterpret_cast<const __half2*>(hsh + (size_t)s0 * 32 + lane));
        float2 v1 = __half22float2(*reinterpret_cast<const __half2*>(hsh + (size_t)s1 * 32 + lane));
        float2 v2 = __half22float2(*reinterpret_cast<const __half2*>(hsh + (size_t)s2 * 32 + lane));
        float2 v3 = __half22float2(*reinterpret_cast<const __half2*>(hsh + (size_t)s3 * 32 + lane));
        acc.x += (v0.x + v1.x) + (v2.x + v3.x);
        acc.y += (v0.y + v1.y) + (v2.y + v3.y);
    }
    for (; e < deg; e++) {
        int s0 = bkt[e];
        float2 v0 = __half22float2(*reinterpret_cast<const __half2*>(hsh + (size_t)s0 * 32 + lane));
        acc.x += v0.x; acc.y += v0.y;
    }
    float dv = g_dinv[gw];
    float2 bb = reinterpret_cast<const float2*>(b1)[lane];
    float ax = fmaxf(fmaf(acc.x, dv, bb.x), 0.f);
    float ay = fmaxf(fmaf(acc.y, dv, bb.y), 0.f);
    g_acth[(size_t)gw * 32 + lane] = packh(ax, ay);
}

// layer-2 GEMM: A = g_acth (exact fp16) @ W2 (fp16 hi/lo) * dinv -> g_hs2h
#define G2_A   0
#define G2_BHI 4608
#define G2_BLO 6912
#define G2_TOT 9216

__global__ __launch_bounds__(512) void k_gemm64h(const float* __restrict__ W2) {
    extern __shared__ uint32_t sg[];
    int tid = threadIdx.x, lane = tid & 31, w = tid >> 5;
    int grp = lane >> 2, tig = lane & 3;
    int wm = w >> 3, wn = w & 7;
    int row0 = blockIdx.x * 128;

    for (int i = tid; i < 64 * 32; i += 512) {
        int j = i >> 5, kp = i & 31;
        float e0 = W2[(2 * kp) * 64 + j];
        float e1 = W2[(2 * kp + 1) * 64 + j];
        uint32_t hi, lo; splith(e0, e1, hi, lo);
        sg[G2_BHI + j * 36 + kp] = hi;
        sg[G2_BLO + j * 36 + kp] = lo;
    }
#pragma unroll
    for (int i = 0; i < 8; i++) {
        int idx = tid + i * 512;
        int r = idx >> 5, kp = idx & 31;
        sg[G2_A + r * 36 + kp] = g_acth[(size_t)(row0 + r) * 32 + kp];
    }
    __syncthreads();

    float acc4[4][4] = {};
#pragma unroll
    for (int cs = 0; cs < 4; cs++) {
        int kb = cs * 8;
        int pb = (wn * 8 + grp) * 36 + kb;
        uint32_t b0h = sg[G2_BHI + pb + tig], b1h = sg[G2_BHI + pb + tig + 4];
        uint32_t b0l = sg[G2_BLO + pb + tig], b1l = sg[G2_BLO + pb + tig + 4];
#pragma unroll
        for (int mi = 0; mi < 4; mi++) {
            int rb = wm * 64 + mi * 16;
            uint32_t Ah[4];
            Ah[0] = sg[G2_A + (rb + grp) * 36 + kb + tig];
            Ah[1] = sg[G2_A + (rb + grp + 8) * 36 + kb + tig];
            Ah[2] = sg[G2_A + (rb + grp) * 36 + kb + tig + 4];
            Ah[3] = sg[G2_A + (rb + grp + 8) * 36 + kb + tig + 4];
            mma_f16(acc4[mi], Ah, b0h, b1h);
            mma_f16(acc4[mi], Ah, b0l, b1l);
        }
    }
#pragma unroll
    for (int mi = 0; mi < 4; mi++) {
#pragma unroll
        for (int rh = 0; rh < 2; rh++) {
            int row = row0 + wm * 64 + mi * 16 + grp + rh * 8;
            float dv = g_dinv[row];
            g_hs2h[(size_t)row * 32 + wn * 4 + tig] =
                packh(acc4[mi][rh * 2] * dv, acc4[mi][rh * 2 + 1] * dv);
        }
    }
}

// layer-2 aggregation: gather g_hs2h (fp16) -> bf16 hi/lo planes
__global__ void k_agg2bf(const float* __restrict__ b) {
    int gw = (blockIdx.x * blockDim.x + threadIdx.x) >> 5;
    int lane = threadIdx.x & 31;
    if (gw >= TT * NN) return;
    int deg = g_deg[gw];
    const int* bkt = g_bkt + (size_t)gw * CAP;
    const uint32_t* h2 = g_hs2h;
    float2 acc = __half22float2(*reinterpret_cast<const __half2*>(
                     h2 + (size_t)gw * 32 + lane));
    int e = 0;
    for (; e + 3 < deg; e += 4) {
        int s0 = bkt[e], s1 = bkt[e + 1], s2 = bkt[e + 2], s3 = bkt[e + 3];
        float2 v0 = __half22float2(*reinterpret_cast<const __half2*>(h2 + (size_t)s0 * 32 + lane));
        float2 v1 = __half22float2(*reinterpret_cast<const __half2*>(h2 + (size_t)s1 * 32 + lane));
        float2 v2 = __half22float2(*reinterpret_cast<const __half2*>(h2 + (size_t)s2 * 32 + lane));
        float2 v3 = __half22float2(*reinterpret_cast<const __half2*>(h2 + (size_t)s3 * 32 + lane));
        acc.x += (v0.x + v1.x) + (v2.x + v3.x);
        acc.y += (v0.y + v1.y) + (v2.y + v3.y);
    }
    for (; e < deg; e++) {
        int s0 = bkt[e];
        float2 v0 = __half22float2(*reinterpret_cast<const __half2*>(h2 + (size_t)s0 * 32 + lane));
        acc.x += v0.x; acc.y += v0.y;
    }
    float dv = g_dinv[gw];
    float2 bb = reinterpret_cast<const float2*>(b)[lane];
    float ox = fmaxf(fmaf(acc.x, dv, bb.x), 0.f);
    float oy = fmaxf(fmaf(acc.y, dv, bb.y), 0.f);
    uint32_t hi, lo; split2(ox, oy, hi, lo);
    g_shi[(size_t)gw * 32 + lane] = hi;
    g_slo[(size_t)gw * 32 + lane] = lo;
}

// fused LSTM over all T + head, bf16-split mma
#define L_XHI  0
#define L_XLO  4608
#define L_HHI  9216
#define L_HLO  13824
#define L_BHI  18432
#define L_BLO  35840
#define L_BIAS 53248
#define L_LOG  53504
#define L_TOT  53632

__global__ __launch_bounds__(512, 1) void k_lstm_bf16(
    const float* __restrict__ w_ih, const float* __restrict__ w_hh,
    const float* __restrict__ b_ih, const float* __restrict__ b_hh,
    const float* __restrict__ head_w, const float* __restrict__ head_b,
    float* __restrict__ out)
{
    extern __shared__ uint32_t sm_u[];
    float* sBias = reinterpret_cast<float*>(sm_u + L_BIAS);
    float* sLog  = reinterpret_cast<float*>(sm_u + L_LOG);

    int tid = threadIdx.x, lane = tid & 31, w = tid >> 5;
    int grp = lane >> 2, tig = lane & 3;
    int wm = w >> 3, wn = w & 7;
    int row0 = blockIdx.x * TILE_M;
    int j0 = (wn << 3) + tig, j1 = j0 + 4;

    for (int i = tid; i < 256 * 64; i += 512) {
        int p = i >> 6, kp = i & 63;
        int wnp = p >> 5, rem = p & 31, q = rem >> 3, e = rem & 7;
        int gate = ((q & 1) << 1) | (e & 1);
        int L = (gate << 6) + (wnp << 3) + ((q >> 1) << 2) + (e >> 1);
        int k = kp * 2;
        float2 v = (k < 64)
            ? *reinterpret_cast<const float2*>(w_ih + (size_t)L * 64 + k)
            : *reinterpret_cast<const float2*>(w_hh + (size_t)L * 64 + (k - 64));
        uint32_t hi, lo; split2(v.x, v.y, hi, lo);
        sm_u[L_BHI + p * 68 + kp] = hi;
        sm_u[L_BLO + p * 68 + kp] = lo;
    }
    for (int i = tid; i < 9216; i += 512) sm_u[L_HHI + i] = 0u;
    if (tid < 256) sBias[tid] = b_ih[tid] + b_hh[tid];
    if (tid < 128) sLog[tid] = 0.f;
#pragma unroll
    for (int i = 0; i < 8; i++) {
        int idx = tid + i * 512;
        int r = idx >> 5, c = idx & 31;
        int row = row0 + r;
        uint32_t hi = 0u, lo = 0u;
        if (row < NN) {
            hi = g_shi[(size_t)row * 32 + c];
            lo = g_slo[(size_t)row * 32 + c];
        }
        sm_u[L_XHI + r * 36 + c] = hi;
        sm_u[L_XLO + r * 36 + c] = lo;
    }
    float hw0 = head_w[j0], hw1 = head_w[j1];
    float creg[4][2][2];
#pragma unroll
    for (int a = 0; a < 4; a++)
#pragma unroll
        for (int b = 0; b < 2; b++) { creg[a][b][0] = 0.f; creg[a][b][1] = 0.f; }
    __syncthreads();

    for (int t = 0; t < TT; t++) {
        float acc[4][4][4] = {};
#pragma unroll 1
        for (int cs = 0; cs < 8; cs++) {
            const uint32_t* Ahi;
            const uint32_t* Alo;
            int kb;
            if (cs < 4) { Ahi = sm_u + L_XHI; Alo = sm_u + L_XLO; kb = cs * 8; }
            else        { Ahi = sm_u + L_HHI; Alo = sm_u + L_HLO; kb = (cs - 4) * 8; }
            int kb2 = cs * 8;
            uint32_t Bh[4][2], Bl[4][2];
#pragma unroll
            for (int q = 0; q < 4; q++) {
                int pb = ((wn << 5) + (q << 3) + grp) * 68 + kb2;
                Bh[q][0] = sm_u[L_BHI + pb + tig];
                Bh[q][1] = sm_u[L_BHI + pb + tig + 4];
                Bl[q][0] = sm_u[L_BLO + pb + tig];
                Bl[q][1] = sm_u[L_BLO + pb + tig + 4];
            }
#pragma unroll
            for (int mi = 0; mi < 4; mi++) {
                int rb = wm * 64 + mi * 16;
                uint32_t Ah[4], Al[4];
                Ah[0] = Ahi[(rb + grp) * 36 + kb + tig];
                Ah[1] = Ahi[(rb + grp + 8) * 36 + kb + tig];
                Ah[2] = Ahi[(rb + grp) * 36 + kb + tig + 4];
                Ah[3] = Ahi[(rb + grp + 8) * 36 + kb + tig + 4];
                Al[0] = Alo[(rb + grp) * 36 + kb + tig];
                Al[1] = Alo[(rb + grp + 8) * 36 + kb + tig];
                Al[2] = Alo[(rb + grp) * 36 + kb + tig + 4];
                Al[3] = Alo[(rb + grp + 8) * 36 + kb + tig + 4];
#pragma unroll
                for (int q = 0; q < 4; q++) {
                    mma_bf16(acc[mi][q], Ah, Bh[q][0], Bh[q][1]);
                    mma_bf16(acc[mi][q], Ah, Bl[q][0], Bl[q][1]);
                    mma_bf16(acc[mi][q], Al, Bh[q][0], Bh[q][1]);
                }
            }
        }
        __syncthreads();

        uint32_t rxh[8], rxl[8];
        if (t < TT - 1) {
            const uint32_t* ph = g_shi + (size_t)(t + 1) * NN * 32;
            const uint32_t* pl = g_slo + (size_t)(t + 1) * NN * 32;
#pragma unroll
            for (int i = 0; i < 8; i++) {
                int idx = tid + i * 512;
                int r = idx >> 5, c = idx & 31;
                int row = row0 + r;
                rxh[i] = (row < NN) ? ph[(size_t)row * 32 + c] : 0u;
                rxl[i] = (row < NN) ? pl[(size_t)row * 32 + c] : 0u;
            }
        }

        float bi0 = sBias[j0], bf0_ = sBias[64 + j0], bg0 = sBias[128 + j0], bo0 = sBias[192 + j0];
        float bi1 = sBias[j1], bf1_ = sBias[64 + j1], bg1 = sBias[128 + j1], bo1 = sBias[192 + j1];
#pragma unroll
        for (int mi = 0; mi < 4; mi++) {
#pragma unroll
            for (int rh = 0; rh < 2; rh++) {
                int r = wm * 64 + mi * 16 + grp + rh * 8;
                int ci = rh * 2;
                float gi0 = acc[mi][0][ci] + bi0, gf0 = acc[mi][0][ci + 1] + bf0_;
                float gg0 = acc[mi][1][ci] + bg0, go0 = acc[mi][1][ci + 1] + bo0;
                float gi1 = acc[mi][2][ci] + bi1, gf1 = acc[mi][2][ci + 1] + bf1_;
                float gg1 = acc[mi][3][ci] + bg1, go1 = acc[mi][3][ci + 1] + bo1;
                float c0 = creg[mi][rh][0], c1 = creg[mi][rh][1];
                c0 = sigf(gf0) * c0 + sigf(gi0) * tanhf_fast(gg0);
                c1 = sigf(gf1) * c1 + sigf(gi1) * tanhf_fast(gg1);
                creg[mi][rh][0] = c0; creg[mi][rh][1] = c1;
                float h0 = sigf(go0) * tanhf_fast(c0);
                float h1 = sigf(go1) * tanhf_fast(c1);
                if (t < TT - 1) {
                    int base0 = r * 36 + (j0 >> 1);
                    int sl = j0 & 1;
                    __nv_bfloat16 b0 = __float2bfloat16(h0);
                    reinterpret_cast<__nv_bfloat16*>(&sm_u[L_HHI + base0])[sl] = b0;
                    reinterpret_cast<__nv_bfloat16*>(&sm_u[L_HLO + base0])[sl] =
                        __float2bfloat16(h0 - __bfloat162float(b0));
                    __nv_bfloat16 b1 = __float2bfloat16(h1);
                    reinterpret_cast<__nv_bfloat16*>(&sm_u[L_HHI + base0 + 2])[sl] = b1;
                    reinterpret_cast<__nv_bfloat16*>(&sm_u[L_HLO + base0 + 2])[sl] =
                        __float2bfloat16(h1 - __bfloat162float(b1));
                } else {
                    float v = h0 * hw0 + h1 * hw1;
                    v += __shfl_xor_sync(0xffffffffu, v, 1);
                    v += __shfl_xor_sync(0xffffffffu, v, 2);
                    if (tig == 0) atomicAdd(&sLog[r], v);
                }
            }
        }

        if (t < TT - 1) {
#pragma unroll
            for (int i = 0; i < 8; i++) {
                int idx = tid + i * 512;
                int r = idx >> 5, c = idx & 31;
                sm_u[L_XHI + r * 36 + c] = rxh[i];
                sm_u[L_XLO + r * 36 + c] = rxl[i];
            }
        }
        __syncthreads();
    }

    if (tid < 128) {
        int row = row0 + tid;
        if (row < NN) out[row] = sLog[tid] + head_b[0];
    }
}

extern "C" void kernel_launch(void* const* d_in, const int* in_sizes, int n_in,
                              void* d_out, int out_size) {
    const float* xs  = (const float*)d_in[0];
    const int*   ei  = (const int*)  d_in[1];
    const float* W1  = (const float*)d_in[2];
    const float* b1  = (const float*)d_in[3];
    const float* W2  = (const float*)d_in[4];
    const float* b2  = (const float*)d_in[5];
    const float* wih = (const float*)d_in[6];
    const float* whh = (const float*)d_in[7];
    const float* bih = (const float*)d_in[8];
    const float* bhh = (const float*)d_in[9];
    const float* hw  = (const float*)d_in[10];
    const float* hb  = (const float*)d_in[11];
    float* out = (float*)d_out;

    cudaFuncSetAttribute(k_lstm_bf16,
                         cudaFuncAttributeMaxDynamicSharedMemorySize, L_TOT * 4);
    cudaFuncSetAttribute(k_gemm64h,
                         cudaFuncAttributeMaxDynamicSharedMemorySize, G2_TOT * 4);

    k_init<<<(TT * NN + 255) / 256, 256>>>();
    k_fill_bucket<<<(TT * EE + 255) / 256, 256>>>(ei);

    k_gemm1h<<<(TT * NN + 127) / 128, 128>>>(xs, W1);
    k_agg1h<<<((size_t)TT * NN * 32 + 511) / 512, 512>>>(b1);
    k_gemm64h<<<(TT * NN) / 128, 512, G2_TOT * 4>>>(W2);
    k_agg2bf<<<((size_t)TT * NN * 32 + 511) / 512, 512>>>(b2);

    k_lstm_bf16<<<NBLK, 512, L_TOT * 4>>>(wih, whh, bih, bhh, hw, hb, out);
}

// round 10
// speedup vs baseline: 1.3175x; 1.0417x over previous
#include <cuda_runtime.h>
#include <cuda_fp16.h>
#include <cuda_bf16.h>
#include <math.h>
#include <stdint.h>

#define NN  50000
#define TT  8
#define EE  800000
#define FIN 9
#define HH  64
#define CAP 96
#define TILE_M 128
#define NBLK ((NN + TILE_M - 1) / TILE_M)

__device__ int      g_deg [TT * NN];
__device__ int      g_bkt [(size_t)TT * NN * CAP];  // pre-scaled word offsets: (t*NN+s)*32
__device__ float    g_dinv[TT * NN];
__device__ uint32_t g_hsh [TT * NN * 32];   // layer-1 hs (dinv-scaled), half2
__device__ uint32_t g_acth[TT * NN * 32];   // layer-1 activation, half2
__device__ uint32_t g_hs2h[TT * NN * 32];   // layer-2 hs, half2
__device__ uint32_t g_shi [TT * NN * 32];   // seq bf16-hi
__device__ uint32_t g_slo [TT * NN * 32];   // seq bf16-lo

// ---------------- MUFU-based nonlinearities --------------------------------
__device__ __forceinline__ float tanh_mufu(float x) {
    float y;
    asm("tanh.approx.f32 %0, %1;" : "=f"(y) : "f"(x));
    return y;
}
__device__ __forceinline__ float sig_mufu(float x) {
    return fmaf(tanh_mufu(x * 0.5f), 0.5f, 0.5f);
}

__device__ __forceinline__ uint32_t packbf(float e0, float e1) {
    uint32_t r;
    asm("cvt.rn.bf16x2.f32 %0, %1, %2;" : "=r"(r) : "f"(e1), "f"(e0));
    return r;
}
__device__ __forceinline__ float2 unpackbf(uint32_t u) {
    __nv_bfloat162 b = *reinterpret_cast<__nv_bfloat162*>(&u);
    return make_float2(__bfloat162float(b.x), __bfloat162float(b.y));
}
__device__ __forceinline__ void split2(float e0, float e1, uint32_t& hi, uint32_t& lo) {
    hi = packbf(e0, e1);
    float2 hf = unpackbf(hi);
    lo = packbf(e0 - hf.x, e1 - hf.y);
}
__device__ __forceinline__ uint32_t packh(float e0, float e1) {
    __half2 p = __floats2half2_rn(e0, e1);
    return *reinterpret_cast<uint32_t*>(&p);
}
__device__ __forceinline__ void splith(float e0, float e1, uint32_t& hi, uint32_t& lo) {
    __half2 p = __floats2half2_rn(e0, e1);
    float2 hf = __half22float2(p);
    hi = *reinterpret_cast<uint32_t*>(&p);
    lo = packh(e0 - hf.x, e1 - hf.y);
}
__device__ __forceinline__ void mma_bf16(float* d, const uint32_t* a,
                                         uint32_t b0, uint32_t b1) {
    asm volatile(
        "mma.sync.aligned.m16n8k16.row.col.f32.bf16.bf16.f32 "
        "{%0,%1,%2,%3}, {%4,%5,%6,%7}, {%8,%9}, {%0,%1,%2,%3};"
        : "+f"(d[0]), "+f"(d[1]), "+f"(d[2]), "+f"(d[3])
        : "r"(a[0]), "r"(a[1]), "r"(a[2]), "r"(a[3]), "r"(b0), "r"(b1));
}
__device__ __forceinline__ void mma_f16(float* d, const uint32_t* a,
                                        uint32_t b0, uint32_t b1) {
    asm volatile(
        "mma.sync.aligned.m16n8k16.row.col.f32.f16.f16.f32 "
        "{%0,%1,%2,%3}, {%4,%5,%6,%7}, {%8,%9}, {%0,%1,%2,%3};"
        : "+f"(d[0]), "+f"(d[1]), "+f"(d[2]), "+f"(d[3])
        : "r"(a[0]), "r"(a[1]), "r"(a[2]), "r"(a[3]), "r"(b0), "r"(b1));
}

__global__ void k_init() {
    int i0 = blockIdx.x * blockDim.x + threadIdx.x;
    for (int i = i0; i < TT * NN; i += gridDim.x * blockDim.x) g_deg[i] = 0;
}

// single-pass bucket scatter; store pre-scaled word offset
__global__ void k_fill_bucket(const int* __restrict__ ei) {
    int idx = blockIdx.x * blockDim.x + threadIdx.x;
    if (idx >= TT * EE) return;
    int t = idx / EE, e = idx - t * EE;
    int s = ei[(size_t)t * 2 * EE + e];
    int d = ei[(size_t)t * 2 * EE + EE + e];
    int td = t * NN + d;
    int pos = atomicAdd(&g_deg[td], 1);
    g_bkt[(size_t)td * CAP + pos] = (t * NN + s) * 32;
}

// layer-1 GEMM (K=9): coalesced x staging; dinv; -> half2 g_hsh
__global__ __launch_bounds__(128) void k_gemm1h(
    const float* __restrict__ x, const float* __restrict__ W1)
{
    __shared__ float sW[FIN * HH];
    __shared__ float sX[128 * FIN];
    int tid = threadIdx.x;
    for (int i = tid; i < FIN * HH; i += 128) sW[i] = W1[i];
    int base = blockIdx.x * 128;
#pragma unroll
    for (int i = 0; i < FIN; i++) {
        int idx = tid + i * 128;
        sX[idx] = x[(size_t)base * FIN + idx];
    }
    __syncthreads();
    int n = base + tid;
    if (n >= TT * NN) return;
    float dv = rsqrtf((float)(g_deg[n] + 1));
    g_dinv[n] = dv;
    float xv[FIN];
#pragma unroll
    for (int k = 0; k < FIN; k++) xv[k] = sX[tid * FIN + k];
#pragma unroll
    for (int c = 0; c < HH; c += 4) {
        float4 o = make_float4(0.f, 0.f, 0.f, 0.f);
#pragma unroll
        for (int k = 0; k < FIN; k++) {
            float xk = xv[k];
            o.x = fmaf(xk, sW[k * HH + c + 0], o.x);
            o.y = fmaf(xk, sW[k * HH + c + 1], o.y);
            o.z = fmaf(xk, sW[k * HH + c + 2], o.z);
            o.w = fmaf(xk, sW[k * HH + c + 3], o.w);
        }
        uint2 u;
        u.x = packh(o.x * dv, o.y * dv);
        u.y = packh(o.z * dv, o.w * dv);
        *reinterpret_cast<uint2*>(g_hsh + (size_t)n * 32 + c / 2) = u;
    }
}

// layer-1 aggregation: fp16 gather w/ pairwise HADD2 -> g_acth
__global__ void k_agg1h(const float* __restrict__ b1) {
    int gw = (blockIdx.x * blockDim.x + threadIdx.x) >> 5;
    int lane = threadIdx.x & 31;
    if (gw >= TT * NN) return;
    int deg = g_deg[gw];
    const int* bkt = g_bkt + (size_t)gw * CAP;
    const __half2* hsh = reinterpret_cast<const __half2*>(g_hsh);
    float2 acc = __half22float2(hsh[(size_t)gw * 32 + lane]);
    int e = 0;
    for (; e + 3 < deg; e += 4) {
        int o0 = bkt[e], o1 = bkt[e + 1], o2 = bkt[e + 2], o3 = bkt[e + 3];
        __half2 v0 = hsh[o0 + lane];
        __half2 v1 = hsh[o1 + lane];
        __half2 v2 = hsh[o2 + lane];
        __half2 v3 = hsh[o3 + lane];
        float2 p01 = __half22float2(__hadd2(v0, v1));
        float2 p23 = __half22float2(__hadd2(v2, v3));
        acc.x += p01.x + p23.x;
        acc.y += p01.y + p23.y;
    }
    for (; e < deg; e++) {
        float2 v0 = __half22float2(hsh[bkt[e] + lane]);
        acc.x += v0.x; acc.y += v0.y;
    }
    float dv = g_dinv[gw];
    float2 bb = reinterpret_cast<const float2*>(b1)[lane];
    float ax = fmaxf(fmaf(acc.x, dv, bb.x), 0.f);
    float ay = fmaxf(fmaf(acc.y, dv, bb.y), 0.f);
    g_acth[(size_t)gw * 32 + lane] = packh(ax, ay);
}

// layer-2 GEMM: A = g_acth (exact fp16) @ W2 (fp16 hi/lo) * dinv -> g_hs2h
#define G2_A   0
#define G2_BHI 4608
#define G2_BLO 6912
#define G2_TOT 9216

__global__ __launch_bounds__(512) void k_gemm64h(const float* __restrict__ W2) {
    extern __shared__ uint32_t sg[];
    int tid = threadIdx.x, lane = tid & 31, w = tid >> 5;
    int grp = lane >> 2, tig = lane & 3;
    int wm = w >> 3, wn = w & 7;
    int row0 = blockIdx.x * 128;

    for (int i = tid; i < 64 * 32; i += 512) {
        int j = i >> 5, kp = i & 31;
        float e0 = W2[(2 * kp) * 64 + j];
        float e1 = W2[(2 * kp + 1) * 64 + j];
        uint32_t hi, lo; splith(e0, e1, hi, lo);
        sg[G2_BHI + j * 36 + kp] = hi;
        sg[G2_BLO + j * 36 + kp] = lo;
    }
#pragma unroll
    for (int i = 0; i < 8; i++) {
        int idx = tid + i * 512;
        int r = idx >> 5, kp = idx & 31;
        sg[G2_A + r * 36 + kp] = g_acth[(size_t)(row0 + r) * 32 + kp];
    }
    __syncthreads();

    float acc4[4][4] = {};
#pragma unroll
    for (int cs = 0; cs < 4; cs++) {
        int kb = cs * 8;
        int pb = (wn * 8 + grp) * 36 + kb;
        uint32_t b0h = sg[G2_BHI + pb + tig], b1h = sg[G2_BHI + pb + tig + 4];
        uint32_t b0l = sg[G2_BLO + pb + tig], b1l = sg[G2_BLO + pb + tig + 4];
#pragma unroll
        for (int mi = 0; mi < 4; mi++) {
            int rb = wm * 64 + mi * 16;
            uint32_t Ah[4];
            Ah[0] = sg[G2_A + (rb + grp) * 36 + kb + tig];
            Ah[1] = sg[G2_A + (rb + grp + 8) * 36 + kb + tig];
            Ah[2] = sg[G2_A + (rb + grp) * 36 + kb + tig + 4];
            Ah[3] = sg[G2_A + (rb + grp + 8) * 36 + kb + tig + 4];
            mma_f16(acc4[mi], Ah, b0h, b1h);
            mma_f16(acc4[mi], Ah, b0l, b1l);
        }
    }
#pragma unroll
    for (int mi = 0; mi < 4; mi++) {
#pragma unroll
        for (int rh = 0; rh < 2; rh++) {
            int row = row0 + wm * 64 + mi * 16 + grp + rh * 8;
            float dv = g_dinv[row];
            g_hs2h[(size_t)row * 32 + wn * 4 + tig] =
                packh(acc4[mi][rh * 2] * dv, acc4[mi][rh * 2 + 1] * dv);
        }
    }
}

// layer-2 aggregation: fp16 gather w/ pairwise HADD2 -> bf16 hi/lo planes
__global__ void k_agg2bf(const float* __restrict__ b) {
    int gw = (blockIdx.x * blockDim.x + threadIdx.x) >> 5;
    int lane = threadIdx.x & 31;
    if (gw >= TT * NN) return;
    int deg = g_deg[gw];
    const int* bkt = g_bkt + (size_t)gw * CAP;
    const __half2* h2 = reinterpret_cast<const __half2*>(g_hs2h);
    float2 acc = __half22float2(h2[(size_t)gw * 32 + lane]);
    int e = 0;
    for (; e + 3 < deg; e += 4) {
        int o0 = bkt[e], o1 = bkt[e + 1], o2 = bkt[e + 2], o3 = bkt[e + 3];
        __half2 v0 = h2[o0 + lane];
        __half2 v1 = h2[o1 + lane];
        __half2 v2 = h2[o2 + lane];
        __half2 v3 = h2[o3 + lane];
        float2 p01 = __half22float2(__hadd2(v0, v1));
        float2 p23 = __half22float2(__hadd2(v2, v3));
        acc.x += p01.x + p23.x;
        acc.y += p01.y + p23.y;
    }
    for (; e < deg; e++) {
        float2 v0 = __half22float2(h2[bkt[e] + lane]);
        acc.x += v0.x; acc.y += v0.y;
    }
    float dv = g_dinv[gw];
    float2 bb = reinterpret_cast<const float2*>(b)[lane];
    float ox = fmaxf(fmaf(acc.x, dv, bb.x), 0.f);
    float oy = fmaxf(fmaf(acc.y, dv, bb.y), 0.f);
    uint32_t hi, lo; split2(ox, oy, hi, lo);
    g_shi[(size_t)gw * 32 + lane] = hi;
    g_slo[(size_t)gw * 32 + lane] = lo;
}

// fused LSTM over all T + head, bf16-split mma, MUFU gates
#define L_XHI  0
#define L_XLO  4608
#define L_HHI  9216
#define L_HLO  13824
#define L_BHI  18432
#define L_BLO  35840
#define L_BIAS 53248
#define L_LOG  53504
#define L_TOT  53632

__global__ __launch_bounds__(512, 1) void k_lstm_bf16(
    const float* __restrict__ w_ih, const float* __restrict__ w_hh,
    const float* __restrict__ b_ih, const float* __restrict__ b_hh,
    const float* __restrict__ head_w, const float* __restrict__ head_b,
    float* __restrict__ out)
{
    extern __shared__ uint32_t sm_u[];
    float* sBias = reinterpret_cast<float*>(sm_u + L_BIAS);
    float* sLog  = reinterpret_cast<float*>(sm_u + L_LOG);

    int tid = threadIdx.x, lane = tid & 31, w = tid >> 5;
    int grp = lane >> 2, tig = lane & 3;
    int wm = w >> 3, wn = w & 7;
    int row0 = blockIdx.x * TILE_M;
    int j0 = (wn << 3) + tig, j1 = j0 + 4;

    for (int i = tid; i < 256 * 64; i += 512) {
        int p = i >> 6, kp = i & 63;
        int wnp = p >> 5, rem = p & 31, q = rem >> 3, e = rem & 7;
        int gate = ((q & 1) << 1) | (e & 1);
        int L = (gate << 6) + (wnp << 3) + ((q >> 1) << 2) + (e >> 1);
        int k = kp * 2;
        float2 v = (k < 64)
            ? *reinterpret_cast<const float2*>(w_ih + (size_t)L * 64 + k)
            : *reinterpret_cast<const float2*>(w_hh + (size_t)L * 64 + (k - 64));
        uint32_t hi, lo; split2(v.x, v.y, hi, lo);
        sm_u[L_BHI + p * 68 + kp] = hi;
        sm_u[L_BLO + p * 68 + kp] = lo;
    }
    for (int i = tid; i < 9216; i += 512) sm_u[L_HHI + i] = 0u;
    if (tid < 256) sBias[tid] = b_ih[tid] + b_hh[tid];
    if (tid < 128) sLog[tid] = 0.f;
#pragma unroll
    for (int i = 0; i < 8; i++) {
        int idx = tid + i * 512;
        int r = idx >> 5, c = idx & 31;
        int row = row0 + r;
        uint32_t hi = 0u, lo = 0u;
        if (row < NN) {
            hi = g_shi[(size_t)row * 32 + c];
            lo = g_slo[(size_t)row * 32 + c];
        }
        sm_u[L_XHI + r * 36 + c] = hi;
        sm_u[L_XLO + r * 36 + c] = lo;
    }
    float hw0 = head_w[j0], hw1 = head_w[j1];
    float creg[4][2][2];
#pragma unroll
    for (int a = 0; a < 4; a++)
#pragma unroll
        for (int b = 0; b < 2; b++) { creg[a][b][0] = 0.f; creg[a][b][1] = 0.f; }
    __syncthreads();

    for (int t = 0; t < TT; t++) {
        float acc[4][4][4] = {};
#pragma unroll 1
        for (int cs = 0; cs < 8; cs++) {
            const uint32_t* Ahi;
            const uint32_t* Alo;
            int kb;
            if (cs < 4) { Ahi = sm_u + L_XHI; Alo = sm_u + L_XLO; kb = cs * 8; }
            else        { Ahi = sm_u + L_HHI; Alo = sm_u + L_HLO; kb = (cs - 4) * 8; }
            int kb2 = cs * 8;
            uint32_t Bh[4][2], Bl[4][2];
#pragma unroll
            for (int q = 0; q < 4; q++) {
                int pb = ((wn << 5) + (q << 3) + grp) * 68 + kb2;
                Bh[q][0] = sm_u[L_BHI + pb + tig];
                Bh[q][1] = sm_u[L_BHI + pb + tig + 4];
                Bl[q][0] = sm_u[L_BLO + pb + tig];
                Bl[q][1] = sm_u[L_BLO + pb + tig + 4];
            }
#pragma unroll
            for (int mi = 0; mi < 4; mi++) {
                int rb = wm * 64 + mi * 16;
                uint32_t Ah[4], Al[4];
                Ah[0] = Ahi[(rb + grp) * 36 + kb + tig];
                Ah[1] = Ahi[(rb + grp + 8) * 36 + kb + tig];
                Ah[2] = Ahi[(rb + grp) * 36 + kb + tig + 4];
                Ah[3] = Ahi[(rb + grp + 8) * 36 + kb + tig + 4];
                Al[0] = Alo[(rb + grp) * 36 + kb + tig];
                Al[1] = Alo[(rb + grp + 8) * 36 + kb + tig];
                Al[2] = Alo[(rb + grp) * 36 + kb + tig + 4];
                Al[3] = Alo[(rb + grp + 8) * 36 + kb + tig + 4];
#pragma unroll
                for (int q = 0; q < 4; q++) {
                    mma_bf16(acc[mi][q], Ah, Bh[q][0], Bh[q][1]);
                    mma_bf16(acc[mi][q], Ah, Bl[q][0], Bl[q][1]);
                    mma_bf16(acc[mi][q], Al, Bh[q][0], Bh[q][1]);
                }
            }
        }
        __syncthreads();

        uint32_t rxh[8], rxl[8];
        if (t < TT - 1) {
            const uint32_t* ph = g_shi + (size_t)(t + 1) * NN * 32;
            const uint32_t* pl = g_slo + (size_t)(t + 1) * NN * 32;
#pragma unroll
            for (int i = 0; i < 8; i++) {
                int idx = tid + i * 512;
                int r = idx >> 5, c = idx & 31;
                int row = row0 + r;
                rxh[i] = (row < NN) ? ph[(size_t)row * 32 + c] : 0u;
                rxl[i] = (row < NN) ? pl[(size_t)row * 32 + c] : 0u;
            }
        }

        float bi0 = sBias[j0], bf0_ = sBias[64 + j0], bg0 = sBias[128 + j0], bo0 = sBias[192 + j0];
        float bi1 = sBias[j1], bf1_ = sBias[64 + j1], bg1 = sBias[128 + j1], bo1 = sBias[192 + j1];
#pragma unroll
        for (int mi = 0; mi < 4; mi++) {
#pragma unroll
            for (int rh = 0; rh < 2; rh++) {
                int r = wm * 64 + mi * 16 + grp + rh * 8;
                int ci = rh * 2;
                float gi0 = acc[mi][0][ci] + bi0, gf0 = acc[mi][0][ci + 1] + bf0_;
                float gg0 = acc[mi][1][ci] + bg0, go0 = acc[mi][1][ci + 1] + bo0;
                float gi1 = acc[mi][2][ci] + bi1, gf1 = acc[mi][2][ci + 1] + bf1_;
                float gg1 = acc[mi][3][ci] + bg1, go1 = acc[mi][3][ci + 1] + bo1;
                float c0 = creg[mi][rh][0], c1 = creg[mi][rh][1];
                c0 = sig_mufu(gf0) * c0 + sig_mufu(gi0) * tanh_mufu(gg0);
                c1 = sig_mufu(gf1) * c1 + sig_mufu(gi1) * tanh_mufu(gg1);
                creg[mi][rh][0] = c0; creg[mi][rh][1] = c1;
                float h0 = sig_mufu(go0) * tanh_mufu(c0);
                float h1 = sig_mufu(go1) * tanh_mufu(c1);
                if (t < TT - 1) {
                    int base0 = r * 36 + (j0 >> 1);
                    int sl = j0 & 1;
                    __nv_bfloat16 b0 = __float2bfloat16(h0);
                    reinterpret_cast<__nv_bfloat16*>(&sm_u[L_HHI + base0])[sl] = b0;
                    reinterpret_cast<__nv_bfloat16*>(&sm_u[L_HLO + base0])[sl] =
                        __float2bfloat16(h0 - __bfloat162float(b0));
                    __nv_bfloat16 b1 = __float2bfloat16(h1);
                    reinterpret_cast<__nv_bfloat16*>(&sm_u[L_HHI + base0 + 2])[sl] = b1;
                    reinterpret_cast<__nv_bfloat16*>(&sm_u[L_HLO + base0 + 2])[sl] =
                        __float2bfloat16(h1 - __bfloat162float(b1));
                } else {
                    float v = h0 * hw0 + h1 * hw1;
                    v += __shfl_xor_sync(0xffffffffu, v, 1);
                    v += __shfl_xor_sync(0xffffffffu, v, 2);
                    if (tig == 0) atomicAdd(&sLog[r], v);
                }
            }
        }

        if (t < TT - 1) {
#pragma unroll
            for (int i = 0; i < 8; i++) {
                int idx = tid + i * 512;
                int r = idx >> 5, c = idx & 31;
                sm_u[L_XHI + r * 36 + c] = rxh[i];
                sm_u[L_XLO + r * 36 + c] = rxl[i];
            }
        }
        __syncthreads();
    }

    if (tid < 128) {
        int row = row0 + tid;
        if (row < NN) out[row] = sLog[tid] + head_b[0];
    }
}

extern "C" void kernel_launch(void* const* d_in, const int* in_sizes, int n_in,
                              void* d_out, int out_size) {
    const float* xs  = (const float*)d_in[0];
    const int*   ei  = (const int*)  d_in[1];
    const float* W1  = (const float*)d_in[2];
    const float* b1  = (const float*)d_in[3];
    const float* W2  = (const float*)d_in[4];
    const float* b2  = (const float*)d_in[5];
    const float* wih = (const float*)d_in[6];
    const float* whh = (const float*)d_in[7];
    const float* bih = (const float*)d_in[8];
    const float* bhh = (const float*)d_in[9];
    const float* hw  = (const float*)d_in[10];
    const float* hb  = (const float*)d_in[11];
    float* out = (float*)d_out;

    cudaFuncSetAttribute(k_lstm_bf16,
                         cudaFuncAttributeMaxDynamicSharedMemorySize, L_TOT * 4);
    cudaFuncSetAttribute(k_gemm64h,
                         cudaFuncAttributeMaxDynamicSharedMemorySize, G2_TOT * 4);

    k_init<<<(TT * NN + 255) / 256, 256>>>();
    k_fill_bucket<<<(TT * EE + 255) / 256, 256>>>(ei);

    k_gemm1h<<<(TT * NN + 127) / 128, 128>>>(xs, W1);
    k_agg1h<<<((size_t)TT * NN * 32 + 511) / 512, 512>>>(b1);
    k_gemm64h<<<(TT * NN) / 128, 512, G2_TOT * 4>>>(W2);
    k_agg2bf<<<((size_t)TT * NN * 32 + 511) / 512, 512>>>(b2);

    k_lstm_bf16<<<NBLK, 512, L_TOT * 4>>>(wih, whh, bih, bhh, hw, hb, out);
}

// round 11
// speedup vs baseline: 1.5350x; 1.1651x over previous
#include <cuda_runtime.h>
#include <cuda_fp16.h>
#include <cuda_bf16.h>
#include <math.h>
#include <stdint.h>

#define NN  50000
#define TT  8
#define EE  800000
#define FIN 9
#define HH  64
#define CAP 96
#define TILE_M 128
#define NBLK ((NN + TILE_M - 1) / TILE_M)

__device__ int      g_deg [TT * NN];
__device__ int      g_bkt [(size_t)TT * NN * CAP];  // pre-scaled word offsets
__device__ float    g_dinv[TT * NN];
__device__ uint32_t g_hsh [TT * NN * 32];   // layer-1 hs (dinv-scaled), half2
__device__ uint32_t g_acth[TT * NN * 32];   // layer-1 activation, half2
__device__ uint32_t g_hs2h[TT * NN * 32];   // layer-2 hs, half2
__device__ uint32_t g_seqh[TT * NN * 32];   // seq, half2 (single plane)

// ---------------- MUFU-based nonlinearities --------------------------------
__device__ __forceinline__ float tanh_mufu(float x) {
    float y;
    asm("tanh.approx.f32 %0, %1;" : "=f"(y) : "f"(x));
    return y;
}
__device__ __forceinline__ float sig_mufu(float x) {
    return fmaf(tanh_mufu(x * 0.5f), 0.5f, 0.5f);
}

__device__ __forceinline__ uint32_t packh(float e0, float e1) {
    __half2 p = __floats2half2_rn(e0, e1);
    return *reinterpret_cast<uint32_t*>(&p);
}
__device__ __forceinline__ void splith(float e0, float e1, uint32_t& hi, uint32_t& lo) {
    __half2 p = __floats2half2_rn(e0, e1);
    float2 hf = __half22float2(p);
    hi = *reinterpret_cast<uint32_t*>(&p);
    lo = packh(e0 - hf.x, e1 - hf.y);
}
__device__ __forceinline__ void mma_f16(float* d, const uint32_t* a,
                                        uint32_t b0, uint32_t b1) {
    asm volatile(
        "mma.sync.aligned.m16n8k16.row.col.f32.f16.f16.f32 "
        "{%0,%1,%2,%3}, {%4,%5,%6,%7}, {%8,%9}, {%0,%1,%2,%3};"
        : "+f"(d[0]), "+f"(d[1]), "+f"(d[2]), "+f"(d[3])
        : "r"(a[0]), "r"(a[1]), "r"(a[2]), "r"(a[3]), "r"(b0), "r"(b1));
}

__global__ void k_init() {
    int i0 = blockIdx.x * blockDim.x + threadIdx.x;
    for (int i = i0; i < TT * NN; i += gridDim.x * blockDim.x) g_deg[i] = 0;
}

__global__ void k_fill_bucket(const int* __restrict__ ei) {
    int idx = blockIdx.x * blockDim.x + threadIdx.x;
    if (idx >= TT * EE) return;
    int t = idx / EE, e = idx - t * EE;
    int s = ei[(size_t)t * 2 * EE + e];
    int d = ei[(size_t)t * 2 * EE + EE + e];
    int td = t * NN + d;
    int pos = atomicAdd(&g_deg[td], 1);
    g_bkt[(size_t)td * CAP + pos] = (t * NN + s) * 32;
}

// layer-1 GEMM (K=9): coalesced x staging; dinv; -> half2 g_hsh
__global__ __launch_bounds__(128) void k_gemm1h(
    const float* __restrict__ x, const float* __restrict__ W1)
{
    __shared__ float sW[FIN * HH];
    __shared__ float sX[128 * FIN];
    int tid = threadIdx.x;
    for (int i = tid; i < FIN * HH; i += 128) sW[i] = W1[i];
    int base = blockIdx.x * 128;
#pragma unroll
    for (int i = 0; i < FIN; i++) {
        int idx = tid + i * 128;
        sX[idx] = x[(size_t)base * FIN + idx];
    }
    __syncthreads();
    int n = base + tid;
    if (n >= TT * NN) return;
    float dv = rsqrtf((float)(g_deg[n] + 1));
    g_dinv[n] = dv;
    float xv[FIN];
#pragma unroll
    for (int k = 0; k < FIN; k++) xv[k] = sX[tid * FIN + k];
#pragma unroll
    for (int c = 0; c < HH; c += 4) {
        float4 o = make_float4(0.f, 0.f, 0.f, 0.f);
#pragma unroll
        for (int k = 0; k < FIN; k++) {
            float xk = xv[k];
            o.x = fmaf(xk, sW[k * HH + c + 0], o.x);
            o.y = fmaf(xk, sW[k * HH + c + 1], o.y);
            o.z = fmaf(xk, sW[k * HH + c + 2], o.z);
            o.w = fmaf(xk, sW[k * HH + c + 3], o.w);
        }
        uint2 u;
        u.x = packh(o.x * dv, o.y * dv);
        u.y = packh(o.z * dv, o.w * dv);
        *reinterpret_cast<uint2*>(g_hsh + (size_t)n * 32 + c / 2) = u;
    }
}

// ---------- generic fp16 gather body, unroll-8 (MLP=8) ---------------------
__device__ __forceinline__ float2 gather16(const __half2* __restrict__ src,
                                           const int* __restrict__ bkt,
                                           int deg, int gw, int lane) {
    float2 acc = __half22float2(src[(size_t)gw * 32 + lane]);
    int e = 0;
    for (; e + 7 < deg; e += 8) {
        int o0 = bkt[e],     o1 = bkt[e + 1], o2 = bkt[e + 2], o3 = bkt[e + 3];
        int o4 = bkt[e + 4], o5 = bkt[e + 5], o6 = bkt[e + 6], o7 = bkt[e + 7];
        __half2 v0 = src[o0 + lane], v1 = src[o1 + lane];
        __half2 v2 = src[o2 + lane], v3 = src[o3 + lane];
        __half2 v4 = src[o4 + lane], v5 = src[o5 + lane];
        __half2 v6 = src[o6 + lane], v7 = src[o7 + lane];
        float2 p01 = __half22float2(__hadd2(v0, v1));
        float2 p23 = __half22float2(__hadd2(v2, v3));
        float2 p45 = __half22float2(__hadd2(v4, v5));
        float2 p67 = __half22float2(__hadd2(v6, v7));
        acc.x += (p01.x + p23.x) + (p45.x + p67.x);
        acc.y += (p01.y + p23.y) + (p45.y + p67.y);
    }
    if (e + 3 < deg) {
        int o0 = bkt[e], o1 = bkt[e + 1], o2 = bkt[e + 2], o3 = bkt[e + 3];
        __half2 v0 = src[o0 + lane], v1 = src[o1 + lane];
        __half2 v2 = src[o2 + lane], v3 = src[o3 + lane];
        float2 p01 = __half22float2(__hadd2(v0, v1));
        float2 p23 = __half22float2(__hadd2(v2, v3));
        acc.x += p01.x + p23.x;
        acc.y += p01.y + p23.y;
        e += 4;
    }
    for (; e < deg; e++) {
        float2 v0 = __half22float2(src[bkt[e] + lane]);
        acc.x += v0.x; acc.y += v0.y;
    }
    return acc;
}

// layer-1 aggregation -> g_acth (half2)
__global__ void k_agg1h(const float* __restrict__ b1) {
    int gw = (blockIdx.x * blockDim.x + threadIdx.x) >> 5;
    int lane = threadIdx.x & 31;
    if (gw >= TT * NN) return;
    int deg = g_deg[gw];
    const int* bkt = g_bkt + (size_t)gw * CAP;
    float2 acc = gather16(reinterpret_cast<const __half2*>(g_hsh), bkt, deg, gw, lane);
    float dv = g_dinv[gw];
    float2 bb = reinterpret_cast<const float2*>(b1)[lane];
    float ax = fmaxf(fmaf(acc.x, dv, bb.x), 0.f);
    float ay = fmaxf(fmaf(acc.y, dv, bb.y), 0.f);
    g_acth[(size_t)gw * 32 + lane] = packh(ax, ay);
}

// layer-2 GEMM: A = g_acth (exact fp16) @ W2 (fp16 hi/lo) * dinv -> g_hs2h
#define G2_A   0
#define G2_BHI 4608
#define G2_BLO 6912
#define G2_TOT 9216

__global__ __launch_bounds__(512) void k_gemm64h(const float* __restrict__ W2) {
    extern __shared__ uint32_t sg[];
    int tid = threadIdx.x, lane = tid & 31, w = tid >> 5;
    int grp = lane >> 2, tig = lane & 3;
    int wm = w >> 3, wn = w & 7;
    int row0 = blockIdx.x * 128;

    for (int i = tid; i < 64 * 32; i += 512) {
        int j = i >> 5, kp = i & 31;
        float e0 = W2[(2 * kp) * 64 + j];
        float e1 = W2[(2 * kp + 1) * 64 + j];
        uint32_t hi, lo; splith(e0, e1, hi, lo);
        sg[G2_BHI + j * 36 + kp] = hi;
        sg[G2_BLO + j * 36 + kp] = lo;
    }
#pragma unroll
    for (int i = 0; i < 8; i++) {
        int idx = tid + i * 512;
        int r = idx >> 5, kp = idx & 31;
        sg[G2_A + r * 36 + kp] = g_acth[(size_t)(row0 + r) * 32 + kp];
    }
    __syncthreads();

    float acc4[4][4] = {};
#pragma unroll
    for (int cs = 0; cs < 4; cs++) {
        int kb = cs * 8;
        int pb = (wn * 8 + grp) * 36 + kb;
        uint32_t b0h = sg[G2_BHI + pb + tig], b1h = sg[G2_BHI + pb + tig + 4];
        uint32_t b0l = sg[G2_BLO + pb + tig], b1l = sg[G2_BLO + pb + tig + 4];
#pragma unroll
        for (int mi = 0; mi < 4; mi++) {
            int rb = wm * 64 + mi * 16;
            uint32_t Ah[4];
            Ah[0] = sg[G2_A + (rb + grp) * 36 + kb + tig];
            Ah[1] = sg[G2_A + (rb + grp + 8) * 36 + kb + tig];
            Ah[2] = sg[G2_A + (rb + grp) * 36 + kb + tig + 4];
            Ah[3] = sg[G2_A + (rb + grp + 8) * 36 + kb + tig + 4];
            mma_f16(acc4[mi], Ah, b0h, b1h);
            mma_f16(acc4[mi], Ah, b0l, b1l);
        }
    }
#pragma unroll
    for (int mi = 0; mi < 4; mi++) {
#pragma unroll
        for (int rh = 0; rh < 2; rh++) {
            int row = row0 + wm * 64 + mi * 16 + grp + rh * 8;
            float dv = g_dinv[row];
            g_hs2h[(size_t)row * 32 + wn * 4 + tig] =
                packh(acc4[mi][rh * 2] * dv, acc4[mi][rh * 2 + 1] * dv);
        }
    }
}

// layer-2 aggregation -> single f16 seq plane
__global__ void k_agg2h(const float* __restrict__ b) {
    int gw = (blockIdx.x * blockDim.x + threadIdx.x) >> 5;
    int lane = threadIdx.x & 31;
    if (gw >= TT * NN) return;
    int deg = g_deg[gw];
    const int* bkt = g_bkt + (size_t)gw * CAP;
    float2 acc = gather16(reinterpret_cast<const __half2*>(g_hs2h), bkt, deg, gw, lane);
    float dv = g_dinv[gw];
    float2 bb = reinterpret_cast<const float2*>(b)[lane];
    float ox = fmaxf(fmaf(acc.x, dv, bb.x), 0.f);
    float oy = fmaxf(fmaf(acc.y, dv, bb.y), 0.f);
    g_seqh[(size_t)gw * 32 + lane] = packh(ox, oy);
}

// ====== fused LSTM over all T + head: A single-f16, B f16 hi/lo, 2 mma =====
#define L_X    0          // 128 x 36 (f16 pairs)
#define L_H    4608       // 128 x 36
#define L_BHI  9216       // 256 x 68
#define L_BLO  26624
#define L_BIAS 44032      // 256 floats
#define L_LOG  44288      // 128 floats
#define L_TOT  44416      // u32 -> 177664 bytes

__global__ __launch_bounds__(512, 1) void k_lstm_f16(
    const float* __restrict__ w_ih, const float* __restrict__ w_hh,
    const float* __restrict__ b_ih, const float* __restrict__ b_hh,
    const float* __restrict__ head_w, const float* __restrict__ head_b,
    float* __restrict__ out)
{
    extern __shared__ uint32_t sm_u[];
    float* sBias = reinterpret_cast<float*>(sm_u + L_BIAS);
    float* sLog  = reinterpret_cast<float*>(sm_u + L_LOG);

    int tid = threadIdx.x, lane = tid & 31, w = tid >> 5;
    int grp = lane >> 2, tig = lane & 3;
    int wm = w >> 3, wn = w & 7;
    int row0 = blockIdx.x * TILE_M;
    int j0 = (wn << 3) + tig, j1 = j0 + 4;

    // B: permuted gate columns, f16 hi/lo split
    for (int i = tid; i < 256 * 64; i += 512) {
        int p = i >> 6, kp = i & 63;
        int wnp = p >> 5, rem = p & 31, q = rem >> 3, e = rem & 7;
        int gate = ((q & 1) << 1) | (e & 1);
        int L = (gate << 6) + (wnp << 3) + ((q >> 1) << 2) + (e >> 1);
        int k = kp * 2;
        float2 v = (k < 64)
            ? *reinterpret_cast<const float2*>(w_ih + (size_t)L * 64 + k)
            : *reinterpret_cast<const float2*>(w_hh + (size_t)L * 64 + (k - 64));
        uint32_t hi, lo; splith(v.x, v.y, hi, lo);
        sm_u[L_BHI + p * 68 + kp] = hi;
        sm_u[L_BLO + p * 68 + kp] = lo;
    }
    for (int i = tid; i < 4608; i += 512) sm_u[L_H + i] = 0u;
    if (tid < 256) sBias[tid] = b_ih[tid] + b_hh[tid];
    if (tid < 128) sLog[tid] = 0.f;
    // x(0)
#pragma unroll
    for (int i = 0; i < 8; i++) {
        int idx = tid + i * 512;
        int r = idx >> 5, c = idx & 31;
        int row = row0 + r;
        sm_u[L_X + r * 36 + c] = (row < NN) ? g_seqh[(size_t)row * 32 + c] : 0u;
    }
    float hw0 = head_w[j0], hw1 = head_w[j1];
    float creg[4][2][2];
#pragma unroll
    for (int a = 0; a < 4; a++)
#pragma unroll
        for (int b = 0; b < 2; b++) { creg[a][b][0] = 0.f; creg[a][b][1] = 0.f; }
    __syncthreads();

    for (int t = 0; t < TT; t++) {
        float acc[4][4][4] = {};
#pragma unroll 1
        for (int cs = 0; cs < 8; cs++) {
            const uint32_t* Ap = sm_u + ((cs < 4) ? L_X : L_H);
            int kb = (cs & 3) * 8;
            int kb2 = cs * 8;
            uint32_t Bh[4][2], Bl[4][2];
#pragma unroll
            for (int q = 0; q < 4; q++) {
                int pb = ((wn << 5) + (q << 3) + grp) * 68 + kb2;
                Bh[q][0] = sm_u[L_BHI + pb + tig];
                Bh[q][1] = sm_u[L_BHI + pb + tig + 4];
                Bl[q][0] = sm_u[L_BLO + pb + tig];
                Bl[q][1] = sm_u[L_BLO + pb + tig + 4];
            }
#pragma unroll
            for (int mi = 0; mi < 4; mi++) {
                int rb = wm * 64 + mi * 16;
                uint32_t Ah[4];
                Ah[0] = Ap[(rb + grp) * 36 + kb + tig];
                Ah[1] = Ap[(rb + grp + 8) * 36 + kb + tig];
                Ah[2] = Ap[(rb + grp) * 36 + kb + tig + 4];
                Ah[3] = Ap[(rb + grp + 8) * 36 + kb + tig + 4];
#pragma unroll
                for (int q = 0; q < 4; q++) {
                    mma_f16(acc[mi][q], Ah, Bh[q][0], Bh[q][1]);
                    mma_f16(acc[mi][q], Ah, Bl[q][0], Bl[q][1]);
                }
            }
        }
        __syncthreads();

        uint32_t rx[8];
        if (t < TT - 1) {
            const uint32_t* ps = g_seqh + (size_t)(t + 1) * NN * 32;
#pragma unroll
            for (int i = 0; i < 8; i++) {
                int idx = tid + i * 512;
                int r = idx >> 5, c = idx & 31;
                int row = row0 + r;
                rx[i] = (row < NN) ? ps[(size_t)row * 32 + c] : 0u;
            }
        }

        float bi0 = sBias[j0], bf0_ = sBias[64 + j0], bg0 = sBias[128 + j0], bo0 = sBias[192 + j0];
        float bi1 = sBias[j1], bf1_ = sBias[64 + j1], bg1 = sBias[128 + j1], bo1 = sBias[192 + j1];
#pragma unroll
        for (int mi = 0; mi < 4; mi++) {
#pragma unroll
            for (int rh = 0; rh < 2; rh++) {
                int r = wm * 64 + mi * 16 + grp + rh * 8;
                int ci = rh * 2;
                float gi0 = acc[mi][0][ci] + bi0, gf0 = acc[mi][0][ci + 1] + bf0_;
                float gg0 = acc[mi][1][ci] + bg0, go0 = acc[mi][1][ci + 1] + bo0;
                float gi1 = acc[mi][2][ci] + bi1, gf1 = acc[mi][2][ci + 1] + bf1_;
                float gg1 = acc[mi][3][ci] + bg1, go1 = acc[mi][3][ci + 1] + bo1;
                float c0 = creg[mi][rh][0], c1 = creg[mi][rh][1];
                c0 = sig_mufu(gf0) * c0 + sig_mufu(gi0) * tanh_mufu(gg0);
                c1 = sig_mufu(gf1) * c1 + sig_mufu(gi1) * tanh_mufu(gg1);
                creg[mi][rh][0] = c0; creg[mi][rh][1] = c1;
                float h0 = sig_mufu(go0) * tanh_mufu(c0);
                float h1 = sig_mufu(go1) * tanh_mufu(c1);
                if (t < TT - 1) {
                    int base0 = L_H + r * 36 + (j0 >> 1);
                    int sl = j0 & 1;
                    reinterpret_cast<__half*>(&sm_u[base0])[sl] = __float2half(h0);
                    reinterpret_cast<__half*>(&sm_u[base0 + 2])[sl] = __float2half(h1);
                } else {
                    float v = h0 * hw0 + h1 * hw1;
                    v += __shfl_xor_sync(0xffffffffu, v, 1);
                    v += __shfl_xor_sync(0xffffffffu, v, 2);
                    if (tig == 0) atomicAdd(&sLog[r], v);
                }
            }
        }

        if (t < TT - 1) {
#pragma unroll
            for (int i = 0; i < 8; i++) {
                int idx = tid + i * 512;
                int r = idx >> 5, c = idx & 31;
                sm_u[L_X + r * 36 + c] = rx[i];
            }
        }
        __syncthreads();
    }

    if (tid < 128) {
        int row = row0 + tid;
        if (row < NN) out[row] = sLog[tid] + head_b[0];
    }
}

extern "C" void kernel_launch(void* const* d_in, const int* in_sizes, int n_in,
                              void* d_out, int out_size) {
    const float* xs  = (const float*)d_in[0];
    const int*   ei  = (const int*)  d_in[1];
    const float* W1  = (const float*)d_in[2];
    const float* b1  = (const float*)d_in[3];
    const float* W2  = (const float*)d_in[4];
    const float* b2  = (const float*)d_in[5];
    const float* wih = (const float*)d_in[6];
    const float* whh = (const float*)d_in[7];
    const float* bih = (const float*)d_in[8];
    const float* bhh = (const float*)d_in[9];
    const float* hw  = (const float*)d_in[10];
    const float* hb  = (const float*)d_in[11];
    float* out = (float*)d_out;

    cudaFuncSetAttribute(k_lstm_f16,
                         cudaFuncAttributeMaxDynamicSharedMemorySize, L_TOT * 4);
    cudaFuncSetAttribute(k_gemm64h,
                         cudaFuncAttributeMaxDynamicSharedMemorySize, G2_TOT * 4);

    k_init<<<(TT * NN + 255) / 256, 256>>>();
    k_fill_bucket<<<(TT * EE + 255) / 256, 256>>>(ei);

    k_gemm1h<<<(TT * NN + 127) / 128, 128>>>(xs, W1);
    k_agg1h<<<((size_t)TT * NN * 32 + 511) / 512, 512>>>(b1);
    k_gemm64h<<<(TT * NN) / 128, 512, G2_TOT * 4>>>(W2);
    k_agg2h<<<((size_t)TT * NN * 32 + 511) / 512, 512>>>(b2);

    k_lstm_f16<<<NBLK, 512, L_TOT * 4>>>(wih, whh, bih, bhh, hw, hb, out);
}

// round 13
// speedup vs baseline: 1.6964x; 1.1051x over previous
#include <cuda_runtime.h>
#include <cuda_fp16.h>
#include <cuda_bf16.h>
#include <math.h>
#include <stdint.h>

#define NN  50000
#define TT  8
#define EE  800000
#define FIN 9
#define HH  64
#define CAP 96
#define TILE_M 128
#define NBLK ((NN + TILE_M - 1) / TILE_M)

__device__ int      g_deg [TT * NN];
__device__ int      g_bkt [(size_t)TT * NN * CAP];  // pre-scaled word offsets
__device__ float    g_dinv[TT * NN];
__device__ uint32_t g_hsh [TT * NN * 32];   // layer-1 hs (dinv-scaled), half2
__device__ uint32_t g_acth[TT * NN * 32];   // layer-1 activation, half2
__device__ uint32_t g_hs2h[TT * NN * 32];   // layer-2 hs, half2
__device__ uint32_t g_seqh[TT * NN * 32];   // seq, half2 (single plane)

// ---------------- MUFU-based nonlinearities --------------------------------
__device__ __forceinline__ float tanh_mufu(float x) {
    float y;
    asm("tanh.approx.f32 %0, %1;" : "=f"(y) : "f"(x));
    return y;
}
__device__ __forceinline__ float sig_mufu(float x) {
    return fmaf(tanh_mufu(x * 0.5f), 0.5f, 0.5f);
}

__device__ __forceinline__ uint32_t packh(float e0, float e1) {
    __half2 p = __floats2half2_rn(e0, e1);
    return *reinterpret_cast<uint32_t*>(&p);
}
__device__ __forceinline__ void splith(float e0, float e1, uint32_t& hi, uint32_t& lo) {
    __half2 p = __floats2half2_rn(e0, e1);
    float2 hf = __half22float2(p);
    hi = *reinterpret_cast<uint32_t*>(&p);
    lo = packh(e0 - hf.x, e1 - hf.y);
}
__device__ __forceinline__ void mma_f16(float* d, const uint32_t* a,
                                        uint32_t b0, uint32_t b1) {
    asm volatile(
        "mma.sync.aligned.m16n8k16.row.col.f32.f16.f16.f32 "
        "{%0,%1,%2,%3}, {%4,%5,%6,%7}, {%8,%9}, {%0,%1,%2,%3};"
        : "+f"(d[0]), "+f"(d[1]), "+f"(d[2]), "+f"(d[3])
        : "r"(a[0]), "r"(a[1]), "r"(a[2]), "r"(a[3]), "r"(b0), "r"(b1));
}

__global__ void k_init() {
    int i0 = blockIdx.x * blockDim.x + threadIdx.x;
    for (int i = i0; i < TT * NN; i += gridDim.x * blockDim.x) g_deg[i] = 0;
}

__global__ void k_fill_bucket(const int* __restrict__ ei) {
    int idx = blockIdx.x * blockDim.x + threadIdx.x;
    if (idx >= TT * EE) return;
    int t = idx / EE, e = idx - t * EE;
    int s = ei[(size_t)t * 2 * EE + e];
    int d = ei[(size_t)t * 2 * EE + EE + e];
    int td = t * NN + d;
    int pos = atomicAdd(&g_deg[td], 1);
    g_bkt[(size_t)td * CAP + pos] = (t * NN + s) * 32;
}

// layer-1 GEMM (K=9): coalesced x staging; dinv; -> half2 g_hsh
__global__ __launch_bounds__(128) void k_gemm1h(
    const float* __restrict__ x, const float* __restrict__ W1)
{
    __shared__ float sW[FIN * HH];
    __shared__ float sX[128 * FIN];
    int tid = threadIdx.x;
    for (int i = tid; i < FIN * HH; i += 128) sW[i] = W1[i];
    int base = blockIdx.x * 128;
#pragma unroll
    for (int i = 0; i < FIN; i++) {
        int idx = tid + i * 128;
        sX[idx] = x[(size_t)base * FIN + idx];
    }
    __syncthreads();
    int n = base + tid;
    if (n >= TT * NN) return;
    float dv = rsqrtf((float)(g_deg[n] + 1));
    g_dinv[n] = dv;
    float xv[FIN];
#pragma unroll
    for (int k = 0; k < FIN; k++) xv[k] = sX[tid * FIN + k];
#pragma unroll
    for (int c = 0; c < HH; c += 4) {
        float4 o = make_float4(0.f, 0.f, 0.f, 0.f);
#pragma unroll
        for (int k = 0; k < FIN; k++) {
            float xk = xv[k];
            o.x = fmaf(xk, sW[k * HH + c + 0], o.x);
            o.y = fmaf(xk, sW[k * HH + c + 1], o.y);
            o.z = fmaf(xk, sW[k * HH + c + 2], o.z);
            o.w = fmaf(xk, sW[k * HH + c + 3], o.w);
        }
        uint2 u;
        u.x = packh(o.x * dv, o.y * dv);
        u.y = packh(o.z * dv, o.w * dv);
        *reinterpret_cast<uint2*>(g_hsh + (size_t)n * 32 + c / 2) = u;
    }
}

// ---------- fp16 gather body, full-degree MLP=16 ---------------------------
__device__ __forceinline__ float2 gather16(const __half2* __restrict__ src,
                                           const int* __restrict__ bkt,
                                           int deg, int gw, int lane) {
    float2 acc = __half22float2(src[(size_t)gw * 32 + lane]);
    int e = 0;
    for (; e + 15 < deg; e += 16) {
        int4 oa = *reinterpret_cast<const int4*>(bkt + e);
        int4 ob = *reinterpret_cast<const int4*>(bkt + e + 4);
        int4 oc = *reinterpret_cast<const int4*>(bkt + e + 8);
        int4 od = *reinterpret_cast<const int4*>(bkt + e + 12);
        __half2 v0 = src[oa.x + lane], v1 = src[oa.y + lane];
        __half2 v2 = src[oa.z + lane], v3 = src[oa.w + lane];
        __half2 v4 = src[ob.x + lane], v5 = src[ob.y + lane];
        __half2 v6 = src[ob.z + lane], v7 = src[ob.w + lane];
        __half2 v8 = src[oc.x + lane], v9 = src[oc.y + lane];
        __half2 va = src[oc.z + lane], vb = src[oc.w + lane];
        __half2 vc = src[od.x + lane], vd = src[od.y + lane];
        __half2 ve = src[od.z + lane], vf = src[od.w + lane];
        float2 p0 = __half22float2(__hadd2(v0, v1));
        float2 p1 = __half22float2(__hadd2(v2, v3));
        float2 p2 = __half22float2(__hadd2(v4, v5));
        float2 p3 = __half22float2(__hadd2(v6, v7));
        float2 p4 = __half22float2(__hadd2(v8, v9));
        float2 p5 = __half22float2(__hadd2(va, vb));
        float2 p6 = __half22float2(__hadd2(vc, vd));
        float2 p7 = __half22float2(__hadd2(ve, vf));
        acc.x += ((p0.x + p1.x) + (p2.x + p3.x)) + ((p4.x + p5.x) + (p6.x + p7.x));
        acc.y += ((p0.y + p1.y) + (p2.y + p3.y)) + ((p4.y + p5.y) + (p6.y + p7.y));
    }
    if (e + 7 < deg) {
        int4 oa = *reinterpret_cast<const int4*>(bkt + e);
        int4 ob = *reinterpret_cast<const int4*>(bkt + e + 4);
        __half2 v0 = src[oa.x + lane], v1 = src[oa.y + lane];
        __half2 v2 = src[oa.z + lane], v3 = src[oa.w + lane];
        __half2 v4 = src[ob.x + lane], v5 = src[ob.y + lane];
        __half2 v6 = src[ob.z + lane], v7 = src[ob.w + lane];
        float2 p0 = __half22float2(__hadd2(v0, v1));
        float2 p1 = __half22float2(__hadd2(v2, v3));
        float2 p2 = __half22float2(__hadd2(v4, v5));
        float2 p3 = __half22float2(__hadd2(v6, v7));
        acc.x += (p0.x + p1.x) + (p2.x + p3.x);
        acc.y += (p0.y + p1.y) + (p2.y + p3.y);
        e += 8;
    }
    if (e + 3 < deg) {
        int4 oa = *reinterpret_cast<const int4*>(bkt + e);
        __half2 v0 = src[oa.x + lane], v1 = src[oa.y + lane];
        __half2 v2 = src[oa.z + lane], v3 = src[oa.w + lane];
        float2 p0 = __half22float2(__hadd2(v0, v1));
        float2 p1 = __half22float2(__hadd2(v2, v3));
        acc.x += p0.x + p1.x;
        acc.y += p0.y + p1.y;
        e += 4;
    }
    for (; e < deg; e++) {
        float2 v0 = __half22float2(src[bkt[e] + lane]);
        acc.x += v0.x; acc.y += v0.y;
    }
    return acc;
}

// layer-1 aggregation -> g_acth (half2)
__global__ void k_agg1h(const float* __restrict__ b1) {
    int gw = (blockIdx.x * blockDim.x + threadIdx.x) >> 5;
    int lane = threadIdx.x & 31;
    if (gw >= TT * NN) return;
    int deg = g_deg[gw];
    const int* bkt = g_bkt + (size_t)gw * CAP;
    float2 acc = gather16(reinterpret_cast<const __half2*>(g_hsh), bkt, deg, gw, lane);
    float dv = g_dinv[gw];
    float2 bb = reinterpret_cast<const float2*>(b1)[lane];
    float ax = fmaxf(fmaf(acc.x, dv, bb.x), 0.f);
    float ay = fmaxf(fmaf(acc.y, dv, bb.y), 0.f);
    g_acth[(size_t)gw * 32 + lane] = packh(ax, ay);
}

// layer-2 GEMM: A = g_acth (exact fp16) @ W2 (fp16 hi/lo) * dinv -> g_hs2h
#define G2_A   0
#define G2_BHI 4608
#define G2_BLO 6912
#define G2_TOT 9216

__global__ __launch_bounds__(512) void k_gemm64h(const float* __restrict__ W2) {
    extern __shared__ uint32_t sg[];
    int tid = threadIdx.x, lane = tid & 31, w = tid >> 5;
    int grp = lane >> 2, tig = lane & 3;
    int wm = w >> 3, wn = w & 7;
    int row0 = blockIdx.x * 128;

    for (int i = tid; i < 64 * 32; i += 512) {
        int j = i >> 5, kp = i & 31;
        float e0 = W2[(2 * kp) * 64 + j];
        float e1 = W2[(2 * kp + 1) * 64 + j];
        uint32_t hi, lo; splith(e0, e1, hi, lo);
        sg[G2_BHI + j * 36 + kp] = hi;
        sg[G2_BLO + j * 36 + kp] = lo;
    }
#pragma unroll
    for (int i = 0; i < 8; i++) {
        int idx = tid + i * 512;
        int r = idx >> 5, kp = idx & 31;
        sg[G2_A + r * 36 + kp] = g_acth[(size_t)(row0 + r) * 32 + kp];
    }
    __syncthreads();

    float acc4[4][4] = {};
#pragma unroll
    for (int cs = 0; cs < 4; cs++) {
        int kb = cs * 8;
        int pb = (wn * 8 + grp) * 36 + kb;
        uint32_t b0h = sg[G2_BHI + pb + tig], b1h = sg[G2_BHI + pb + tig + 4];
        uint32_t b0l = sg[G2_BLO + pb + tig], b1l = sg[G2_BLO + pb + tig + 4];
#pragma unroll
        for (int mi = 0; mi < 4; mi++) {
            int rb = wm * 64 + mi * 16;
            uint32_t Ah[4];
            Ah[0] = sg[G2_A + (rb + grp) * 36 + kb + tig];
            Ah[1] = sg[G2_A + (rb + grp + 8) * 36 + kb + tig];
            Ah[2] = sg[G2_A + (rb + grp) * 36 + kb + tig + 4];
            Ah[3] = sg[G2_A + (rb + grp + 8) * 36 + kb + tig + 4];
            mma_f16(acc4[mi], Ah, b0h, b1h);
            mma_f16(acc4[mi], Ah, b0l, b1l);
        }
    }
#pragma unroll
    for (int mi = 0; mi < 4; mi++) {
#pragma unroll
        for (int rh = 0; rh < 2; rh++) {
            int row = row0 + wm * 64 + mi * 16 + grp + rh * 8;
            float dv = g_dinv[row];
            g_hs2h[(size_t)row * 32 + wn * 4 + tig] =
                packh(acc4[mi][rh * 2] * dv, acc4[mi][rh * 2 + 1] * dv);
        }
    }
}

// layer-2 aggregation -> single f16 seq plane
__global__ void k_agg2h(const float* __restrict__ b) {
    int gw = (blockIdx.x * blockDim.x + threadIdx.x) >> 5;
    int lane = threadIdx.x & 31;
    if (gw >= TT * NN) return;
    int deg = g_deg[gw];
    const int* bkt = g_bkt + (size_t)gw * CAP;
    float2 acc = gather16(reinterpret_cast<const __half2*>(g_hs2h), bkt, deg, gw, lane);
    float dv = g_dinv[gw];
    float2 bb = reinterpret_cast<const float2*>(b)[lane];
    float ox = fmaxf(fmaf(acc.x, dv, bb.x), 0.f);
    float oy = fmaxf(fmaf(acc.y, dv, bb.y), 0.f);
    g_seqh[(size_t)gw * 32 + lane] = packh(ox, oy);
}

// ====== fused LSTM over all T + head: A and B single-f16, 1 mma/tile =======
#define L_X    0          // 128 x 36 (f16 pairs)
#define L_H    4608       // 128 x 36
#define L_B    9216       // 256 x 68
#define L_BIAS 26624      // 256 floats
#define L_LOG  26880      // 128 floats
#define L_TOT  27008      // u32 -> 108032 bytes

__global__ __launch_bounds__(512, 1) void k_lstm_f16(
    const float* __restrict__ w_ih, const float* __restrict__ w_hh,
    const float* __restrict__ b_ih, const float* __restrict__ b_hh,
    const float* __restrict__ head_w, const float* __restrict__ head_b,
    float* __restrict__ out)
{
    extern __shared__ uint32_t sm_u[];
    float* sBias = reinterpret_cast<float*>(sm_u + L_BIAS);
    float* sLog  = reinterpret_cast<float*>(sm_u + L_LOG);

    int tid = threadIdx.x, lane = tid & 31, w = tid >> 5;
    int grp = lane >> 2, tig = lane & 3;
    int wm = w >> 3, wn = w & 7;
    int row0 = blockIdx.x * TILE_M;
    int j0 = (wn << 3) + tig, j1 = j0 + 4;

    // B: permuted gate columns, single f16
    for (int i = tid; i < 256 * 64; i += 512) {
        int p = i >> 6, kp = i & 63;
        int wnp = p >> 5, rem = p & 31, q = rem >> 3, e = rem & 7;
        int gate = ((q & 1) << 1) | (e & 1);
        int L = (gate << 6) + (wnp << 3) + ((q >> 1) << 2) + (e >> 1);
        int k = kp * 2;
        float2 v = (k < 64)
            ? *reinterpret_cast<const float2*>(w_ih + (size_t)L * 64 + k)
            : *reinterpret_cast<const float2*>(w_hh + (size_t)L * 64 + (k - 64));
        sm_u[L_B + p * 68 + kp] = packh(v.x, v.y);
    }
    for (int i = tid; i < 4608; i += 512) sm_u[L_H + i] = 0u;
    if (tid < 256) sBias[tid] = b_ih[tid] + b_hh[tid];
    if (tid < 128) sLog[tid] = 0.f;
    // x(0)
#pragma unroll
    for (int i = 0; i < 8; i++) {
        int idx = tid + i * 512;
        int r = idx >> 5, c = idx & 31;
        int row = row0 + r;
        sm_u[L_X + r * 36 + c] = (row < NN) ? g_seqh[(size_t)row * 32 + c] : 0u;
    }
    float hw0 = head_w[j0], hw1 = head_w[j1];
    float creg[4][2][2];
#pragma unroll
    for (int a = 0; a < 4; a++)
#pragma unroll
        for (int b = 0; b < 2; b++) { creg[a][b][0] = 0.f; creg[a][b][1] = 0.f; }
    __syncthreads();

    for (int t = 0; t < TT; t++) {
        float acc[4][4][4] = {};
#pragma unroll 1
        for (int cs = 0; cs < 8; cs++) {
            const uint32_t* Ap = sm_u + ((cs < 4) ? L_X : L_H);
            int kb = (cs & 3) * 8;
            int kb2 = cs * 8;
            uint32_t Bh[4][2];
#pragma unroll
            for (int q = 0; q < 4; q++) {
                int pb = ((wn << 5) + (q << 3) + grp) * 68 + kb2;
                Bh[q][0] = sm_u[L_B + pb + tig];
                Bh[q][1] = sm_u[L_B + pb + tig + 4];
            }
#pragma unroll
            for (int mi = 0; mi < 4; mi++) {
                int rb = wm * 64 + mi * 16;
                uint32_t Ah[4];
                Ah[0] = Ap[(rb + grp) * 36 + kb + tig];
                Ah[1] = Ap[(rb + grp + 8) * 36 + kb + tig];
                Ah[2] = Ap[(rb + grp) * 36 + kb + tig + 4];
                Ah[3] = Ap[(rb + grp + 8) * 36 + kb + tig + 4];
#pragma unroll
                for (int q = 0; q < 4; q++)
                    mma_f16(acc[mi][q], Ah, Bh[q][0], Bh[q][1]);
            }
        }
        __syncthreads();

        uint32_t rx[8];
        if (t < TT - 1) {
            const uint32_t* ps = g_seqh + (size_t)(t + 1) * NN * 32;
#pragma unroll
            for (int i = 0; i < 8; i++) {
                int idx = tid + i * 512;
                int r = idx >> 5, c = idx & 31;
                int row = row0 + r;
                rx[i] = (row < NN) ? ps[(size_t)row * 32 + c] : 0u;
            }
        }

        float bi0 = sBias[j0], bf0_ = sBias[64 + j0], bg0 = sBias[128 + j0], bo0 = sBias[192 + j0];
        float bi1 = sBias[j1], bf1_ = sBias[64 + j1], bg1 = sBias[128 + j1], bo1 = sBias[192 + j1];
#pragma unroll
        for (int mi = 0; mi < 4; mi++) {
#pragma unroll
            for (int rh = 0; rh < 2; rh++) {
                int r = wm * 64 + mi * 16 + grp + rh * 8;
                int ci = rh * 2;
                float gi0 = acc[mi][0][ci] + bi0, gf0 = acc[mi][0][ci + 1] + bf0_;
                float gg0 = acc[mi][1][ci] + bg0, go0 = acc[mi][1][ci + 1] + bo0;
                float gi1 = acc[mi][2][ci] + bi1, gf1 = acc[mi][2][ci + 1] + bf1_;
                float gg1 = acc[mi][3][ci] + bg1, go1 = acc[mi][3][ci + 1] + bo1;
                float c0 = creg[mi][rh][0], c1 = creg[mi][rh][1];
                c0 = sig_mufu(gf0) * c0 + sig_mufu(gi0) * tanh_mufu(gg0);
                c1 = sig_mufu(gf1) * c1 + sig_mufu(gi1) * tanh_mufu(gg1);
                creg[mi][rh][0] = c0; creg[mi][rh][1] = c1;
                float h0 = sig_mufu(go0) * tanh_mufu(c0);
                float h1 = sig_mufu(go1) * tanh_mufu(c1);
                if (t < TT - 1) {
                    int base0 = L_H + r * 36 + (j0 >> 1);
                    int sl = j0 & 1;
                    reinterpret_cast<__half*>(&sm_u[base0])[sl] = __float2half(h0);
                    reinterpret_cast<__half*>(&sm_u[base0 + 2])[sl] = __float2half(h1);
                } else {
                    float v = h0 * hw0 + h1 * hw1;
                    v += __shfl_xor_sync(0xffffffffu, v, 1);
                    v += __shfl_xor_sync(0xffffffffu, v, 2);
                    if (tig == 0) atomicAdd(&sLog[r], v);
                }
            }
        }

        if (t < TT - 1) {
#pragma unroll
            for (int i = 0; i < 8; i++) {
                int idx = tid + i * 512;
                int r = idx >> 5, c = idx & 31;
                sm_u[L_X + r * 36 + c] = rx[i];
            }
        }
        __syncthreads();
    }

    if (tid < 128) {
        int row = row0 + tid;
        if (row < NN) out[row] = sLog[tid] + head_b[0];
    }
}

extern "C" void kernel_launch(void* const* d_in, const int* in_sizes, int n_in,
                              void* d_out, int out_size) {
    const float* xs  = (const float*)d_in[0];
    const int*   ei  = (const int*)  d_in[1];
    const float* W1  = (const float*)d_in[2];
    const float* b1  = (const float*)d_in[3];
    const float* W2  = (const float*)d_in[4];
    const float* b2  = (const float*)d_in[5];
    const float* wih = (const float*)d_in[6];
    const float* whh = (const float*)d_in[7];
    const float* bih = (const float*)d_in[8];
    const float* bhh = (const float*)d_in[9];
    const float* hw  = (const float*)d_in[10];
    const float* hb  = (const float*)d_in[11];
    float* out = (float*)d_out;

    cudaFuncSetAttribute(k_lstm_f16,
                         cudaFuncAttributeMaxDynamicSharedMemorySize, L_TOT * 4);
    cudaFuncSetAttribute(k_gemm64h,
                         cudaFuncAttributeMaxDynamicSharedMemorySize, G2_TOT * 4);

    k_init<<<(TT * NN + 255) / 256, 256>>>();
    k_fill_bucket<<<(TT * EE + 255) / 256, 256>>>(ei);

    k_gemm1h<<<(TT * NN + 127) / 128, 128>>>(xs, W1);
    k_agg1h<<<((size_t)TT * NN * 32 + 511) / 512, 512>>>(b1);
    k_gemm64h<<<(TT * NN) / 128, 512, G2_TOT * 4>>>(W2);
    k_agg2h<<<((size_t)TT * NN * 32 + 511) / 512, 512>>>(b2);

    k_lstm_f16<<<NBLK, 512, L_TOT * 4>>>(wih, whh, bih, bhh, hw, hb, out);
}

// round 14
// speedup vs baseline: 1.8473x; 1.0890x over previous
#include <cuda_runtime.h>
#include <cuda_fp16.h>
#include <cuda_bf16.h>
#include <math.h>
#include <stdint.h>

#define NN  50000
#define TT  8
#define EE  800000
#define FIN 9
#define HH  64
#define CAP 96
#define TILE_M 128
#define NBLK ((NN + TILE_M - 1) / TILE_M)

__device__ int   g_deg [TT * NN];                 // zeroed by LSTM tail each launch
__device__ int   g_bkt [(size_t)TT * NN * CAP];   // uint2-unit offsets: (t*NN+s)*16
__device__ float g_dinv[TT * NN];
__device__ uint2 g_hsh [TT * NN * 16];   // layer-1 hs (dinv-scaled), 4 halves/entry
__device__ uint2 g_acth[TT * NN * 16];   // layer-1 activation
__device__ uint2 g_hs2h[TT * NN * 16];   // layer-2 hs
__device__ uint2 g_seqh[TT * NN * 16];   // seq (f16)

// ---------------- MUFU-based nonlinearities --------------------------------
__device__ __forceinline__ float tanh_mufu(float x) {
    float y;
    asm("tanh.approx.f32 %0, %1;" : "=f"(y) : "f"(x));
    return y;
}
__device__ __forceinline__ float sig_mufu(float x) {
    return fmaf(tanh_mufu(x * 0.5f), 0.5f, 0.5f);
}

__device__ __forceinline__ uint32_t packh(float e0, float e1) {
    __half2 p = __floats2half2_rn(e0, e1);
    return *reinterpret_cast<uint32_t*>(&p);
}
__device__ __forceinline__ float2 h2f(uint32_t u) {
    return __half22float2(*reinterpret_cast<__half2*>(&u));
}
__device__ __forceinline__ uint32_t hadd2u(uint32_t a, uint32_t b) {
    __half2 r = __hadd2(*reinterpret_cast<__half2*>(&a), *reinterpret_cast<__half2*>(&b));
    return *reinterpret_cast<uint32_t*>(&r);
}
__device__ __forceinline__ void mma_f16(float* d, const uint32_t* a,
                                        uint32_t b0, uint32_t b1) {
    asm volatile(
        "mma.sync.aligned.m16n8k16.row.col.f32.f16.f16.f32 "
        "{%0,%1,%2,%3}, {%4,%5,%6,%7}, {%8,%9}, {%0,%1,%2,%3};"
        : "+f"(d[0]), "+f"(d[1]), "+f"(d[2]), "+f"(d[3])
        : "r"(a[0]), "r"(a[1]), "r"(a[2]), "r"(a[3]), "r"(b0), "r"(b1));
}

__global__ void k_fill_bucket(const int* __restrict__ ei) {
    int idx = blockIdx.x * blockDim.x + threadIdx.x;
    if (idx >= TT * EE) return;
    int t = idx / EE, e = idx - t * EE;
    int s = ei[(size_t)t * 2 * EE + e];
    int d = ei[(size_t)t * 2 * EE + EE + e];
    int td = t * NN + d;
    int pos = atomicAdd(&g_deg[td], 1);
    g_bkt[(size_t)td * CAP + pos] = (t * NN + s) * 16;   // uint2 units
}

// layer-1 GEMM (K=9): coalesced x staging; dinv; -> g_hsh
__global__ __launch_bounds__(128) void k_gemm1h(
    const float* __restrict__ x, const float* __restrict__ W1)
{
    __shared__ float sW[FIN * HH];
    __shared__ float sX[128 * FIN];
    int tid = threadIdx.x;
    for (int i = tid; i < FIN * HH; i += 128) sW[i] = W1[i];
    int base = blockIdx.x * 128;
#pragma unroll
    for (int i = 0; i < FIN; i++) {
        int idx = tid + i * 128;
        sX[idx] = x[(size_t)base * FIN + idx];
    }
    __syncthreads();
    int n = base + tid;
    if (n >= TT * NN) return;
    float dv = rsqrtf((float)(g_deg[n] + 1));
    g_dinv[n] = dv;
    float xv[FIN];
#pragma unroll
    for (int k = 0; k < FIN; k++) xv[k] = sX[tid * FIN + k];
#pragma unroll
    for (int c = 0; c < HH; c += 4) {
        float4 o = make_float4(0.f, 0.f, 0.f, 0.f);
#pragma unroll
        for (int k = 0; k < FIN; k++) {
            float xk = xv[k];
            o.x = fmaf(xk, sW[k * HH + c + 0], o.x);
            o.y = fmaf(xk, sW[k * HH + c + 1], o.y);
            o.z = fmaf(xk, sW[k * HH + c + 2], o.z);
            o.w = fmaf(xk, sW[k * HH + c + 3], o.w);
        }
        uint2 u;
        u.x = packh(o.x * dv, o.y * dv);
        u.y = packh(o.z * dv, o.w * dv);
        g_hsh[(size_t)n * 16 + c / 4] = u;
    }
}

// ---------- gather: TWO nodes per warp (16 lanes each, uint2/lane) ---------
// returns 4 floats (halves 4*l16 .. 4*l16+3 of the node's row)
__device__ __forceinline__ void gather2n(const uint2* __restrict__ src,
                                         const int* __restrict__ bkt,
                                         int deg, int gw, int l16, float* f) {
    uint2 s = src[(size_t)gw * 16 + l16];
    float2 a0 = h2f(s.x), a1 = h2f(s.y);
    f[0] = a0.x; f[1] = a0.y; f[2] = a1.x; f[3] = a1.y;
    int e = 0;
    for (; e + 7 < deg; e += 8) {
        int4 oa = *reinterpret_cast<const int4*>(bkt + e);
        int4 ob = *reinterpret_cast<const int4*>(bkt + e + 4);
        uint2 v0 = src[oa.x + l16], v1 = src[oa.y + l16];
        uint2 v2 = src[oa.z + l16], v3 = src[oa.w + l16];
        uint2 v4 = src[ob.x + l16], v5 = src[ob.y + l16];
        uint2 v6 = src[ob.z + l16], v7 = src[ob.w + l16];
        uint32_t p0x = hadd2u(v0.x, v1.x), p0y = hadd2u(v0.y, v1.y);
        uint32_t p1x = hadd2u(v2.x, v3.x), p1y = hadd2u(v2.y, v3.y);
        uint32_t p2x = hadd2u(v4.x, v5.x), p2y = hadd2u(v4.y, v5.y);
        uint32_t p3x = hadd2u(v6.x, v7.x), p3y = hadd2u(v6.y, v7.y);
        float2 q0 = h2f(p0x), q1 = h2f(p1x), q2 = h2f(p2x), q3 = h2f(p3x);
        f[0] += (q0.x + q1.x) + (q2.x + q3.x);
        f[1] += (q0.y + q1.y) + (q2.y + q3.y);
        float2 r0 = h2f(p0y), r1 = h2f(p1y), r2 = h2f(p2y), r3 = h2f(p3y);
        f[2] += (r0.x + r1.x) + (r2.x + r3.x);
        f[3] += (r0.y + r1.y) + (r2.y + r3.y);
    }
    if (e + 3 < deg) {
        int4 oa = *reinterpret_cast<const int4*>(bkt + e);
        uint2 v0 = src[oa.x + l16], v1 = src[oa.y + l16];
        uint2 v2 = src[oa.z + l16], v3 = src[oa.w + l16];
        uint32_t p0x = hadd2u(v0.x, v1.x), p0y = hadd2u(v0.y, v1.y);
        uint32_t p1x = hadd2u(v2.x, v3.x), p1y = hadd2u(v2.y, v3.y);
        float2 q0 = h2f(p0x), q1 = h2f(p1x);
        f[0] += q0.x + q1.x;
        f[1] += q0.y + q1.y;
        float2 r0 = h2f(p0y), r1 = h2f(p1y);
        f[2] += r0.x + r1.x;
        f[3] += r0.y + r1.y;
        e += 4;
    }
    for (; e < deg; e++) {
        uint2 v = src[bkt[e] + l16];
        float2 q = h2f(v.x), r = h2f(v.y);
        f[0] += q.x; f[1] += q.y; f[2] += r.x; f[3] += r.y;
    }
}

// layer-1 aggregation -> g_acth
__global__ void k_agg1h(const float* __restrict__ b1) {
    int gw = ((blockIdx.x * blockDim.x + threadIdx.x) >> 4);  // half-warp id
    int l16 = threadIdx.x & 15;
    if (gw >= TT * NN) return;
    int deg = g_deg[gw];
    const int* bkt = g_bkt + (size_t)gw * CAP;
    float f[4];
    gather2n(g_hsh, bkt, deg, gw, l16, f);
    float dv = g_dinv[gw];
    float4 bb = *reinterpret_cast<const float4*>(b1 + l16 * 4);
    float a0 = fmaxf(fmaf(f[0], dv, bb.x), 0.f);
    float a1 = fmaxf(fmaf(f[1], dv, bb.y), 0.f);
    float a2 = fmaxf(fmaf(f[2], dv, bb.z), 0.f);
    float a3 = fmaxf(fmaf(f[3], dv, bb.w), 0.f);
    uint2 u; u.x = packh(a0, a1); u.y = packh(a2, a3);
    g_acth[(size_t)gw * 16 + l16] = u;
}

// layer-2 GEMM: A = g_acth (exact fp16) @ W2 (single f16) * dinv -> g_hs2h
#define G2_A   0          // 128 x 36 u32
#define G2_B   4608       // 64 x 36 u32
#define G2_TOT 6912

__global__ __launch_bounds__(512) void k_gemm64h(const float* __restrict__ W2) {
    extern __shared__ uint32_t sg[];
    int tid = threadIdx.x, lane = tid & 31, w = tid >> 5;
    int grp = lane >> 2, tig = lane & 3;
    int wm = w >> 3, wn = w & 7;
    int row0 = blockIdx.x * 128;

    for (int i = tid; i < 64 * 32; i += 512) {
        int j = i >> 5, kp = i & 31;
        float e0 = W2[(2 * kp) * 64 + j];
        float e1 = W2[(2 * kp + 1) * 64 + j];
        sg[G2_B + j * 36 + kp] = packh(e0, e1);
    }
#pragma unroll
    for (int i = 0; i < 4; i++) {
        int idx = tid + i * 512;              // 2048 uint2
        int r = idx >> 4, k2 = idx & 15;
        uint2 v = g_acth[(size_t)(row0 + r) * 16 + k2];
        sg[G2_A + r * 36 + 2 * k2] = v.x;
        sg[G2_A + r * 36 + 2 * k2 + 1] = v.y;
    }
    __syncthreads();

    float acc4[4][4] = {};
#pragma unroll
    for (int cs = 0; cs < 4; cs++) {
        int kb = cs * 8;
        int pb = (wn * 8 + grp) * 36 + kb;
        uint32_t b0 = sg[G2_B + pb + tig], b1 = sg[G2_B + pb + tig + 4];
#pragma unroll
        for (int mi = 0; mi < 4; mi++) {
            int rb = wm * 64 + mi * 16;
            uint32_t Ah[4];
            Ah[0] = sg[G2_A + (rb + grp) * 36 + kb + tig];
            Ah[1] = sg[G2_A + (rb + grp + 8) * 36 + kb + tig];
            Ah[2] = sg[G2_A + (rb + grp) * 36 + kb + tig + 4];
            Ah[3] = sg[G2_A + (rb + grp + 8) * 36 + kb + tig + 4];
            mma_f16(acc4[mi], Ah, b0, b1);
        }
    }
#pragma unroll
    for (int mi = 0; mi < 4; mi++) {
#pragma unroll
        for (int rh = 0; rh < 2; rh++) {
            int row = row0 + wm * 64 + mi * 16 + grp + rh * 8;
            float dv = g_dinv[row];
            reinterpret_cast<uint32_t*>(g_hs2h)[(size_t)row * 32 + wn * 4 + tig] =
                packh(acc4[mi][rh * 2] * dv, acc4[mi][rh * 2 + 1] * dv);
        }
    }
}

// layer-2 aggregation -> g_seqh
__global__ void k_agg2h(const float* __restrict__ b) {
    int gw = ((blockIdx.x * blockDim.x + threadIdx.x) >> 4);
    int l16 = threadIdx.x & 15;
    if (gw >= TT * NN) return;
    int deg = g_deg[gw];
    const int* bkt = g_bkt + (size_t)gw * CAP;
    float f[4];
    gather2n(g_hs2h, bkt, deg, gw, l16, f);
    float dv = g_dinv[gw];
    float4 bb = *reinterpret_cast<const float4*>(b + l16 * 4);
    float a0 = fmaxf(fmaf(f[0], dv, bb.x), 0.f);
    float a1 = fmaxf(fmaf(f[1], dv, bb.y), 0.f);
    float a2 = fmaxf(fmaf(f[2], dv, bb.z), 0.f);
    float a3 = fmaxf(fmaf(f[3], dv, bb.w), 0.f);
    uint2 u; u.x = packh(a0, a1); u.y = packh(a2, a3);
    g_seqh[(size_t)gw * 16 + l16] = u;
}

// ====== fused LSTM over all T + head; zeros g_deg at tail ==================
#define L_X    0          // 128 x 36 (f16 pairs)
#define L_H    4608       // 128 x 36
#define L_B    9216       // 256 x 68
#define L_BIAS 26624      // 256 floats
#define L_LOG  26880      // 128 floats
#define L_TOT  27008      // u32 -> 108032 bytes

__global__ __launch_bounds__(512, 1) void k_lstm_f16(
    const float* __restrict__ w_ih, const float* __restrict__ w_hh,
    const float* __restrict__ b_ih, const float* __restrict__ b_hh,
    const float* __restrict__ head_w, const float* __restrict__ head_b,
    float* __restrict__ out)
{
    extern __shared__ uint32_t sm_u[];
    float* sBias = reinterpret_cast<float*>(sm_u + L_BIAS);
    float* sLog  = reinterpret_cast<float*>(sm_u + L_LOG);

    int tid = threadIdx.x, lane = tid & 31, w = tid >> 5;
    int grp = lane >> 2, tig = lane & 3;
    int wm = w >> 3, wn = w & 7;
    int row0 = blockIdx.x * TILE_M;
    int j0 = (wn << 3) + tig, j1 = j0 + 4;

    for (int i = tid; i < 256 * 64; i += 512) {
        int p = i >> 6, kp = i & 63;
        int wnp = p >> 5, rem = p & 31, q = rem >> 3, e = rem & 7;
        int gate = ((q & 1) << 1) | (e & 1);
        int L = (gate << 6) + (wnp << 3) + ((q >> 1) << 2) + (e >> 1);
        int k = kp * 2;
        float2 v = (k < 64)
            ? *reinterpret_cast<const float2*>(w_ih + (size_t)L * 64 + k)
            : *reinterpret_cast<const float2*>(w_hh + (size_t)L * 64 + (k - 64));
        sm_u[L_B + p * 68 + kp] = packh(v.x, v.y);
    }
    for (int i = tid; i < 4608; i += 512) sm_u[L_H + i] = 0u;
    if (tid < 256) sBias[tid] = b_ih[tid] + b_hh[tid];
    if (tid < 128) sLog[tid] = 0.f;
    // x(0)
#pragma unroll
    for (int i = 0; i < 4; i++) {
        int idx = tid + i * 512;              // 2048 uint2
        int r = idx >> 4, c2 = idx & 15;
        int row = row0 + r;
        uint2 v = make_uint2(0u, 0u);
        if (row < NN) v = g_seqh[(size_t)row * 16 + c2];
        sm_u[L_X + r * 36 + 2 * c2] = v.x;
        sm_u[L_X + r * 36 + 2 * c2 + 1] = v.y;
    }
    float hw0 = head_w[j0], hw1 = head_w[j1];
    float creg[4][2][2];
#pragma unroll
    for (int a = 0; a < 4; a++)
#pragma unroll
        for (int b = 0; b < 2; b++) { creg[a][b][0] = 0.f; creg[a][b][1] = 0.f; }
    __syncthreads();

    for (int t = 0; t < TT; t++) {
        float acc[4][4][4] = {};
#pragma unroll 1
        for (int cs = 0; cs < 8; cs++) {
            const uint32_t* Ap = sm_u + ((cs < 4) ? L_X : L_H);
            int kb = (cs & 3) * 8;
            int kb2 = cs * 8;
            uint32_t Bh[4][2];
#pragma unroll
            for (int q = 0; q < 4; q++) {
                int pb = ((wn << 5) + (q << 3) + grp) * 68 + kb2;
                Bh[q][0] = sm_u[L_B + pb + tig];
                Bh[q][1] = sm_u[L_B + pb + tig + 4];
            }
#pragma unroll
            for (int mi = 0; mi < 4; mi++) {
                int rb = wm * 64 + mi * 16;
                uint32_t Ah[4];
                Ah[0] = Ap[(rb + grp) * 36 + kb + tig];
                Ah[1] = Ap[(rb + grp + 8) * 36 + kb + tig];
                Ah[2] = Ap[(rb + grp) * 36 + kb + tig + 4];
                Ah[3] = Ap[(rb + grp + 8) * 36 + kb + tig + 4];
#pragma unroll
                for (int q = 0; q < 4; q++)
                    mma_f16(acc[mi][q], Ah, Bh[q][0], Bh[q][1]);
            }
        }
        __syncthreads();

        uint2 rx2[4];
        if (t < TT - 1) {
            const uint2* ps = g_seqh + (size_t)(t + 1) * NN * 16;
#pragma unroll
            for (int i = 0; i < 4; i++) {
                int idx = tid + i * 512;
                int r = idx >> 4, c2 = idx & 15;
                int row = row0 + r;
                rx2[i] = (row < NN) ? ps[(size_t)row * 16 + c2] : make_uint2(0u, 0u);
            }
        }

        float bi0 = sBias[j0], bf0_ = sBias[64 + j0], bg0 = sBias[128 + j0], bo0 = sBias[192 + j0];
        float bi1 = sBias[j1], bf1_ = sBias[64 + j1], bg1 = sBias[128 + j1], bo1 = sBias[192 + j1];
#pragma unroll
        for (int mi = 0; mi < 4; mi++) {
#pragma unroll
            for (int rh = 0; rh < 2; rh++) {
                int r = wm * 64 + mi * 16 + grp + rh * 8;
                int ci = rh * 2;
                float gi0 = acc[mi][0][ci] + bi0, gf0 = acc[mi][0][ci + 1] + bf0_;
                float gg0 = acc[mi][1][ci] + bg0, go0 = acc[mi][1][ci + 1] + bo0;
                float gi1 = acc[mi][2][ci] + bi1, gf1 = acc[mi][2][ci + 1] + bf1_;
                float gg1 = acc[mi][3][ci] + bg1, go1 = acc[mi][3][ci + 1] + bo1;
                float c0 = creg[mi][rh][0], c1 = creg[mi][rh][1];
                c0 = sig_mufu(gf0) * c0 + sig_mufu(gi0) * tanh_mufu(gg0);
                c1 = sig_mufu(gf1) * c1 + sig_mufu(gi1) * tanh_mufu(gg1);
                creg[mi][rh][0] = c0; creg[mi][rh][1] = c1;
                float h0 = sig_mufu(go0) * tanh_mufu(c0);
                float h1 = sig_mufu(go1) * tanh_mufu(c1);
                if (t < TT - 1) {
                    int base0 = L_H + r * 36 + (j0 >> 1);
                    int sl = j0 & 1;
                    reinterpret_cast<__half*>(&sm_u[base0])[sl] = __float2half(h0);
                    reinterpret_cast<__half*>(&sm_u[base0 + 2])[sl] = __float2half(h1);
                } else {
                    float v = h0 * hw0 + h1 * hw1;
                    v += __shfl_xor_sync(0xffffffffu, v, 1);
                    v += __shfl_xor_sync(0xffffffffu, v, 2);
                    if (tig == 0) atomicAdd(&sLog[r], v);
                }
            }
        }

        if (t < TT - 1) {
#pragma unroll
            for (int i = 0; i < 4; i++) {
                int idx = tid + i * 512;
                int r = idx >> 4, c2 = idx & 15;
                sm_u[L_X + r * 36 + 2 * c2] = rx2[i].x;
                sm_u[L_X + r * 36 + 2 * c2 + 1] = rx2[i].y;
            }
        }
        __syncthreads();
    }

    if (tid < 128) {
        int row = row0 + tid;
        if (row < NN) out[row] = sLog[tid] + head_b[0];
    }

    // zero g_deg for the next graph replay (391 blocks x 1024 entries)
    int z0 = blockIdx.x * 1024 + tid;
    if (z0 < TT * NN) g_deg[z0] = 0;
    if (z0 + 512 < TT * NN) g_deg[z0 + 512] = 0;
}

extern "C" void kernel_launch(void* const* d_in, const int* in_sizes, int n_in,
                              void* d_out, int out_size) {
    const float* xs  = (const float*)d_in[0];
    const int*   ei  = (const int*)  d_in[1];
    const float* W1  = (const float*)d_in[2];
    const float* b1  = (const float*)d_in[3];
    const float* W2  = (const float*)d_in[4];
    const float* b2  = (const float*)d_in[5];
    const float* wih = (const float*)d_in[6];
    const float* whh = (const float*)d_in[7];
    const float* bih = (const float*)d_in[8];
    const float* bhh = (const float*)d_in[9];
    const float* hw  = (const float*)d_in[10];
    const float* hb  = (const float*)d_in[11];
    float* out = (float*)d_out;

    cudaFuncSetAttribute(k_lstm_f16,
                         cudaFuncAttributeMaxDynamicSharedMemorySize, L_TOT * 4);
    cudaFuncSetAttribute(k_gemm64h,
                         cudaFuncAttributeMaxDynamicSharedMemorySize, G2_TOT * 4);

    k_fill_bucket<<<(TT * EE + 255) / 256, 256>>>(ei);

    k_gemm1h<<<(TT * NN + 127) / 128, 128>>>(xs, W1);
    k_agg1h<<<((size_t)TT * NN * 16 + 511) / 512, 512>>>(b1);
    k_gemm64h<<<(TT * NN) / 128, 512, G2_TOT * 4>>>(W2);
    k_agg2h<<<((size_t)TT * NN * 16 + 511) / 512, 512>>>(b2);

    k_lstm_f16<<<NBLK, 512, L_TOT * 4>>>(wih, whh, bih, bhh, hw, hb, out);
}

// round 15
// speedup vs baseline: 2.0277x; 1.0977x over previous
#include <cuda_runtime.h>
#include <cuda_fp16.h>
#include <cuda_bf16.h>
#include <math.h>
#include <stdint.h>

#define NN  50000
#define TT  8
#define EE  800000
#define FIN 9
#define HH  64
#define CAP 96
#define TILE_M 128
#define NBLK ((NN + TILE_M - 1) / TILE_M)

__device__ int      g_deg [TT * NN];                 // zeroed by LSTM tail each launch
__device__ int      g_bkt [(size_t)TT * NN * CAP];   // uint2-unit offsets: (t*NN+s)*16
__device__ float    g_dinv[TT * NN];
__device__ uint32_t g_w2p [64 * 32];                 // W2 packed f16 pairs [j][kp]
__device__ uint2    g_hsh [TT * NN * 16];   // layer-1 hs (dinv-scaled)
__device__ uint2    g_acth[TT * NN * 16];   // layer-1 activation
__device__ uint2    g_hs2h[TT * NN * 16];   // layer-2 hs
__device__ uint2    g_seqh[TT * NN * 16];   // seq (f16)

// ---------------- MUFU-based nonlinearities --------------------------------
__device__ __forceinline__ float tanh_mufu(float x) {
    float y;
    asm("tanh.approx.f32 %0, %1;" : "=f"(y) : "f"(x));
    return y;
}
__device__ __forceinline__ float sig_mufu(float x) {
    return fmaf(tanh_mufu(x * 0.5f), 0.5f, 0.5f);
}

__device__ __forceinline__ uint32_t packh(float e0, float e1) {
    __half2 p = __floats2half2_rn(e0, e1);
    return *reinterpret_cast<uint32_t*>(&p);
}
__device__ __forceinline__ float2 h2f(uint32_t u) {
    return __half22float2(*reinterpret_cast<__half2*>(&u));
}
__device__ __forceinline__ uint32_t hadd2u(uint32_t a, uint32_t b) {
    __half2 r = __hadd2(*reinterpret_cast<__half2*>(&a), *reinterpret_cast<__half2*>(&b));
    return *reinterpret_cast<uint32_t*>(&r);
}
__device__ __forceinline__ void mma_f16(float* d, const uint32_t* a,
                                        uint32_t b0, uint32_t b1) {
    asm volatile(
        "mma.sync.aligned.m16n8k16.row.col.f32.f16.f16.f32 "
        "{%0,%1,%2,%3}, {%4,%5,%6,%7}, {%8,%9}, {%0,%1,%2,%3};"
        : "+f"(d[0]), "+f"(d[1]), "+f"(d[2]), "+f"(d[3])
        : "r"(a[0]), "r"(a[1]), "r"(a[2]), "r"(a[3]), "r"(b0), "r"(b1));
}

__global__ void k_fill_bucket(const int* __restrict__ ei) {
    int idx = blockIdx.x * blockDim.x + threadIdx.x;
    if (idx >= TT * EE) return;
    int t = idx / EE, e = idx - t * EE;
    int s = ei[(size_t)t * 2 * EE + e];
    int d = ei[(size_t)t * 2 * EE + EE + e];
    int td = t * NN + d;
    int pos = atomicAdd(&g_deg[td], 1);
    g_bkt[(size_t)td * CAP + pos] = (t * NN + s) * 16;   // uint2 units
}

// pre-pack W2 into [j][kp] f16-pair layout with coalesced reads
__global__ void k_packw2(const float* __restrict__ W2) {
    int t = blockIdx.x * blockDim.x + threadIdx.x;   // 0..2047
    if (t >= 2048) return;
    int j = t & 63, kp = t >> 6;
    float e0 = W2[(2 * kp) * 64 + j];
    float e1 = W2[(2 * kp + 1) * 64 + j];
    g_w2p[j * 32 + kp] = packh(e0, e1);
}

// layer-1 GEMM (K=9): coalesced x staging; dinv; -> g_hsh
__global__ __launch_bounds__(128) void k_gemm1h(
    const float* __restrict__ x, const float* __restrict__ W1)
{
    __shared__ float sW[FIN * HH];
    __shared__ float sX[128 * FIN];
    int tid = threadIdx.x;
    for (int i = tid; i < FIN * HH; i += 128) sW[i] = W1[i];
    int base = blockIdx.x * 128;
#pragma unroll
    for (int i = 0; i < FIN; i++) {
        int idx = tid + i * 128;
        sX[idx] = x[(size_t)base * FIN + idx];
    }
    __syncthreads();
    int n = base + tid;
    if (n >= TT * NN) return;
    float dv = rsqrtf((float)(g_deg[n] + 1));
    g_dinv[n] = dv;
    float xv[FIN];
#pragma unroll
    for (int k = 0; k < FIN; k++) xv[k] = sX[tid * FIN + k];
#pragma unroll
    for (int c = 0; c < HH; c += 4) {
        float4 o = make_float4(0.f, 0.f, 0.f, 0.f);
#pragma unroll
        for (int k = 0; k < FIN; k++) {
            float xk = xv[k];
            o.x = fmaf(xk, sW[k * HH + c + 0], o.x);
            o.y = fmaf(xk, sW[k * HH + c + 1], o.y);
            o.z = fmaf(xk, sW[k * HH + c + 2], o.z);
            o.w = fmaf(xk, sW[k * HH + c + 3], o.w);
        }
        uint2 u;
        u.x = packh(o.x * dv, o.y * dv);
        u.y = packh(o.z * dv, o.w * dv);
        g_hsh[(size_t)n * 16 + c / 4] = u;
    }
}

// ---------- gather: TWO nodes per warp (16 lanes each, uint2/lane) ---------
__device__ __forceinline__ void gather2n(const uint2* __restrict__ src,
                                         const int* __restrict__ bkt,
                                         int deg, int gw, int l16, float* f) {
    uint2 s = src[(size_t)gw * 16 + l16];
    float2 a0 = h2f(s.x), a1 = h2f(s.y);
    f[0] = a0.x; f[1] = a0.y; f[2] = a1.x; f[3] = a1.y;
    int e = 0;
    for (; e + 7 < deg; e += 8) {
        int4 oa = *reinterpret_cast<const int4*>(bkt + e);
        int4 ob = *reinterpret_cast<const int4*>(bkt + e + 4);
        uint2 v0 = src[oa.x + l16], v1 = src[oa.y + l16];
        uint2 v2 = src[oa.z + l16], v3 = src[oa.w + l16];
        uint2 v4 = src[ob.x + l16], v5 = src[ob.y + l16];
        uint2 v6 = src[ob.z + l16], v7 = src[ob.w + l16];
        uint32_t p0x = hadd2u(v0.x, v1.x), p0y = hadd2u(v0.y, v1.y);
        uint32_t p1x = hadd2u(v2.x, v3.x), p1y = hadd2u(v2.y, v3.y);
        uint32_t p2x = hadd2u(v4.x, v5.x), p2y = hadd2u(v4.y, v5.y);
        uint32_t p3x = hadd2u(v6.x, v7.x), p3y = hadd2u(v6.y, v7.y);
        float2 q0 = h2f(p0x), q1 = h2f(p1x), q2 = h2f(p2x), q3 = h2f(p3x);
        f[0] += (q0.x + q1.x) + (q2.x + q3.x);
        f[1] += (q0.y + q1.y) + (q2.y + q3.y);
        float2 r0 = h2f(p0y), r1 = h2f(p1y), r2 = h2f(p2y), r3 = h2f(p3y);
        f[2] += (r0.x + r1.x) + (r2.x + r3.x);
        f[3] += (r0.y + r1.y) + (r2.y + r3.y);
    }
    if (e + 3 < deg) {
        int4 oa = *reinterpret_cast<const int4*>(bkt + e);
        uint2 v0 = src[oa.x + l16], v1 = src[oa.y + l16];
        uint2 v2 = src[oa.z + l16], v3 = src[oa.w + l16];
        uint32_t p0x = hadd2u(v0.x, v1.x), p0y = hadd2u(v0.y, v1.y);
        uint32_t p1x = hadd2u(v2.x, v3.x), p1y = hadd2u(v2.y, v3.y);
        float2 q0 = h2f(p0x), q1 = h2f(p1x);
        f[0] += q0.x + q1.x;
        f[1] += q0.y + q1.y;
        float2 r0 = h2f(p0y), r1 = h2f(p1y);
        f[2] += r0.x + r1.x;
        f[3] += r0.y + r1.y;
        e += 4;
    }
    for (; e < deg; e++) {
        uint2 v = src[bkt[e] + l16];
        float2 q = h2f(v.x), r = h2f(v.y);
        f[0] += q.x; f[1] += q.y; f[2] += r.x; f[3] += r.y;
    }
}

// layer-1 aggregation -> g_acth
__global__ void k_agg1h(const float* __restrict__ b1) {
    int gw = ((blockIdx.x * blockDim.x + threadIdx.x) >> 4);
    int l16 = threadIdx.x & 15;
    if (gw >= TT * NN) return;
    int deg = g_deg[gw];
    const int* bkt = g_bkt + (size_t)gw * CAP;
    float f[4];
    gather2n(g_hsh, bkt, deg, gw, l16, f);
    float dv = g_dinv[gw];
    float4 bb = *reinterpret_cast<const float4*>(b1 + l16 * 4);
    float a0 = fmaxf(fmaf(f[0], dv, bb.x), 0.f);
    float a1 = fmaxf(fmaf(f[1], dv, bb.y), 0.f);
    float a2 = fmaxf(fmaf(f[2], dv, bb.z), 0.f);
    float a3 = fmaxf(fmaf(f[3], dv, bb.w), 0.f);
    uint2 u; u.x = packh(a0, a1); u.y = packh(a2, a3);
    g_acth[(size_t)gw * 16 + l16] = u;
}

// layer-2 GEMM: A = g_acth (exact fp16) @ W2 (pre-packed f16) * dinv -> g_hs2h
#define G2_A   0          // 128 x 36 u32
#define G2_B   4608       // 64 x 36 u32
#define G2_TOT 6912

__global__ __launch_bounds__(512) void k_gemm64h() {
    extern __shared__ uint32_t sg[];
    int tid = threadIdx.x, lane = tid & 31, w = tid >> 5;
    int grp = lane >> 2, tig = lane & 3;
    int wm = w >> 3, wn = w & 7;
    int row0 = blockIdx.x * 128;

    // flat coalesced B staging from pre-packed global
#pragma unroll
    for (int i = 0; i < 4; i++) {
        int idx = tid + i * 512;              // 0..2047
        int j = idx >> 5, kp = idx & 31;
        sg[G2_B + j * 36 + kp] = g_w2p[idx];
    }
#pragma unroll
    for (int i = 0; i < 4; i++) {
        int idx = tid + i * 512;              // 2048 uint2
        int r = idx >> 4, k2 = idx & 15;
        uint2 v = g_acth[(size_t)(row0 + r) * 16 + k2];
        sg[G2_A + r * 36 + 2 * k2] = v.x;
        sg[G2_A + r * 36 + 2 * k2 + 1] = v.y;
    }
    __syncthreads();

    float acc4[4][4] = {};
#pragma unroll
    for (int cs = 0; cs < 4; cs++) {
        int kb = cs * 8;
        int pb = (wn * 8 + grp) * 36 + kb;
        uint32_t b0 = sg[G2_B + pb + tig], b1 = sg[G2_B + pb + tig + 4];
#pragma unroll
        for (int mi = 0; mi < 4; mi++) {
            int rb = wm * 64 + mi * 16;
            uint32_t Ah[4];
            Ah[0] = sg[G2_A + (rb + grp) * 36 + kb + tig];
            Ah[1] = sg[G2_A + (rb + grp + 8) * 36 + kb + tig];
            Ah[2] = sg[G2_A + (rb + grp) * 36 + kb + tig + 4];
            Ah[3] = sg[G2_A + (rb + grp + 8) * 36 + kb + tig + 4];
            mma_f16(acc4[mi], Ah, b0, b1);
        }
    }
#pragma unroll
    for (int mi = 0; mi < 4; mi++) {
#pragma unroll
        for (int rh = 0; rh < 2; rh++) {
            int row = row0 + wm * 64 + mi * 16 + grp + rh * 8;
            float dv = g_dinv[row];
            reinterpret_cast<uint32_t*>(g_hs2h)[(size_t)row * 32 + wn * 4 + tig] =
                packh(acc4[mi][rh * 2] * dv, acc4[mi][rh * 2 + 1] * dv);
        }
    }
}

// layer-2 aggregation -> g_seqh
__global__ void k_agg2h(const float* __restrict__ b) {
    int gw = ((blockIdx.x * blockDim.x + threadIdx.x) >> 4);
    int l16 = threadIdx.x & 15;
    if (gw >= TT * NN) return;
    int deg = g_deg[gw];
    const int* bkt = g_bkt + (size_t)gw * CAP;
    float f[4];
    gather2n(g_hs2h, bkt, deg, gw, l16, f);
    float dv = g_dinv[gw];
    float4 bb = *reinterpret_cast<const float4*>(b + l16 * 4);
    float a0 = fmaxf(fmaf(f[0], dv, bb.x), 0.f);
    float a1 = fmaxf(fmaf(f[1], dv, bb.y), 0.f);
    float a2 = fmaxf(fmaf(f[2], dv, bb.z), 0.f);
    float a3 = fmaxf(fmaf(f[3], dv, bb.w), 0.f);
    uint2 u; u.x = packh(a0, a1); u.y = packh(a2, a3);
    g_seqh[(size_t)gw * 16 + l16] = u;
}

// ====== fused LSTM over all T + head; zeros g_deg at tail ==================
#define L_X    0
#define L_H    4608
#define L_B    9216
#define L_BIAS 26624
#define L_LOG  26880
#define L_TOT  27008

__global__ __launch_bounds__(512, 1) void k_lstm_f16(
    const float* __restrict__ w_ih, const float* __restrict__ w_hh,
    const float* __restrict__ b_ih, const float* __restrict__ b_hh,
    const float* __restrict__ head_w, const float* __restrict__ head_b,
    float* __restrict__ out)
{
    extern __shared__ uint32_t sm_u[];
    float* sBias = reinterpret_cast<float*>(sm_u + L_BIAS);
    float* sLog  = reinterpret_cast<float*>(sm_u + L_LOG);

    int tid = threadIdx.x, lane = tid & 31, w = tid >> 5;
    int grp = lane >> 2, tig = lane & 3;
    int wm = w >> 3, wn = w & 7;
    int row0 = blockIdx.x * TILE_M;
    int j0 = (wn << 3) + tig, j1 = j0 + 4;

    for (int i = tid; i < 256 * 64; i += 512) {
        int p = i >> 6, kp = i & 63;
        int wnp = p >> 5, rem = p & 31, q = rem >> 3, e = rem & 7;
        int gate = ((q & 1) << 1) | (e & 1);
        int L = (gate << 6) + (wnp << 3) + ((q >> 1) << 2) + (e >> 1);
        int k = kp * 2;
        float2 v = (k < 64)
            ? *reinterpret_cast<const float2*>(w_ih + (size_t)L * 64 + k)
            : *reinterpret_cast<const float2*>(w_hh + (size_t)L * 64 + (k - 64));
        sm_u[L_B + p * 68 + kp] = packh(v.x, v.y);
    }
    for (int i = tid; i < 4608; i += 512) sm_u[L_H + i] = 0u;
    if (tid < 256) sBias[tid] = b_ih[tid] + b_hh[tid];
    if (tid < 128) sLog[tid] = 0.f;
#pragma unroll
    for (int i = 0; i < 4; i++) {
        int idx = tid + i * 512;
        int r = idx >> 4, c2 = idx & 15;
        int row = row0 + r;
        uint2 v = make_uint2(0u, 0u);
        if (row < NN) v = g_seqh[(size_t)row * 16 + c2];
        sm_u[L_X + r * 36 + 2 * c2] = v.x;
        sm_u[L_X + r * 36 + 2 * c2 + 1] = v.y;
    }
    float hw0 = head_w[j0], hw1 = head_w[j1];
    float creg[4][2][2];
#pragma unroll
    for (int a = 0; a < 4; a++)
#pragma unroll
        for (int b = 0; b < 2; b++) { creg[a][b][0] = 0.f; creg[a][b][1] = 0.f; }
    __syncthreads();

    for (int t = 0; t < TT; t++) {
        float acc[4][4][4] = {};
#pragma unroll 1
        for (int cs = 0; cs < 8; cs++) {
            const uint32_t* Ap = sm_u + ((cs < 4) ? L_X : L_H);
            int kb = (cs & 3) * 8;
            int kb2 = cs * 8;
            uint32_t Bh[4][2];
#pragma unroll
            for (int q = 0; q < 4; q++) {
                int pb = ((wn << 5) + (q << 3) + grp) * 68 + kb2;
                Bh[q][0] = sm_u[L_B + pb + tig];
                Bh[q][1] = sm_u[L_B + pb + tig + 4];
            }
#pragma unroll
            for (int mi = 0; mi < 4; mi++) {
                int rb = wm * 64 + mi * 16;
                uint32_t Ah[4];
                Ah[0] = Ap[(rb + grp) * 36 + kb + tig];
                Ah[1] = Ap[(rb + grp + 8) * 36 + kb + tig];
                Ah[2] = Ap[(rb + grp) * 36 + kb + tig + 4];
                Ah[3] = Ap[(rb + grp + 8) * 36 + kb + tig + 4];
#pragma unroll
                for (int q = 0; q < 4; q++)
                    mma_f16(acc[mi][q], Ah, Bh[q][0], Bh[q][1]);
            }
        }
        __syncthreads();

        uint2 rx2[4];
        if (t < TT - 1) {
            const uint2* ps = g_seqh + (size_t)(t + 1) * NN * 16;
#pragma unroll
            for (int i = 0; i < 4; i++) {
                int idx = tid + i * 512;
                int r = idx >> 4, c2 = idx & 15;
                int row = row0 + r;
                rx2[i] = (row < NN) ? ps[(size_t)row * 16 + c2] : make_uint2(0u, 0u);
            }
        }

        float bi0 = sBias[j0], bf0_ = sBias[64 + j0], bg0 = sBias[128 + j0], bo0 = sBias[192 + j0];
        float bi1 = sBias[j1], bf1_ = sBias[64 + j1], bg1 = sBias[128 + j1], bo1 = sBias[192 + j1];
#pragma unroll
        for (int mi = 0; mi < 4; mi++) {
#pragma unroll
            for (int rh = 0; rh < 2; rh++) {
                int r = wm * 64 + mi * 16 + grp + rh * 8;
                int ci = rh * 2;
                float gi0 = acc[mi][0][ci] + bi0, gf0 = acc[mi][0][ci + 1] + bf0_;
                float gg0 = acc[mi][1][ci] + bg0, go0 = acc[mi][1][ci + 1] + bo0;
                float gi1 = acc[mi][2][ci] + bi1, gf1 = acc[mi][2][ci + 1] + bf1_;
                float gg1 = acc[mi][3][ci] + bg1, go1 = acc[mi][3][ci + 1] + bo1;
                float c0 = creg[mi][rh][0], c1 = creg[mi][rh][1];
                c0 = sig_mufu(gf0) * c0 + sig_mufu(gi0) * tanh_mufu(gg0);
                c1 = sig_mufu(gf1) * c1 + sig_mufu(gi1) * tanh_mufu(gg1);
                creg[mi][rh][0] = c0; creg[mi][rh][1] = c1;
                float h0 = sig_mufu(go0) * tanh_mufu(c0);
                float h1 = sig_mufu(go1) * tanh_mufu(c1);
                if (t < TT - 1) {
                    int base0 = L_H + r * 36 + (j0 >> 1);
                    int sl = j0 & 1;
                    reinterpret_cast<__half*>(&sm_u[base0])[sl] = __float2half(h0);
                    reinterpret_cast<__half*>(&sm_u[base0 + 2])[sl] = __float2half(h1);
                } else {
                    float v = h0 * hw0 + h1 * hw1;
                    v += __shfl_xor_sync(0xffffffffu, v, 1);
                    v += __shfl_xor_sync(0xffffffffu, v, 2);
                    if (tig == 0) atomicAdd(&sLog[r], v);
                }
            }
        }

        if (t < TT - 1) {
#pragma unroll
            for (int i = 0; i < 4; i++) {
                int idx = tid + i * 512;
                int r = idx >> 4, c2 = idx & 15;
                sm_u[L_X + r * 36 + 2 * c2] = rx2[i].x;
                sm_u[L_X + r * 36 + 2 * c2 + 1] = rx2[i].y;
            }
        }
        __syncthreads();
    }

    if (tid < 128) {
        int row = row0 + tid;
        if (row < NN) out[row] = sLog[tid] + head_b[0];
    }

    // zero g_deg for the next graph replay
    int z0 = blockIdx.x * 1024 + tid;
    if (z0 < TT * NN) g_deg[z0] = 0;
    if (z0 + 512 < TT * NN) g_deg[z0 + 512] = 0;
}

extern "C" void kernel_launch(void* const* d_in, const int* in_sizes, int n_in,
                              void* d_out, int out_size) {
    const float* xs  = (const float*)d_in[0];
    const int*   ei  = (const int*)  d_in[1];
    const float* W1  = (const float*)d_in[2];
    const float* b1  = (const float*)d_in[3];
    const float* W2  = (const float*)d_in[4];
    const float* b2  = (const float*)d_in[5];
    const float* wih = (const float*)d_in[6];
    const float* whh = (const float*)d_in[7];
    const float* bih = (const float*)d_in[8];
    const float* bhh = (const float*)d_in[9];
    const float* hw  = (const float*)d_in[10];
    const float* hb  = (const float*)d_in[11];
    float* out = (float*)d_out;

    cudaFuncSetAttribute(k_lstm_f16,
                         cudaFuncAttributeMaxDynamicSharedMemorySize, L_TOT * 4);
    cudaFuncSetAttribute(k_gemm64h,
                         cudaFuncAttributeMaxDynamicSharedMemorySize, G2_TOT * 4);

    k_fill_bucket<<<(TT * EE + 255) / 256, 256>>>(ei);
    k_packw2<<<8, 256>>>(W2);

    k_gemm1h<<<(TT * NN + 127) / 128, 128>>>(xs, W1);
    k_agg1h<<<((size_t)TT * NN * 16 + 511) / 512, 512>>>(b1);
    k_gemm64h<<<(TT * NN) / 128, 512, G2_TOT * 4>>>();
    k_agg2h<<<((size_t)TT * NN * 16 + 511) / 512, 512>>>(b2);

    k_lstm_f16<<<NBLK, 512, L_TOT * 4>>>(wih, whh, bih, bhh, hw, hb, out);
}

// round 16
// speedup vs baseline: 2.2373x; 1.1034x over previous
#include <cuda_runtime.h>
#include <cuda_fp16.h>
#include <cuda_bf16.h>
#include <math.h>
#include <stdint.h>

#define NN  50000
#define TT  8
#define EE  800000
#define FIN 9
#define HH  64
#define CAP 96
#define TILE_M 128
#define NBLK ((NN + TILE_M - 1) / TILE_M)

__device__ int      g_deg [TT * NN];                 // zeroed by LSTM tail each launch
__device__ int      g_bkt [(size_t)TT * NN * CAP];   // uint4-unit offsets: (t*NN+s)*8
__device__ float    g_dinv[TT * NN];
__device__ uint32_t g_w2p [64 * 32];                 // W2 packed f16 pairs [j][kp]
__device__ uint4    g_hsh [TT * NN * 8];   // layer-1 hs (dinv-scaled), f16
__device__ uint4    g_acth[TT * NN * 8];   // layer-1 activation
__device__ uint4    g_hs2h[TT * NN * 8];   // layer-2 hs
__device__ uint4    g_seqh[TT * NN * 8];   // seq (f16)

// ---------------- MUFU-based nonlinearities --------------------------------
__device__ __forceinline__ float tanh_mufu(float x) {
    float y;
    asm("tanh.approx.f32 %0, %1;" : "=f"(y) : "f"(x));
    return y;
}
__device__ __forceinline__ float sig_mufu(float x) {
    return fmaf(tanh_mufu(x * 0.5f), 0.5f, 0.5f);
}

__device__ __forceinline__ uint32_t packh(float e0, float e1) {
    __half2 p = __floats2half2_rn(e0, e1);
    return *reinterpret_cast<uint32_t*>(&p);
}
__device__ __forceinline__ float2 h2f(uint32_t u) {
    return __half22float2(*reinterpret_cast<__half2*>(&u));
}
__device__ __forceinline__ uint32_t hadd2u(uint32_t a, uint32_t b) {
    __half2 r = __hadd2(*reinterpret_cast<__half2*>(&a), *reinterpret_cast<__half2*>(&b));
    return *reinterpret_cast<uint32_t*>(&r);
}
__device__ __forceinline__ void mma_f16(float* d, const uint32_t* a,
                                        uint32_t b0, uint32_t b1) {
    asm volatile(
        "mma.sync.aligned.m16n8k16.row.col.f32.f16.f16.f32 "
        "{%0,%1,%2,%3}, {%4,%5,%6,%7}, {%8,%9}, {%0,%1,%2,%3};"
        : "+f"(d[0]), "+f"(d[1]), "+f"(d[2]), "+f"(d[3])
        : "r"(a[0]), "r"(a[1]), "r"(a[2]), "r"(a[3]), "r"(b0), "r"(b1));
}

__global__ void k_fill_bucket(const int* __restrict__ ei) {
    int idx = blockIdx.x * blockDim.x + threadIdx.x;
    if (idx >= TT * EE) return;
    int t = idx / EE, e = idx - t * EE;
    int s = ei[(size_t)t * 2 * EE + e];
    int d = ei[(size_t)t * 2 * EE + EE + e];
    int td = t * NN + d;
    int pos = atomicAdd(&g_deg[td], 1);
    g_bkt[(size_t)td * CAP + pos] = (t * NN + s) * 8;   // uint4 units
}

// pre-pack W2 into [j][kp] f16-pair layout with coalesced reads
__global__ void k_packw2(const float* __restrict__ W2) {
    int t = blockIdx.x * blockDim.x + threadIdx.x;
    if (t >= 2048) return;
    int j = t & 63, kp = t >> 6;
    float e0 = W2[(2 * kp) * 64 + j];
    float e1 = W2[(2 * kp + 1) * 64 + j];
    g_w2p[j * 32 + kp] = packh(e0, e1);
}

// layer-1 GEMM (K=9): coalesced x staging; dinv; -> g_hsh
__global__ __launch_bounds__(128) void k_gemm1h(
    const float* __restrict__ x, const float* __restrict__ W1)
{
    __shared__ float sW[FIN * HH];
    __shared__ float sX[128 * FIN];
    int tid = threadIdx.x;
    for (int i = tid; i < FIN * HH; i += 128) sW[i] = W1[i];
    int base = blockIdx.x * 128;
#pragma unroll
    for (int i = 0; i < FIN; i++) {
        int idx = tid + i * 128;
        sX[idx] = x[(size_t)base * FIN + idx];
    }
    __syncthreads();
    int n = base + tid;
    if (n >= TT * NN) return;
    float dv = rsqrtf((float)(g_deg[n] + 1));
    g_dinv[n] = dv;
    float xv[FIN];
#pragma unroll
    for (int k = 0; k < FIN; k++) xv[k] = sX[tid * FIN + k];
#pragma unroll
    for (int c = 0; c < HH; c += 8) {
        float o[8];
#pragma unroll
        for (int j = 0; j < 8; j++) o[j] = 0.f;
#pragma unroll
        for (int k = 0; k < FIN; k++) {
            float xk = xv[k];
#pragma unroll
            for (int j = 0; j < 8; j++)
                o[j] = fmaf(xk, sW[k * HH + c + j], o[j]);
        }
        uint4 u;
        u.x = packh(o[0] * dv, o[1] * dv);
        u.y = packh(o[2] * dv, o[3] * dv);
        u.z = packh(o[4] * dv, o[5] * dv);
        u.w = packh(o[6] * dv, o[7] * dv);
        g_hsh[(size_t)n * 8 + c / 8] = u;
    }
}

// ---------- gather: FOUR nodes per warp (8 lanes each, uint4/lane) ---------
__device__ __forceinline__ void acc8(float* f, uint4 p) {
    float2 q0 = h2f(p.x), q1 = h2f(p.y), q2 = h2f(p.z), q3 = h2f(p.w);
    f[0] += q0.x; f[1] += q0.y; f[2] += q1.x; f[3] += q1.y;
    f[4] += q2.x; f[5] += q2.y; f[6] += q3.x; f[7] += q3.y;
}

__device__ __forceinline__ void gather4n(const uint4* __restrict__ src,
                                         const int* __restrict__ bkt,
                                         int deg, int gw, int l8, float* f) {
    uint4 s = src[(size_t)gw * 8 + l8];
    float2 a0 = h2f(s.x), a1 = h2f(s.y), a2 = h2f(s.z), a3 = h2f(s.w);
    f[0] = a0.x; f[1] = a0.y; f[2] = a1.x; f[3] = a1.y;
    f[4] = a2.x; f[5] = a2.y; f[6] = a3.x; f[7] = a3.y;
    int e = 0;
    for (; e + 7 < deg; e += 8) {
        int4 oa = *reinterpret_cast<const int4*>(bkt + e);
        int4 ob = *reinterpret_cast<const int4*>(bkt + e + 4);
        uint4 v0 = src[oa.x + l8], v1 = src[oa.y + l8];
        uint4 v2 = src[oa.z + l8], v3 = src[oa.w + l8];
        uint4 v4 = src[ob.x + l8], v5 = src[ob.y + l8];
        uint4 v6 = src[ob.z + l8], v7 = src[ob.w + l8];
        uint4 p0, p1, p2, p3;
        p0.x = hadd2u(v0.x, v1.x); p0.y = hadd2u(v0.y, v1.y);
        p0.z = hadd2u(v0.z, v1.z); p0.w = hadd2u(v0.w, v1.w);
        p1.x = hadd2u(v2.x, v3.x); p1.y = hadd2u(v2.y, v3.y);
        p1.z = hadd2u(v2.z, v3.z); p1.w = hadd2u(v2.w, v3.w);
        p2.x = hadd2u(v4.x, v5.x); p2.y = hadd2u(v4.y, v5.y);
        p2.z = hadd2u(v4.z, v5.z); p2.w = hadd2u(v4.w, v5.w);
        p3.x = hadd2u(v6.x, v7.x); p3.y = hadd2u(v6.y, v7.y);
        p3.z = hadd2u(v6.z, v7.z); p3.w = hadd2u(v6.w, v7.w);
        acc8(f, p0); acc8(f, p1); acc8(f, p2); acc8(f, p3);
    }
    if (e + 3 < deg) {
        int4 oa = *reinterpret_cast<const int4*>(bkt + e);
        uint4 v0 = src[oa.x + l8], v1 = src[oa.y + l8];
        uint4 v2 = src[oa.z + l8], v3 = src[oa.w + l8];
        uint4 p0, p1;
        p0.x = hadd2u(v0.x, v1.x); p0.y = hadd2u(v0.y, v1.y);
        p0.z = hadd2u(v0.z, v1.z); p0.w = hadd2u(v0.w, v1.w);
        p1.x = hadd2u(v2.x, v3.x); p1.y = hadd2u(v2.y, v3.y);
        p1.z = hadd2u(v2.z, v3.z); p1.w = hadd2u(v2.w, v3.w);
        acc8(f, p0); acc8(f, p1);
        e += 4;
    }
    for (; e < deg; e++) {
        uint4 v = src[bkt[e] + l8];
        acc8(f, v);
    }
}

// layer-1 aggregation -> g_acth
__global__ void k_agg1h(const float* __restrict__ b1) {
    int gw = ((blockIdx.x * blockDim.x + threadIdx.x) >> 3);
    int l8 = threadIdx.x & 7;
    if (gw >= TT * NN) return;
    int deg = g_deg[gw];
    const int* bkt = g_bkt + (size_t)gw * CAP;
    float f[8];
    gather4n(g_hsh, bkt, deg, gw, l8, f);
    float dv = g_dinv[gw];
    float4 bA = *reinterpret_cast<const float4*>(b1 + l8 * 8);
    float4 bB = *reinterpret_cast<const float4*>(b1 + l8 * 8 + 4);
    float a0 = fmaxf(fmaf(f[0], dv, bA.x), 0.f);
    float a1 = fmaxf(fmaf(f[1], dv, bA.y), 0.f);
    float a2 = fmaxf(fmaf(f[2], dv, bA.z), 0.f);
    float a3 = fmaxf(fmaf(f[3], dv, bA.w), 0.f);
    float a4 = fmaxf(fmaf(f[4], dv, bB.x), 0.f);
    float a5 = fmaxf(fmaf(f[5], dv, bB.y), 0.f);
    float a6 = fmaxf(fmaf(f[6], dv, bB.z), 0.f);
    float a7 = fmaxf(fmaf(f[7], dv, bB.w), 0.f);
    uint4 u;
    u.x = packh(a0, a1); u.y = packh(a2, a3);
    u.z = packh(a4, a5); u.w = packh(a6, a7);
    g_acth[(size_t)gw * 8 + l8] = u;
}

// layer-2 GEMM: A = g_acth (exact fp16) @ W2 (pre-packed f16) * dinv -> g_hs2h
#define G2_A   0          // 128 x 36 u32
#define G2_B   4608       // 64 x 36 u32
#define G2_TOT 6912

__global__ __launch_bounds__(512) void k_gemm64h() {
    extern __shared__ uint32_t sg[];
    int tid = threadIdx.x, lane = tid & 31, w = tid >> 5;
    int grp = lane >> 2, tig = lane & 3;
    int wm = w >> 3, wn = w & 7;
    int row0 = blockIdx.x * 128;

#pragma unroll
    for (int i = 0; i < 4; i++) {
        int idx = tid + i * 512;              // 0..2047
        int j = idx >> 5, kp = idx & 31;
        sg[G2_B + j * 36 + kp] = g_w2p[idx];
    }
#pragma unroll
    for (int i = 0; i < 2; i++) {
        int idx = tid + i * 512;              // 1024 uint4
        int r = idx >> 3, k4 = idx & 7;
        uint4 v = g_acth[(size_t)(row0 + r) * 8 + k4];
        *reinterpret_cast<uint4*>(&sg[G2_A + r * 36 + 4 * k4]) = v;
    }
    __syncthreads();

    float acc4[4][4] = {};
#pragma unroll
    for (int cs = 0; cs < 4; cs++) {
        int kb = cs * 8;
        int pb = (wn * 8 + grp) * 36 + kb;
        uint32_t b0 = sg[G2_B + pb + tig], b1 = sg[G2_B + pb + tig + 4];
#pragma unroll
        for (int mi = 0; mi < 4; mi++) {
            int rb = wm * 64 + mi * 16;
            uint32_t Ah[4];
            Ah[0] = sg[G2_A + (rb + grp) * 36 + kb + tig];
            Ah[1] = sg[G2_A + (rb + grp + 8) * 36 + kb + tig];
            Ah[2] = sg[G2_A + (rb + grp) * 36 + kb + tig + 4];
            Ah[3] = sg[G2_A + (rb + grp + 8) * 36 + kb + tig + 4];
            mma_f16(acc4[mi], Ah, b0, b1);
        }
    }
#pragma unroll
    for (int mi = 0; mi < 4; mi++) {
#pragma unroll
        for (int rh = 0; rh < 2; rh++) {
            int row = row0 + wm * 64 + mi * 16 + grp + rh * 8;
            float dv = g_dinv[row];
            reinterpret_cast<uint32_t*>(g_hs2h)[(size_t)row * 32 + wn * 4 + tig] =
                packh(acc4[mi][rh * 2] * dv, acc4[mi][rh * 2 + 1] * dv);
        }
    }
}

// layer-2 aggregation -> g_seqh
__global__ void k_agg2h(const float* __restrict__ b) {
    int gw = ((blockIdx.x * blockDim.x + threadIdx.x) >> 3);
    int l8 = threadIdx.x & 7;
    if (gw >= TT * NN) return;
    int deg = g_deg[gw];
    const int* bkt = g_bkt + (size_t)gw * CAP;
    float f[8];
    gather4n(g_hs2h, bkt, deg, gw, l8, f);
    float dv = g_dinv[gw];
    float4 bA = *reinterpret_cast<const float4*>(b + l8 * 8);
    float4 bB = *reinterpret_cast<const float4*>(b + l8 * 8 + 4);
    float a0 = fmaxf(fmaf(f[0], dv, bA.x), 0.f);
    float a1 = fmaxf(fmaf(f[1], dv, bA.y), 0.f);
    float a2 = fmaxf(fmaf(f[2], dv, bA.z), 0.f);
    float a3 = fmaxf(fmaf(f[3], dv, bA.w), 0.f);
    float a4 = fmaxf(fmaf(f[4], dv, bB.x), 0.f);
    float a5 = fmaxf(fmaf(f[5], dv, bB.y), 0.f);
    float a6 = fmaxf(fmaf(f[6], dv, bB.z), 0.f);
    float a7 = fmaxf(fmaf(f[7], dv, bB.w), 0.f);
    uint4 u;
    u.x = packh(a0, a1); u.y = packh(a2, a3);
    u.z = packh(a4, a5); u.w = packh(a6, a7);
    g_seqh[(size_t)gw * 8 + l8] = u;
}

// ====== fused LSTM over all T + head; zeros g_deg at tail ==================
#define L_X    0
#define L_H    4608
#define L_B    9216
#define L_BIAS 26624
#define L_LOG  26880
#define L_TOT  27008

__global__ __launch_bounds__(512, 1) void k_lstm_f16(
    const float* __restrict__ w_ih, const float* __restrict__ w_hh,
    const float* __restrict__ b_ih, const float* __restrict__ b_hh,
    const float* __restrict__ head_w, const float* __restrict__ head_b,
    float* __restrict__ out)
{
    extern __shared__ uint32_t sm_u[];
    float* sBias = reinterpret_cast<float*>(sm_u + L_BIAS);
    float* sLog  = reinterpret_cast<float*>(sm_u + L_LOG);

    int tid = threadIdx.x, lane = tid & 31, w = tid >> 5;
    int grp = lane >> 2, tig = lane & 3;
    int wm = w >> 3, wn = w & 7;
    int row0 = blockIdx.x * TILE_M;
    int j0 = (wn << 3) + tig, j1 = j0 + 4;

    for (int i = tid; i < 256 * 64; i += 512) {
        int p = i >> 6, kp = i & 63;
        int wnp = p >> 5, rem = p & 31, q = rem >> 3, e = rem & 7;
        int gate = ((q & 1) << 1) | (e & 1);
        int L = (gate << 6) + (wnp << 3) + ((q >> 1) << 2) + (e >> 1);
        int k = kp * 2;
        float2 v = (k < 64)
            ? *reinterpret_cast<const float2*>(w_ih + (size_t)L * 64 + k)
            : *reinterpret_cast<const float2*>(w_hh + (size_t)L * 64 + (k - 64));
        sm_u[L_B + p * 68 + kp] = packh(v.x, v.y);
    }
    for (int i = tid; i < 4608; i += 512) sm_u[L_H + i] = 0u;
    if (tid < 256) sBias[tid] = b_ih[tid] + b_hh[tid];
    if (tid < 128) sLog[tid] = 0.f;
    // x(0)
#pragma unroll
    for (int i = 0; i < 2; i++) {
        int idx = tid + i * 512;              // 1024 uint4
        int r = idx >> 3, c4 = idx & 7;
        int row = row0 + r;
        uint4 v = make_uint4(0u, 0u, 0u, 0u);
        if (row < NN) v = g_seqh[(size_t)row * 8 + c4];
        *reinterpret_cast<uint4*>(&sm_u[L_X + r * 36 + 4 * c4]) = v;
    }
    float hw0 = head_w[j0], hw1 = head_w[j1];
    float creg[4][2][2];
#pragma unroll
    for (int a = 0; a < 4; a++)
#pragma unroll
        for (int b = 0; b < 2; b++) { creg[a][b][0] = 0.f; creg[a][b][1] = 0.f; }
    __syncthreads();

    for (int t = 0; t < TT; t++) {
        float acc[4][4][4] = {};
#pragma unroll 1
        for (int cs = 0; cs < 8; cs++) {
            const uint32_t* Ap = sm_u + ((cs < 4) ? L_X : L_H);
            int kb = (cs & 3) * 8;
            int kb2 = cs * 8;
            uint32_t Bh[4][2];
#pragma unroll
            for (int q = 0; q < 4; q++) {
                int pb = ((wn << 5) + (q << 3) + grp) * 68 + kb2;
                Bh[q][0] = sm_u[L_B + pb + tig];
                Bh[q][1] = sm_u[L_B + pb + tig + 4];
            }
#pragma unroll
            for (int mi = 0; mi < 4; mi++) {
                int rb = wm * 64 + mi * 16;
                uint32_t Ah[4];
                Ah[0] = Ap[(rb + grp) * 36 + kb + tig];
                Ah[1] = Ap[(rb + grp + 8) * 36 + kb + tig];
                Ah[2] = Ap[(rb + grp) * 36 + kb + tig + 4];
                Ah[3] = Ap[(rb + grp + 8) * 36 + kb + tig + 4];
#pragma unroll
                for (int q = 0; q < 4; q++)
                    mma_f16(acc[mi][q], Ah, Bh[q][0], Bh[q][1]);
            }
        }
        __syncthreads();

        uint4 rx4[2];
        if (t < TT - 1) {
            const uint4* ps = g_seqh + (size_t)(t + 1) * NN * 8;
#pragma unroll
            for (int i = 0; i < 2; i++) {
                int idx = tid + i * 512;
                int r = idx >> 3, c4 = idx & 7;
                int row = row0 + r;
                rx4[i] = (row < NN) ? ps[(size_t)row * 8 + c4]
                                    : make_uint4(0u, 0u, 0u, 0u);
            }
        }

        float bi0 = sBias[j0], bf0_ = sBias[64 + j0], bg0 = sBias[128 + j0], bo0 = sBias[192 + j0];
        float bi1 = sBias[j1], bf1_ = sBias[64 + j1], bg1 = sBias[128 + j1], bo1 = sBias[192 + j1];
#pragma unroll
        for (int mi = 0; mi < 4; mi++) {
#pragma unroll
            for (int rh = 0; rh < 2; rh++) {
                int r = wm * 64 + mi * 16 + grp + rh * 8;
                int ci = rh * 2;
                float gi0 = acc[mi][0][ci] + bi0, gf0 = acc[mi][0][ci + 1] + bf0_;
                float gg0 = acc[mi][1][ci] + bg0, go0 = acc[mi][1][ci + 1] + bo0;
                float gi1 = acc[mi][2][ci] + bi1, gf1 = acc[mi][2][ci + 1] + bf1_;
                float gg1 = acc[mi][3][ci] + bg1, go1 = acc[mi][3][ci + 1] + bo1;
                float c0 = creg[mi][rh][0], c1 = creg[mi][rh][1];
                c0 = sig_mufu(gf0) * c0 + sig_mufu(gi0) * tanh_mufu(gg0);
                c1 = sig_mufu(gf1) * c1 + sig_mufu(gi1) * tanh_mufu(gg1);
                creg[mi][rh][0] = c0; creg[mi][rh][1] = c1;
                float h0 = sig_mufu(go0) * tanh_mufu(c0);
                float h1 = sig_mufu(go1) * tanh_mufu(c1);
                if (t < TT - 1) {
                    int base0 = L_H + r * 36 + (j0 >> 1);
                    int sl = j0 & 1;
                    reinterpret_cast<__half*>(&sm_u[base0])[sl] = __float2half(h0);
                    reinterpret_cast<__half*>(&sm_u[base0 + 2])[sl] = __float2half(h1);
                } else {
                    float v = h0 * hw0 + h1 * hw1;
                    v += __shfl_xor_sync(0xffffffffu, v, 1);
                    v += __shfl_xor_sync(0xffffffffu, v, 2);
                    if (tig == 0) atomicAdd(&sLog[r], v);
                }
            }
        }

        if (t < TT - 1) {
#pragma unroll
            for (int i = 0; i < 2; i++) {
                int idx = tid + i * 512;
                int r = idx >> 3, c4 = idx & 7;
                *reinterpret_cast<uint4*>(&sm_u[L_X + r * 36 + 4 * c4]) = rx4[i];
            }
        }
        __syncthreads();
    }

    if (tid < 128) {
        int row = row0 + tid;
        if (row < NN) out[row] = sLog[tid] + head_b[0];
    }

    // zero g_deg for the next graph replay
    int z0 = blockIdx.x * 1024 + tid;
    if (z0 < TT * NN) g_deg[z0] = 0;
    if (z0 + 512 < TT * NN) g_deg[z0 + 512] = 0;
}

extern "C" void kernel_launch(void* const* d_in, const int* in_sizes, int n_in,
                              void* d_out, int out_size) {
    const float* xs  = (const float*)d_in[0];
    const int*   ei  = (const int*)  d_in[1];
    const float* W1  = (const float*)d_in[2];
    const float* b1  = (const float*)d_in[3];
    const float* W2  = (const float*)d_in[4];
    const float* b2  = (const float*)d_in[5];
    const float* wih = (const float*)d_in[6];
    const float* whh = (const float*)d_in[7];
    const float* bih = (const float*)d_in[8];
    const float* bhh = (const float*)d_in[9];
    const float* hw  = (const float*)d_in[10];
    const float* hb  = (const float*)d_in[11];
    float* out = (float*)d_out;

    cudaFuncSetAttribute(k_lstm_f16,
                         cudaFuncAttributeMaxDynamicSharedMemorySize, L_TOT * 4);
    cudaFuncSetAttribute(k_gemm64h,
                         cudaFuncAttributeMaxDynamicSharedMemorySize, G2_TOT * 4);

    k_fill_bucket<<<(TT * EE + 255) / 256, 256>>>(ei);
    k_packw2<<<8, 256>>>(W2);

    k_gemm1h<<<(TT * NN + 127) / 128, 128>>>(xs, W1);
    k_agg1h<<<((size_t)TT * NN * 8 + 511) / 512, 512>>>(b1);
    k_gemm64h<<<(TT * NN) / 128, 512, G2_TOT * 4>>>();
    k_agg2h<<<((size_t)TT * NN * 8 + 511) / 512, 512>>>(b2);

    k_lstm_f16<<<NBLK, 512, L_TOT * 4>>>(wih, whh, bih, bhh, hw, hb, out);
}